// round 1
// baseline (speedup 1.0000x reference)
#include <cuda_runtime.h>
#include <cuda_bf16.h>
#include <cstdint>

// ---------------------------------------------------------------------------
// InteractionGNN on GB300 — round 1: correct fused-MLP FFMA baseline.
//
// Pipeline (all fp32):
//   h = MLP_ne(nodes)                                [N,16] -> [N,128]
//   e = MLP_ee(h[start] || h[end])                   [E,256] -> [E,128]
//   4x:
//     msg    = segment_sum(e, end)                   scatter-add
//     h_new  = MLP_nn(h || msg) + h
//     e      = MLP_en(h[start] || h[end] || e) + e   (old h)
//     h      = h_new
//   pred = MLP_pe(h[start] || h[end] || e)           [E,384] -> [E,1]
// ---------------------------------------------------------------------------

#define N_NODES 100000
#define N_EDGES 600000
#define F_IN    16
#define DD      128
#define NUM_ITERS 4

static constexpr int ROWS = 64;   // rows per block
static constexpr int NTHR = 256;  // threads per block
static constexpr int STR  = 68;   // padded row-dim stride in smem (conflict control)

// Scratch (device-global; no runtime allocation allowed)
__device__ float g_h  [(size_t)N_NODES * DD];
__device__ float g_h2 [(size_t)N_NODES * DD];
__device__ float g_msg[(size_t)N_NODES * DD];
__device__ float g_e  [(size_t)N_EDGES * DD];
__device__ int   g_start[N_EDGES];
__device__ int   g_end  [N_EDGES];

// ---------------------------------------------------------------------------
// edge_index dtype detection + conversion to int32.
// If the data is int64 (values < 1e5), every odd 32-bit word of the first 128
// entries is zero. For int32 data, P(all 128 sampled words == 0) ~ 1e-640.
// Each block decides independently (deterministic, no cross-kernel flag).
// ---------------------------------------------------------------------------
__global__ void convert_idx_kernel(const void* __restrict__ raw,
                                   int* __restrict__ st, int* __restrict__ en,
                                   int E) {
    __shared__ int s_is64;
    if (threadIdx.x == 0) {
        const unsigned int* w = (const unsigned int*)raw;
        unsigned int acc = 0;
        #pragma unroll 8
        for (int i = 0; i < 128; ++i) acc |= w[2 * i + 1];
        s_is64 = (acc == 0u);
    }
    __syncthreads();
    const int is64 = s_is64;
    int i = blockIdx.x * blockDim.x + threadIdx.x;
    if (i >= 2 * E) return;
    int v;
    if (is64) v = (int)((const long long*)raw)[i];
    else      v = ((const int*)raw)[i];
    if (i < E) st[i] = v; else en[i - E] = v;
}

__global__ void zero_kernel(float4* __restrict__ p, int n4) {
    int i = blockIdx.x * blockDim.x + threadIdx.x;
    if (i < n4) p[i] = make_float4(0.f, 0.f, 0.f, 0.f);
}

// Scatter-add: one warp per edge, lane = 4-column chunk.
__global__ void scatter_add_kernel(const float* __restrict__ e,
                                   const int* __restrict__ end,
                                   float* __restrict__ msg, int E) {
    long long i = (long long)blockIdx.x * blockDim.x + threadIdx.x;
    if (i >= (long long)E * 32) return;
    int edge = (int)(i >> 5);
    int c4   = (int)(i & 31);
    float4 v = ((const float4*)(e + (size_t)edge * DD))[c4];
    float* dst = msg + (size_t)end[edge] * DD + c4 * 4;
    atomicAdd(dst + 0, v.x);
    atomicAdd(dst + 1, v.y);
    atomicAdd(dst + 2, v.z);
    atomicAdd(dst + 3, v.w);
}

// ---------------------------------------------------------------------------
// Fused 2-layer MLP:  out = relu(X @ W1 + b1) @ W2 + b2 (+ res)
// X rows are gathered/concatenated from up to 3 sources (idx==nullptr -> identity).
// Block: 64 rows x 128 cols, 256 threads, 8x4 register tile per thread.
// X is staged transposed in smem (xT[k][row], stride 68), hidden in hT.
// ---------------------------------------------------------------------------
template <int IN_DIM, int NPART, bool RES, bool OUT1>
__global__ void __launch_bounds__(NTHR)
mlp_kernel(const float* __restrict__ s0, const float* __restrict__ s1,
           const float* __restrict__ s2,
           const int* __restrict__ i0, const int* __restrict__ i1,
           const int* __restrict__ i2,
           const float* __restrict__ W1, const float* __restrict__ b1,
           const float* __restrict__ W2, const float* __restrict__ b2,
           const float* __restrict__ res, float* __restrict__ out,
           int nrows_total) {
    extern __shared__ float smem[];
    float* xT = smem;                          // [IN_DIM][STR]
    float* hT = smem + (size_t)IN_DIM * STR;   // [128][STR]

    constexpr int PD = IN_DIM / NPART;
    const int tid  = threadIdx.x;
    const int lane = tid & 31;
    const int warp = tid >> 5;
    const int row0 = blockIdx.x * ROWS;

    const float* srcs[3] = {s0, s1, s2};
    const int*   idxs[3] = {i0, i1, i2};

    // ---------------- stage X (transposed) ----------------
    #pragma unroll
    for (int p = 0; p < NPART; ++p) {
        const float* src = srcs[p];
        const int*   idx = idxs[p];
        for (int r = warp; r < ROWS; r += 8) {
            int grow = row0 + r;
            const float4* sp = nullptr;
            if (grow < nrows_total) {
                int srow = idx ? idx[grow] : grow;
                sp = (const float4*)(src + (size_t)srow * PD);
            }
            #pragma unroll
            for (int c4 = lane; c4 < PD / 4; c4 += 32) {
                float4 v = sp ? sp[c4] : make_float4(0.f, 0.f, 0.f, 0.f);
                int kb = p * PD + c4 * 4;
                xT[(kb + 0) * STR + r] = v.x;
                xT[(kb + 1) * STR + r] = v.y;
                xT[(kb + 2) * STR + r] = v.z;
                xT[(kb + 3) * STR + r] = v.w;
            }
        }
    }
    __syncthreads();

    const int c0 = lane;   // thread cols: c0, c0+32, c0+64, c0+96
    const int rg = warp;   // thread rows: rg*8 .. rg*8+7

    // ---------------- layer 1: hidden = relu(X@W1 + b1) ----------------
    float acc[8][4];
    #pragma unroll
    for (int j = 0; j < 4; ++j) {
        float bv = __ldg(&b1[c0 + 32 * j]);
        #pragma unroll
        for (int i = 0; i < 8; ++i) acc[i][j] = bv;
    }

    #pragma unroll 4
    for (int k = 0; k < IN_DIM; ++k) {
        float4 xa = *(const float4*)&xT[k * STR + rg * 8];
        float4 xb = *(const float4*)&xT[k * STR + rg * 8 + 4];
        float w0 = __ldg(&W1[k * DD + c0]);
        float w1 = __ldg(&W1[k * DD + c0 + 32]);
        float w2 = __ldg(&W1[k * DD + c0 + 64]);
        float w3 = __ldg(&W1[k * DD + c0 + 96]);
        float xs[8] = {xa.x, xa.y, xa.z, xa.w, xb.x, xb.y, xb.z, xb.w};
        #pragma unroll
        for (int i = 0; i < 8; ++i) {
            acc[i][0] += xs[i] * w0;
            acc[i][1] += xs[i] * w1;
            acc[i][2] += xs[i] * w2;
            acc[i][3] += xs[i] * w3;
        }
    }

    #pragma unroll
    for (int i = 0; i < 8; ++i)
        #pragma unroll
        for (int j = 0; j < 4; ++j)
            hT[(c0 + 32 * j) * STR + rg * 8 + i] = fmaxf(acc[i][j], 0.f);
    __syncthreads();

    // ---------------- layer 2 ----------------
    if constexpr (OUT1) {
        // W2: [128,1], b2: [1]. One thread per row.
        if (tid < ROWS) {
            int grow = row0 + tid;
            float a = __ldg(&b2[0]);
            #pragma unroll 8
            for (int k = 0; k < DD; ++k)
                a += hT[k * STR + tid] * __ldg(&W2[k]);
            if (grow < nrows_total) out[grow] = a;
        }
    } else {
        float acc2[8][4];
        #pragma unroll
        for (int j = 0; j < 4; ++j) {
            float bv = __ldg(&b2[c0 + 32 * j]);
            #pragma unroll
            for (int i = 0; i < 8; ++i) acc2[i][j] = bv;
        }
        #pragma unroll 4
        for (int k = 0; k < DD; ++k) {
            float4 xa = *(const float4*)&hT[k * STR + rg * 8];
            float4 xb = *(const float4*)&hT[k * STR + rg * 8 + 4];
            float w0 = __ldg(&W2[k * DD + c0]);
            float w1 = __ldg(&W2[k * DD + c0 + 32]);
            float w2 = __ldg(&W2[k * DD + c0 + 64]);
            float w3 = __ldg(&W2[k * DD + c0 + 96]);
            float xs[8] = {xa.x, xa.y, xa.z, xa.w, xb.x, xb.y, xb.z, xb.w};
            #pragma unroll
            for (int i = 0; i < 8; ++i) {
                acc2[i][0] += xs[i] * w0;
                acc2[i][1] += xs[i] * w1;
                acc2[i][2] += xs[i] * w2;
                acc2[i][3] += xs[i] * w3;
            }
        }
        #pragma unroll
        for (int i = 0; i < 8; ++i) {
            int grow = row0 + rg * 8 + i;
            if (grow < nrows_total) {
                #pragma unroll
                for (int j = 0; j < 4; ++j) {
                    int c = c0 + 32 * j;
                    float v = acc2[i][j];
                    if (RES) v += res[(size_t)grow * DD + c];
                    out[(size_t)grow * DD + c] = v;
                }
            }
        }
    }
}

// ---------------------------------------------------------------------------
static inline int smem_bytes(int in_dim) { return (in_dim + DD) * STR * (int)sizeof(float); }

extern "C" void kernel_launch(void* const* d_in, const int* in_sizes, int n_in,
                              void* d_out, int out_size) {
    const float* nodes = (const float*)d_in[0];
    const void*  eidx  = d_in[1];
    const float* ne_W1 = (const float*)d_in[2];
    const float* ne_b1 = (const float*)d_in[3];
    const float* ne_W2 = (const float*)d_in[4];
    const float* ne_b2 = (const float*)d_in[5];
    const float* ee_W1 = (const float*)d_in[6];
    const float* ee_b1 = (const float*)d_in[7];
    const float* ee_W2 = (const float*)d_in[8];
    const float* ee_b2 = (const float*)d_in[9];
    const float* nn_W1 = (const float*)d_in[10];
    const float* nn_b1 = (const float*)d_in[11];
    const float* nn_W2 = (const float*)d_in[12];
    const float* nn_b2 = (const float*)d_in[13];
    const float* en_W1 = (const float*)d_in[14];
    const float* en_b1 = (const float*)d_in[15];
    const float* en_W2 = (const float*)d_in[16];
    const float* en_b2 = (const float*)d_in[17];
    const float* pe_W1 = (const float*)d_in[18];
    const float* pe_b1 = (const float*)d_in[19];
    const float* pe_W2 = (const float*)d_in[20];
    const float* pe_b2 = (const float*)d_in[21];

    float *h, *h2, *msg, *e;
    int *st, *en_;
    cudaGetSymbolAddress((void**)&h,   g_h);
    cudaGetSymbolAddress((void**)&h2,  g_h2);
    cudaGetSymbolAddress((void**)&msg, g_msg);
    cudaGetSymbolAddress((void**)&e,   g_e);
    cudaGetSymbolAddress((void**)&st,  g_start);
    cudaGetSymbolAddress((void**)&en_, g_end);

    // allow >48KB dynamic smem (idempotent host calls, not stream ops)
    cudaFuncSetAttribute(mlp_kernel<16, 1, false, false>,
                         cudaFuncAttributeMaxDynamicSharedMemorySize, smem_bytes(16));
    cudaFuncSetAttribute(mlp_kernel<256, 2, false, false>,
                         cudaFuncAttributeMaxDynamicSharedMemorySize, smem_bytes(256));
    cudaFuncSetAttribute(mlp_kernel<256, 2, true, false>,
                         cudaFuncAttributeMaxDynamicSharedMemorySize, smem_bytes(256));
    cudaFuncSetAttribute(mlp_kernel<384, 3, true, false>,
                         cudaFuncAttributeMaxDynamicSharedMemorySize, smem_bytes(384));
    cudaFuncSetAttribute(mlp_kernel<384, 3, false, true>,
                         cudaFuncAttributeMaxDynamicSharedMemorySize, smem_bytes(384));

    const int nblk_n = (N_NODES + ROWS - 1) / ROWS;  // 1563
    const int nblk_e = (N_EDGES + ROWS - 1) / ROWS;  // 9375

    // 0) edge_index -> int32 start/end
    convert_idx_kernel<<<(2 * N_EDGES + 255) / 256, 256>>>(eidx, st, en_, N_EDGES);

    // 1) h = MLP_ne(nodes)
    mlp_kernel<16, 1, false, false><<<nblk_n, NTHR, smem_bytes(16)>>>(
        nodes, nullptr, nullptr, nullptr, nullptr, nullptr,
        ne_W1, ne_b1, ne_W2, ne_b2, nullptr, h, N_NODES);

    // 2) e = MLP_ee(h[start] || h[end])
    mlp_kernel<256, 2, false, false><<<nblk_e, NTHR, smem_bytes(256)>>>(
        h, h, nullptr, st, en_, nullptr,
        ee_W1, ee_b1, ee_W2, ee_b2, nullptr, e, N_EDGES);

    float* hA = h;
    float* hB = h2;
    const int zero_n4   = N_NODES * DD / 4;
    const int zero_blks = (zero_n4 + 255) / 256;
    const long long sc_thr = (long long)N_EDGES * 32;
    const int sc_blks = (int)((sc_thr + 255) / 256);

    for (int it = 0; it < NUM_ITERS; ++it) {
        // msg = segment_sum(e, end)
        zero_kernel<<<zero_blks, 256>>>((float4*)msg, zero_n4);
        scatter_add_kernel<<<sc_blks, 256>>>(e, en_, msg, N_EDGES);

        // h_new = MLP_nn(h || msg) + h
        mlp_kernel<256, 2, true, false><<<nblk_n, NTHR, smem_bytes(256)>>>(
            hA, msg, nullptr, nullptr, nullptr, nullptr,
            nn_W1, nn_b1, nn_W2, nn_b2, hA, hB, N_NODES);

        // e = MLP_en(h[start] || h[end] || e) + e   (old h; in-place row-local)
        mlp_kernel<384, 3, true, false><<<nblk_e, NTHR, smem_bytes(384)>>>(
            hA, hA, e, st, en_, nullptr,
            en_W1, en_b1, en_W2, en_b2, e, e, N_EDGES);

        // h = h_new
        float* t = hA; hA = hB; hB = t;
    }

    // 3) pred = MLP_pe(h[start] || h[end] || e)
    mlp_kernel<384, 3, false, true><<<nblk_e, NTHR, smem_bytes(384)>>>(
        hA, hA, e, st, en_, nullptr,
        pe_W1, pe_b1, pe_W2, pe_b2, nullptr, (float*)d_out, N_EDGES);
}

// round 3
// speedup vs baseline: 2.9579x; 2.9579x over previous
#include <cuda_runtime.h>
#include <cuda_bf16.h>
#include <cstdint>

// ---------------------------------------------------------------------------
// InteractionGNN on GB300 — round 3: warp-level bf16 mma.sync (baseline PTX,
// compute_103-safe) with 3-term split-float GEMMs.
//
//   h = MLP_ne(nodes); e = MLP_ee(h[s]||h[e])
//   4x: msg = scatter_add(e,end); h' = MLP_nn(h||msg)+h; e = MLP_en(h[s]||h[e]||e)+e
//   pred = MLP_pe(h[s]||h[e]||e)
//
// GEMM: D = A @ W. A fp32 -> bf16 hi/lo split; W prepacked transposed [n][k]
// bf16 hi/lo. 3 mma terms: Ah*Wh + Ah*Wl + Al*Wh, fp32 accum => ~1e-5 rel err.
// ---------------------------------------------------------------------------

#define N_NODES 100000
#define N_EDGES 600000
#define DD      128
#define NUM_ITERS 4

// ---------------- device scratch -------------------------------------------
__device__ float g_h  [(size_t)N_NODES * DD];
__device__ float g_h2 [(size_t)N_NODES * DD];
__device__ float g_msg[(size_t)N_NODES * DD];
__device__ float g_e  [(size_t)N_EDGES * DD];
__device__ int   g_start[N_EDGES];
__device__ int   g_end  [N_EDGES];
// prepacked weights: 15 chunks x [128 n][128 k] bf16, hi and lo images
__device__ __nv_bfloat16 g_pwh[15 * 16384];
__device__ __nv_bfloat16 g_pwl[15 * 16384];

// ---------------- smem layout ----------------------------------------------
static constexpr int ROW_B = 272;                 // bytes per smem row (16B aligned)
static constexpr int SM_B1 = 64;                  // 128 f32
static constexpr int SM_W2V = 576;                // 128 f32
static constexpr int SM_B2 = 1088;                // 128 f32
static constexpr int SM_AH = 2048;
static constexpr int ABUF  = 128 * ROW_B;         // 34816
static constexpr int SM_AL = SM_AH + ABUF;
static constexpr int SM_BH = SM_AL + ABUF;
static constexpr int SM_BL = SM_BH + ABUF;
static constexpr int SM_TOTAL = SM_BL + ABUF;     // 141312 bytes

// ---------------- helpers ---------------------------------------------------
__device__ __forceinline__ uint32_t smem_u32(const void* p) {
    uint32_t a;
    asm("{ .reg .u64 t; cvta.to.shared.u64 t, %1; cvt.u32.u64 %0, t; }"
        : "=r"(a) : "l"(p));
    return a;
}

#define LDSM_X4(R0, R1, R2, R3, ADDR) \
    asm volatile("ldmatrix.sync.aligned.m8n8.x4.shared.b16 {%0,%1,%2,%3}, [%4];" \
                 : "=r"(R0), "=r"(R1), "=r"(R2), "=r"(R3) : "r"(ADDR))

__device__ __forceinline__ void mma16816(float* c, const uint32_t* a,
                                         const uint32_t* b) {
    asm volatile(
        "mma.sync.aligned.m16n8k16.row.col.f32.bf16.bf16.f32 "
        "{%0,%1,%2,%3}, {%4,%5,%6,%7}, {%8,%9}, {%0,%1,%2,%3};"
        : "+f"(c[0]), "+f"(c[1]), "+f"(c[2]), "+f"(c[3])
        : "r"(a[0]), "r"(a[1]), "r"(a[2]), "r"(a[3]), "r"(b[0]), "r"(b[1]));
}

__device__ __forceinline__ uint32_t pack_bf2(float a, float b) {
    __nv_bfloat162 t = __floats2bfloat162_rn(a, b);
    return *reinterpret_cast<uint32_t*>(&t);
}

// split fp32 pair -> bf16 hi pair (u32) + bf16 lo pair (u32)
__device__ __forceinline__ void split2(float x, float y, uint32_t& H, uint32_t& L) {
    __nv_bfloat16 hx = __float2bfloat16(x);
    __nv_bfloat16 hy = __float2bfloat16(y);
    float lx = x - __bfloat162float(hx);
    float ly = y - __bfloat162float(hy);
    H = pack_bf2(__bfloat162float(hx), __bfloat162float(hy));
    L = pack_bf2(lx, ly);
}

// ---------------- small utility kernels ------------------------------------
__global__ void convert_idx_kernel(const void* __restrict__ raw,
                                   int* __restrict__ st, int* __restrict__ en,
                                   int E) {
    __shared__ int s_is64;
    if (threadIdx.x == 0) {
        const unsigned int* w = (const unsigned int*)raw;
        unsigned int acc = 0;
        #pragma unroll 8
        for (int i = 0; i < 128; ++i) acc |= w[2 * i + 1];
        s_is64 = (acc == 0u);
    }
    __syncthreads();
    const int is64 = s_is64;
    int i = blockIdx.x * blockDim.x + threadIdx.x;
    if (i >= 2 * E) return;
    int v;
    if (is64) v = (int)((const long long*)raw)[i];
    else      v = ((const int*)raw)[i];
    if (i < E) st[i] = v; else en[i - E] = v;
}

__global__ void zero_kernel(float4* __restrict__ p, int n4) {
    int i = blockIdx.x * blockDim.x + threadIdx.x;
    if (i < n4) p[i] = make_float4(0.f, 0.f, 0.f, 0.f);
}

__global__ void scatter_add_kernel(const float* __restrict__ e,
                                   const int* __restrict__ end,
                                   float* __restrict__ msg, int E) {
    long long i = (long long)blockIdx.x * blockDim.x + threadIdx.x;
    if (i >= (long long)E * 32) return;
    int edge = (int)(i >> 5);
    int c4   = (int)(i & 31);
    float4 v = ((const float4*)(e + (size_t)edge * DD))[c4];
    float* dst = msg + (size_t)end[edge] * DD + c4 * 4;
    atomicAdd(dst + 0, v.x);
    atomicAdd(dst + 1, v.y);
    atomicAdd(dst + 2, v.z);
    atomicAdd(dst + 3, v.w);
}

// Pack weights transposed: image[chunk][n][k] = W[(koff+k)*128 + n], bf16 hi/lo.
// Chunks: 0:ne_W1(k<16) 1:ne_W2  2-3:ee_W1 4:ee_W2  5-6:nn_W1 7:nn_W2
//         8-10:en_W1 11:en_W2  12-14:pe_W1
__global__ void pack_w_kernel(const float* neW1, const float* neW2,
                              const float* eeW1, const float* eeW2,
                              const float* nnW1, const float* nnW2,
                              const float* enW1, const float* enW2,
                              const float* peW1,
                              __nv_bfloat16* gh, __nv_bfloat16* gl) {
    int t = blockIdx.x * blockDim.x + threadIdx.x;
    if (t >= 15 * 16384) return;
    int chunk = t >> 14;
    int e = t & 16383;
    int k = e & 127;
    int n = e >> 7;
    const float* W; int koff = 0; int kvalid = 128;
    switch (chunk) {
        case 0:  W = neW1; kvalid = 16; break;
        case 1:  W = neW2; break;
        case 2: case 3:  W = eeW1; koff = (chunk - 2) * 128; break;
        case 4:  W = eeW2; break;
        case 5: case 6:  W = nnW1; koff = (chunk - 5) * 128; break;
        case 7:  W = nnW2; break;
        case 8: case 9: case 10: W = enW1; koff = (chunk - 8) * 128; break;
        case 11: W = enW2; break;
        default: W = peW1; koff = (chunk - 12) * 128; break;
    }
    float x = (k < kvalid) ? W[(size_t)(koff + k) * 128 + n] : 0.f;
    __nv_bfloat16 h = __float2bfloat16(x);
    __nv_bfloat16 l = __float2bfloat16(x - __bfloat162float(h));
    gh[(size_t)chunk * 16384 + n * 128 + k] = h;
    gl[(size_t)chunk * 16384 + n * 128 + k] = l;
}

// 3-term split GEMM over one 128-wide K chunk: acc += A(128x128) @ W(128x128)^T
// (A in smem hi/lo, W in smem hi/lo as [n][k]); warp tile 32(M) x 64(N).
__device__ __forceinline__ void gemm_chunk(uint32_t sb, int m0, int n0,
                                           int a_ro, int a_co, int b_ro, int b_co,
                                           float acc[2][8][4]) {
    const uint32_t abufs[3] = {sb + SM_AH, sb + SM_AH, sb + SM_AL};
    const uint32_t bbufs[3] = {sb + SM_BH, sb + SM_BL, sb + SM_BH};
    #pragma unroll
    for (int t = 0; t < 3; ++t) {
        const uint32_t ab = abufs[t];
        const uint32_t bb = bbufs[t];
        #pragma unroll
        for (int ks = 0; ks < 8; ++ks) {
            const int k0 = ks * 16;
            uint32_t af[2][4];
            #pragma unroll
            for (int ma = 0; ma < 2; ++ma) {
                uint32_t ad = ab + (uint32_t)(m0 + ma * 16 + a_ro) * ROW_B +
                              (uint32_t)(k0 + a_co) * 2;
                LDSM_X4(af[ma][0], af[ma][1], af[ma][2], af[ma][3], ad);
            }
            uint32_t bfm[8][2];
            #pragma unroll
            for (int nb = 0; nb < 4; ++nb) {
                uint32_t bd = bb + (uint32_t)(n0 + nb * 16 + b_ro) * ROW_B +
                              (uint32_t)(k0 + b_co) * 2;
                uint32_t r0, r1, r2, r3;
                LDSM_X4(r0, r1, r2, r3, bd);
                bfm[nb * 2][0] = r0;  bfm[nb * 2][1] = r1;
                bfm[nb * 2 + 1][0] = r2;  bfm[nb * 2 + 1][1] = r3;
            }
            #pragma unroll
            for (int ma = 0; ma < 2; ++ma)
                #pragma unroll
                for (int na = 0; na < 8; ++na)
                    mma16816(acc[ma][na], af[ma], bfm[na]);
        }
    }
}

// copy prepacked weight chunk -> smem hi/lo tiles ([n][k], row stride 272B)
__device__ __forceinline__ void copy_w(char* smem, int tid,
                                       const __nv_bfloat16* gh,
                                       const __nv_bfloat16* gl, int chunk) {
    const int4* srcH = (const int4*)(gh + (size_t)chunk * 16384);
    const int4* srcL = (const int4*)(gl + (size_t)chunk * 16384);
    #pragma unroll
    for (int i = tid; i < 2048; i += 256) {
        int rr = i >> 4, q = i & 15;
        *(int4*)(smem + SM_BH + rr * ROW_B + q * 16) = srcH[i];
        *(int4*)(smem + SM_BL + rr * ROW_B + q * 16) = srcL[i];
    }
}

// ---------------------------------------------------------------------------
// Fused 2-layer MLP.  CTA = 128 rows x 128 cols, 256 threads (8 warps 4Mx2N).
// ---------------------------------------------------------------------------
template <int NCHUNKS, int SRC_K, bool RES, bool OUT1>
__global__ void __launch_bounds__(256, 1)
mlp_mma(const float* __restrict__ s0, const float* __restrict__ s1,
        const float* __restrict__ s2,
        const int* __restrict__ i0, const int* __restrict__ i1,
        const int* __restrict__ i2,
        int w1_chunk, int w2_chunk,
        const float* __restrict__ b1, const float* __restrict__ b2,
        const float* __restrict__ w2vec,
        const float* __restrict__ res, float* __restrict__ out, int nrows) {
    extern __shared__ char smem[];
    const uint32_t sb = smem_u32(smem);
    const int tid  = threadIdx.x;
    const int lane = tid & 31;
    const int wid  = tid >> 5;
    const int row0 = blockIdx.x * 128;

    const int g   = lane >> 2;   // group id
    const int tig = lane & 3;    // thread in group
    const int mw  = wid >> 1;    // 0..3
    const int nw  = wid & 1;     // 0..1
    const int m0  = mw * 32;
    const int n0  = nw * 64;
    // ldmatrix per-thread address offsets
    const int a_ro = (lane & 7) + ((lane >> 3) & 1) * 8;
    const int a_co = ((lane >> 4) & 1) * 8;
    const int b_ro = (lane & 7) + ((lane >> 4) & 1) * 8;
    const int b_co = ((lane >> 3) & 1) * 8;

    float* b1s = (float*)(smem + SM_B1);
    float* b2s = (float*)(smem + SM_B2);
    float* w2s = (float*)(smem + SM_W2V);
    if (tid < 128) {
        b1s[tid] = b1[tid];
        if (OUT1) w2s[tid] = w2vec[tid];
        else      b2s[tid] = b2[tid];
    }

    const float* srcs[3] = {s0, s1, s2};
    const int*   idxs[3] = {i0, i1, i2};

    float acc[2][8][4];
    #pragma unroll
    for (int ma = 0; ma < 2; ++ma)
        #pragma unroll
        for (int na = 0; na < 8; ++na)
            #pragma unroll
            for (int q = 0; q < 4; ++q) acc[ma][na][q] = 0.f;

    // ---------------- layer 1 over K chunks ----------------
    for (int c = 0; c < NCHUNKS; ++c) {
        if (c) __syncthreads();  // previous chunk's smem reads done
        // stage A chunk: gather rows, split fp32 -> bf16 hi/lo
        {
            const float* src = srcs[c];
            const int*   idx = idxs[c];
            for (int r = wid; r < 128; r += 8) {
                int grow = row0 + r;
                const float4* sp = nullptr;
                if (grow < nrows) {
                    int sr = idx ? idx[grow] : grow;
                    sp = (const float4*)(src + (size_t)sr * SRC_K);
                }
                float4 v = (sp && lane < SRC_K / 4) ? sp[lane]
                                                    : make_float4(0.f, 0.f, 0.f, 0.f);
                uint32_t h0, l0, h1, l1;
                split2(v.x, v.y, h0, l0);
                split2(v.z, v.w, h1, l1);
                uint32_t off = r * ROW_B + lane * 8;
                *(uint2*)(smem + SM_AH + off) = make_uint2(h0, h1);
                *(uint2*)(smem + SM_AL + off) = make_uint2(l0, l1);
            }
        }
        copy_w(smem, tid, g_pwh, g_pwl, w1_chunk + c);
        __syncthreads();
        gemm_chunk(sb, m0, n0, a_ro, a_co, b_ro, b_co, acc);
    }
    __syncthreads();  // all layer-1 smem reads done

    if constexpr (OUT1) {
        // hidden fp32 into smem [k-col][?]: store as [row][col] stride 129
        float* hT = (float*)(smem + SM_AH);
        #pragma unroll
        for (int ma = 0; ma < 2; ++ma) {
            int rl = m0 + ma * 16 + g;
            #pragma unroll
            for (int na = 0; na < 8; ++na) {
                int cc = n0 + na * 8 + 2 * tig;
                hT[rl * 129 + cc]     = fmaxf(acc[ma][na][0] + b1s[cc], 0.f);
                hT[rl * 129 + cc + 1] = fmaxf(acc[ma][na][1] + b1s[cc + 1], 0.f);
                hT[(rl + 8) * 129 + cc]     = fmaxf(acc[ma][na][2] + b1s[cc], 0.f);
                hT[(rl + 8) * 129 + cc + 1] = fmaxf(acc[ma][na][3] + b1s[cc + 1], 0.f);
            }
        }
        __syncthreads();
        if (tid < 128) {
            int grow = row0 + tid;
            float a = __ldg(&b2[0]);
            #pragma unroll 8
            for (int k = 0; k < 128; ++k) a += hT[tid * 129 + k] * w2s[k];
            if (grow < nrows) out[grow] = a;
        }
        return;
    }

    // ---------------- hidden = relu(acc + b1) -> A smem (bf16 hi/lo) --------
    #pragma unroll
    for (int ma = 0; ma < 2; ++ma) {
        int rl = m0 + ma * 16 + g;
        #pragma unroll
        for (int na = 0; na < 8; ++na) {
            int cc = n0 + na * 8 + 2 * tig;
            float v0 = fmaxf(acc[ma][na][0] + b1s[cc], 0.f);
            float v1 = fmaxf(acc[ma][na][1] + b1s[cc + 1], 0.f);
            float v2 = fmaxf(acc[ma][na][2] + b1s[cc], 0.f);
            float v3 = fmaxf(acc[ma][na][3] + b1s[cc + 1], 0.f);
            uint32_t H, L;
            split2(v0, v1, H, L);
            *(uint32_t*)(smem + SM_AH + rl * ROW_B + cc * 2) = H;
            *(uint32_t*)(smem + SM_AL + rl * ROW_B + cc * 2) = L;
            split2(v2, v3, H, L);
            *(uint32_t*)(smem + SM_AH + (rl + 8) * ROW_B + cc * 2) = H;
            *(uint32_t*)(smem + SM_AL + (rl + 8) * ROW_B + cc * 2) = L;
        }
    }
    copy_w(smem, tid, g_pwh, g_pwl, w2_chunk);
    __syncthreads();

    // ---------------- layer 2 ----------------
    #pragma unroll
    for (int ma = 0; ma < 2; ++ma)
        #pragma unroll
        for (int na = 0; na < 8; ++na)
            #pragma unroll
            for (int q = 0; q < 4; ++q) acc[ma][na][q] = 0.f;
    gemm_chunk(sb, m0, n0, a_ro, a_co, b_ro, b_co, acc);

    // ---------------- epilogue: out = acc + b2 (+ res) ----------------
    #pragma unroll
    for (int ma = 0; ma < 2; ++ma) {
        int rl = m0 + ma * 16 + g;
        int grow0 = row0 + rl;
        int grow1 = grow0 + 8;
        #pragma unroll
        for (int na = 0; na < 8; ++na) {
            int cc = n0 + na * 8 + 2 * tig;
            float bx = b2s[cc], by = b2s[cc + 1];
            if (grow0 < nrows) {
                float2 o = make_float2(acc[ma][na][0] + bx, acc[ma][na][1] + by);
                if (RES) {
                    float2 rv = *(const float2*)(res + (size_t)grow0 * DD + cc);
                    o.x += rv.x; o.y += rv.y;
                }
                *(float2*)(out + (size_t)grow0 * DD + cc) = o;
            }
            if (grow1 < nrows) {
                float2 o = make_float2(acc[ma][na][2] + bx, acc[ma][na][3] + by);
                if (RES) {
                    float2 rv = *(const float2*)(res + (size_t)grow1 * DD + cc);
                    o.x += rv.x; o.y += rv.y;
                }
                *(float2*)(out + (size_t)grow1 * DD + cc) = o;
            }
        }
    }
}

// ---------------------------------------------------------------------------
extern "C" void kernel_launch(void* const* d_in, const int* in_sizes, int n_in,
                              void* d_out, int out_size) {
    const float* nodes = (const float*)d_in[0];
    const void*  eidx  = d_in[1];
    const float* ne_W1 = (const float*)d_in[2];
    const float* ne_b1 = (const float*)d_in[3];
    const float* ne_W2 = (const float*)d_in[4];
    const float* ne_b2 = (const float*)d_in[5];
    const float* ee_W1 = (const float*)d_in[6];
    const float* ee_b1 = (const float*)d_in[7];
    const float* ee_W2 = (const float*)d_in[8];
    const float* ee_b2 = (const float*)d_in[9];
    const float* nn_W1 = (const float*)d_in[10];
    const float* nn_b1 = (const float*)d_in[11];
    const float* nn_W2 = (const float*)d_in[12];
    const float* nn_b2 = (const float*)d_in[13];
    const float* en_W1 = (const float*)d_in[14];
    const float* en_b1 = (const float*)d_in[15];
    const float* en_W2 = (const float*)d_in[16];
    const float* en_b2 = (const float*)d_in[17];
    const float* pe_W1 = (const float*)d_in[18];
    const float* pe_b1 = (const float*)d_in[19];
    const float* pe_W2 = (const float*)d_in[20];
    const float* pe_b2 = (const float*)d_in[21];

    float *h, *h2, *msg, *e;
    int *st, *en_;
    __nv_bfloat16 *pwh, *pwl;
    cudaGetSymbolAddress((void**)&h,   g_h);
    cudaGetSymbolAddress((void**)&h2,  g_h2);
    cudaGetSymbolAddress((void**)&msg, g_msg);
    cudaGetSymbolAddress((void**)&e,   g_e);
    cudaGetSymbolAddress((void**)&st,  g_start);
    cudaGetSymbolAddress((void**)&en_, g_end);
    cudaGetSymbolAddress((void**)&pwh, g_pwh);
    cudaGetSymbolAddress((void**)&pwl, g_pwl);

    cudaFuncSetAttribute(mlp_mma<1, 16, false, false>,
                         cudaFuncAttributeMaxDynamicSharedMemorySize, SM_TOTAL);
    cudaFuncSetAttribute(mlp_mma<2, 128, false, false>,
                         cudaFuncAttributeMaxDynamicSharedMemorySize, SM_TOTAL);
    cudaFuncSetAttribute(mlp_mma<2, 128, true, false>,
                         cudaFuncAttributeMaxDynamicSharedMemorySize, SM_TOTAL);
    cudaFuncSetAttribute(mlp_mma<3, 128, true, false>,
                         cudaFuncAttributeMaxDynamicSharedMemorySize, SM_TOTAL);
    cudaFuncSetAttribute(mlp_mma<3, 128, false, true>,
                         cudaFuncAttributeMaxDynamicSharedMemorySize, SM_TOTAL);

    const int nblk_n = (N_NODES + 127) / 128;  // 782
    const int nblk_e = (N_EDGES + 127) / 128;  // 4688

    convert_idx_kernel<<<(2 * N_EDGES + 255) / 256, 256>>>(eidx, st, en_, N_EDGES);
    pack_w_kernel<<<(15 * 16384 + 255) / 256, 256>>>(
        ne_W1, ne_W2, ee_W1, ee_W2, nn_W1, nn_W2, en_W1, en_W2, pe_W1, pwh, pwl);

    // 1) h = MLP_ne(nodes)
    mlp_mma<1, 16, false, false><<<nblk_n, 256, SM_TOTAL>>>(
        nodes, nullptr, nullptr, nullptr, nullptr, nullptr,
        0, 1, ne_b1, ne_b2, nullptr, nullptr, h, N_NODES);

    // 2) e = MLP_ee(h[start] || h[end])
    mlp_mma<2, 128, false, false><<<nblk_e, 256, SM_TOTAL>>>(
        h, h, nullptr, st, en_, nullptr,
        2, 4, ee_b1, ee_b2, nullptr, nullptr, e, N_EDGES);

    float* hA = h;
    float* hB = h2;
    const int zero_n4   = N_NODES * DD / 4;
    const int zero_blks = (zero_n4 + 255) / 256;
    const long long sc_thr = (long long)N_EDGES * 32;
    const int sc_blks = (int)((sc_thr + 255) / 256);

    for (int it = 0; it < NUM_ITERS; ++it) {
        zero_kernel<<<zero_blks, 256>>>((float4*)msg, zero_n4);
        scatter_add_kernel<<<sc_blks, 256>>>(e, en_, msg, N_EDGES);

        // h_new = MLP_nn(h || msg) + h
        mlp_mma<2, 128, true, false><<<nblk_n, 256, SM_TOTAL>>>(
            hA, msg, nullptr, nullptr, nullptr, nullptr,
            5, 7, nn_b1, nn_b2, nullptr, hA, hB, N_NODES);

        // e = MLP_en(h[start] || h[end] || e) + e   (old h; in-place row-local)
        mlp_mma<3, 128, true, false><<<nblk_e, 256, SM_TOTAL>>>(
            hA, hA, e, st, en_, nullptr,
            8, 11, en_b1, en_b2, nullptr, e, e, N_EDGES);

        float* t = hA; hA = hB; hB = t;
    }

    // 3) pred = MLP_pe(h[start] || h[end] || e)
    mlp_mma<3, 128, false, true><<<nblk_e, 256, SM_TOTAL>>>(
        hA, hA, e, st, en_, nullptr,
        12, 0, pe_b1, pe_b2, pe_W2, nullptr, (float*)d_out, N_EDGES);
}

// round 4
// speedup vs baseline: 5.4730x; 1.8503x over previous
#include <cuda_runtime.h>
#include <cuda_bf16.h>
#include <cstdint>

// ---------------------------------------------------------------------------
// InteractionGNN on GB300 — round 4: mma.sync bf16x3 + node-side W1 precompute
// + 64-row CTAs (2 CTAs/SM).
//
//   h = MLP_ne(nodes)
//   Pa,Pb = h@eeW1a, h@eeW1b          (node precompute)
//   e = relu(Pa[s]+Pb[e]+b1) @ eeW2 + b2
//   4x: msg = scatter(e,end)
//       h' = MLP_nn(h||msg) + h
//       Qa,Qb = h@enW1a, h@enW1b      (old h)
//       e  = (relu(e@enW1c + Qa[s]+Qb[e]+b1) @ enW2 + b2) + e
//       h  = h'
//   Ra,Rb = h@peW1a, h@peW1b
//   pred = relu(e@peW1c + Ra[s]+Rb[e]+b1) . peW2 + b2
//
// All GEMMs: 3-term bf16 split (Ah*Wh + Ah*Wl + Al*Wh), fp32 accum.
// ---------------------------------------------------------------------------

#define N_NODES 100000
#define N_EDGES 600000
#define DD      128
#define NUM_ITERS 4

// ---------------- device scratch -------------------------------------------
__device__ float g_h  [(size_t)N_NODES * DD];
__device__ float g_h2 [(size_t)N_NODES * DD];
__device__ float g_msg[(size_t)N_NODES * DD];
__device__ float g_e  [(size_t)N_EDGES * DD];
__device__ float g_pa [(size_t)N_NODES * DD];
__device__ float g_pb [(size_t)N_NODES * DD];
__device__ int   g_start[N_EDGES];
__device__ int   g_end  [N_EDGES];
// prepacked weights: 15 chunks x [128 n][128 k] bf16, hi and lo images
__device__ __nv_bfloat16 g_pwh[15 * 16384];
__device__ __nv_bfloat16 g_pwl[15 * 16384];

// ---------------- smem layout (64-row A tile) -------------------------------
static constexpr int ROW_B = 272;                 // bytes per smem row
static constexpr int SM_B1 = 64;                  // 128 f32
static constexpr int SM_W2V = 576;                // 128 f32
static constexpr int SM_B2 = 1088;                // 128 f32
static constexpr int SM_AH = 2048;
static constexpr int ABUF  = 64 * ROW_B;          // 17408
static constexpr int SM_AL = SM_AH + ABUF;        // 19456
static constexpr int SM_BH = SM_AL + ABUF;        // 36864
static constexpr int BBUF  = 128 * ROW_B;         // 34816
static constexpr int SM_BL = SM_BH + BBUF;        // 71680
static constexpr int SM_TOTAL = SM_BL + BBUF;     // 106496

// ---------------- helpers ---------------------------------------------------
__device__ __forceinline__ uint32_t smem_u32(const void* p) {
    uint32_t a;
    asm("{ .reg .u64 t; cvta.to.shared.u64 t, %1; cvt.u32.u64 %0, t; }"
        : "=r"(a) : "l"(p));
    return a;
}

#define LDSM_X4(R0, R1, R2, R3, ADDR) \
    asm volatile("ldmatrix.sync.aligned.m8n8.x4.shared.b16 {%0,%1,%2,%3}, [%4];" \
                 : "=r"(R0), "=r"(R1), "=r"(R2), "=r"(R3) : "r"(ADDR))

__device__ __forceinline__ void mma16816(float* c, const uint32_t* a,
                                         const uint32_t* b) {
    asm volatile(
        "mma.sync.aligned.m16n8k16.row.col.f32.bf16.bf16.f32 "
        "{%0,%1,%2,%3}, {%4,%5,%6,%7}, {%8,%9}, {%0,%1,%2,%3};"
        : "+f"(c[0]), "+f"(c[1]), "+f"(c[2]), "+f"(c[3])
        : "r"(a[0]), "r"(a[1]), "r"(a[2]), "r"(a[3]), "r"(b[0]), "r"(b[1]));
}

__device__ __forceinline__ uint32_t pack_bf2(float a, float b) {
    __nv_bfloat162 t = __floats2bfloat162_rn(a, b);
    return *reinterpret_cast<uint32_t*>(&t);
}

__device__ __forceinline__ void split2(float x, float y, uint32_t& H, uint32_t& L) {
    __nv_bfloat16 hx = __float2bfloat16(x);
    __nv_bfloat16 hy = __float2bfloat16(y);
    float lx = x - __bfloat162float(hx);
    float ly = y - __bfloat162float(hy);
    H = pack_bf2(__bfloat162float(hx), __bfloat162float(hy));
    L = pack_bf2(lx, ly);
}

// ---------------- small utility kernels ------------------------------------
__global__ void convert_idx_kernel(const void* __restrict__ raw,
                                   int* __restrict__ st, int* __restrict__ en,
                                   int E) {
    __shared__ int s_is64;
    if (threadIdx.x == 0) {
        const unsigned int* w = (const unsigned int*)raw;
        unsigned int acc = 0;
        #pragma unroll 8
        for (int i = 0; i < 128; ++i) acc |= w[2 * i + 1];
        s_is64 = (acc == 0u);
    }
    __syncthreads();
    const int is64 = s_is64;
    int i = blockIdx.x * blockDim.x + threadIdx.x;
    if (i >= 2 * E) return;
    int v;
    if (is64) v = (int)((const long long*)raw)[i];
    else      v = ((const int*)raw)[i];
    if (i < E) st[i] = v; else en[i - E] = v;
}

__global__ void zero_kernel(float4* __restrict__ p, int n4) {
    int i = blockIdx.x * blockDim.x + threadIdx.x;
    if (i < n4) p[i] = make_float4(0.f, 0.f, 0.f, 0.f);
}

__global__ void scatter_add_kernel(const float* __restrict__ e,
                                   const int* __restrict__ end,
                                   float* __restrict__ msg, int E) {
    long long i = (long long)blockIdx.x * blockDim.x + threadIdx.x;
    if (i >= (long long)E * 32) return;
    int edge = (int)(i >> 5);
    int c4   = (int)(i & 31);
    float4 v = ((const float4*)(e + (size_t)edge * DD))[c4];
    float* dst = msg + (size_t)end[edge] * DD + c4 * 4;
    atomicAdd(dst + 0, v.x);
    atomicAdd(dst + 1, v.y);
    atomicAdd(dst + 2, v.z);
    atomicAdd(dst + 3, v.w);
}

// Pack weights transposed: image[chunk][n][k] = W[(koff+k)*128 + n], bf16 hi/lo.
// 0:ne_W1(k<16) 1:ne_W2  2-3:ee_W1(a,b) 4:ee_W2  5-6:nn_W1 7:nn_W2
// 8-10:en_W1(a,b,c) 11:en_W2  12-14:pe_W1(a,b,c)
__global__ void pack_w_kernel(const float* neW1, const float* neW2,
                              const float* eeW1, const float* eeW2,
                              const float* nnW1, const float* nnW2,
                              const float* enW1, const float* enW2,
                              const float* peW1,
                              __nv_bfloat16* gh, __nv_bfloat16* gl) {
    int t = blockIdx.x * blockDim.x + threadIdx.x;
    if (t >= 15 * 16384) return;
    int chunk = t >> 14;
    int e = t & 16383;
    int k = e & 127;
    int n = e >> 7;
    const float* W; int koff = 0; int kvalid = 128;
    switch (chunk) {
        case 0:  W = neW1; kvalid = 16; break;
        case 1:  W = neW2; break;
        case 2: case 3:  W = eeW1; koff = (chunk - 2) * 128; break;
        case 4:  W = eeW2; break;
        case 5: case 6:  W = nnW1; koff = (chunk - 5) * 128; break;
        case 7:  W = nnW2; break;
        case 8: case 9: case 10: W = enW1; koff = (chunk - 8) * 128; break;
        case 11: W = enW2; break;
        default: W = peW1; koff = (chunk - 12) * 128; break;
    }
    float x = (k < kvalid) ? W[(size_t)(koff + k) * 128 + n] : 0.f;
    __nv_bfloat16 h = __float2bfloat16(x);
    __nv_bfloat16 l = __float2bfloat16(x - __bfloat162float(h));
    gh[(size_t)chunk * 16384 + n * 128 + k] = h;
    gl[(size_t)chunk * 16384 + n * 128 + k] = l;
}

// copy prepacked weight chunk -> smem hi/lo B tiles
__device__ __forceinline__ void copy_w(char* smem, int tid, int chunk) {
    const int4* srcH = (const int4*)(g_pwh + (size_t)chunk * 16384);
    const int4* srcL = (const int4*)(g_pwl + (size_t)chunk * 16384);
    #pragma unroll
    for (int i = tid; i < 2048; i += 256) {
        int rr = i >> 4, q = i & 15;
        *(int4*)(smem + SM_BH + rr * ROW_B + q * 16) = srcH[i];
        *(int4*)(smem + SM_BL + rr * ROW_B + q * 16) = srcL[i];
    }
}

// 3-term split GEMM, warp tile 32(M) x 32(N), fused fragment loads.
template <int KSTEPS>
__device__ __forceinline__ void gemm3(uint32_t sb, int m0, int n0,
                                      int a_ro, int a_co, int b_ro, int b_co,
                                      float acc[2][4][4]) {
    #pragma unroll
    for (int ks = 0; ks < KSTEPS; ++ks) {
        const int k0 = ks * 16;
        uint32_t afh[2][4], afl[2][4];
        #pragma unroll
        for (int ma = 0; ma < 2; ++ma) {
            uint32_t ro = (uint32_t)(m0 + ma * 16 + a_ro) * ROW_B +
                          (uint32_t)(k0 + a_co) * 2;
            LDSM_X4(afh[ma][0], afh[ma][1], afh[ma][2], afh[ma][3], sb + SM_AH + ro);
            LDSM_X4(afl[ma][0], afl[ma][1], afl[ma][2], afl[ma][3], sb + SM_AL + ro);
        }
        uint32_t bh[4][2], bl[4][2];
        #pragma unroll
        for (int nb = 0; nb < 2; ++nb) {
            uint32_t ro = (uint32_t)(n0 + nb * 16 + b_ro) * ROW_B +
                          (uint32_t)(k0 + b_co) * 2;
            uint32_t r0, r1, r2, r3;
            LDSM_X4(r0, r1, r2, r3, sb + SM_BH + ro);
            bh[nb * 2][0] = r0; bh[nb * 2][1] = r1;
            bh[nb * 2 + 1][0] = r2; bh[nb * 2 + 1][1] = r3;
            LDSM_X4(r0, r1, r2, r3, sb + SM_BL + ro);
            bl[nb * 2][0] = r0; bl[nb * 2][1] = r1;
            bl[nb * 2 + 1][0] = r2; bl[nb * 2 + 1][1] = r3;
        }
        #pragma unroll
        for (int ma = 0; ma < 2; ++ma)
            #pragma unroll
            for (int na = 0; na < 4; ++na) {
                mma16816(acc[ma][na], afh[ma], bh[na]);
                mma16816(acc[ma][na], afh[ma], bl[na]);
                mma16816(acc[ma][na], afl[ma], bh[na]);
            }
    }
}

// stage 64 rows x SRC_K fp32 (optional gather) into A hi/lo smem tiles
template <int SRC_K>
__device__ __forceinline__ void stage_a(char* smem, int wid, int lane, int row0,
                                        const float* __restrict__ src,
                                        const int* __restrict__ idx, int nrows) {
    for (int r = wid; r < 64; r += 8) {
        int grow = row0 + r;
        float4 v = make_float4(0.f, 0.f, 0.f, 0.f);
        if (grow < nrows && lane < SRC_K / 4) {
            int sr = idx ? idx[grow] : grow;
            v = ((const float4*)(src + (size_t)sr * SRC_K))[lane];
        }
        if (lane < SRC_K / 4) {
            uint32_t h0, l0, h1, l1;
            split2(v.x, v.y, h0, l0);
            split2(v.z, v.w, h1, l1);
            uint32_t off = r * ROW_B + lane * 8;
            *(uint2*)(smem + SM_AH + off) = make_uint2(h0, h1);
            *(uint2*)(smem + SM_AL + off) = make_uint2(l0, l1);
        }
    }
}

// ---------------------------------------------------------------------------
// Node precompute: outA = X @ Wchunk(cA), outB = X @ Wchunk(cB).  64 rows/CTA.
// ---------------------------------------------------------------------------
__global__ void __launch_bounds__(256, 2)
node_pre(const float* __restrict__ X, int cA, float* __restrict__ outA,
         int cB, float* __restrict__ outB, int nrows) {
    extern __shared__ char smem[];
    const uint32_t sb = smem_u32(smem);
    const int tid = threadIdx.x, lane = tid & 31, wid = tid >> 5;
    const int row0 = blockIdx.x * 64;
    const int g = lane >> 2, tig = lane & 3;
    const int m0 = (wid >> 2) * 32, n0 = (wid & 3) * 32;
    const int a_ro = (lane & 7) + ((lane >> 3) & 1) * 8;
    const int a_co = ((lane >> 4) & 1) * 8;
    const int b_ro = (lane & 7) + ((lane >> 4) & 1) * 8;
    const int b_co = ((lane >> 3) & 1) * 8;

    stage_a<128>(smem, wid, lane, row0, X, nullptr, nrows);
    copy_w(smem, tid, cA);
    __syncthreads();

    float acc[2][4][4];
    #pragma unroll
    for (int q = 0; q < 32; ++q) (&acc[0][0][0])[q] = 0.f;
    gemm3<8>(sb, m0, n0, a_ro, a_co, b_ro, b_co, acc);

    #pragma unroll
    for (int ma = 0; ma < 2; ++ma) {
        int rl = m0 + ma * 16 + g;
        #pragma unroll
        for (int na = 0; na < 4; ++na) {
            int cc = n0 + na * 8 + 2 * tig;
            int g0 = row0 + rl, g1 = g0 + 8;
            if (g0 < nrows)
                *(float2*)(outA + (size_t)g0 * DD + cc) =
                    make_float2(acc[ma][na][0], acc[ma][na][1]);
            if (g1 < nrows)
                *(float2*)(outA + (size_t)g1 * DD + cc) =
                    make_float2(acc[ma][na][2], acc[ma][na][3]);
        }
    }
    __syncthreads();
    copy_w(smem, tid, cB);
    __syncthreads();

    #pragma unroll
    for (int q = 0; q < 32; ++q) (&acc[0][0][0])[q] = 0.f;
    gemm3<8>(sb, m0, n0, a_ro, a_co, b_ro, b_co, acc);

    #pragma unroll
    for (int ma = 0; ma < 2; ++ma) {
        int rl = m0 + ma * 16 + g;
        #pragma unroll
        for (int na = 0; na < 4; ++na) {
            int cc = n0 + na * 8 + 2 * tig;
            int g0 = row0 + rl, g1 = g0 + 8;
            if (g0 < nrows)
                *(float2*)(outB + (size_t)g0 * DD + cc) =
                    make_float2(acc[ma][na][0], acc[ma][na][1]);
            if (g1 < nrows)
                *(float2*)(outB + (size_t)g1 * DD + cc) =
                    make_float2(acc[ma][na][2], acc[ma][na][3]);
        }
    }
}

// ---------------------------------------------------------------------------
// Fused 2-layer MLP, 64 rows/CTA, 256 thr (8 warps, 2Mx4N, warp tile 32x32).
//   layer1: acc = sum_c A_c @ W1_c  (+ PRE: Pa[ip0]+Pb[ip1] in epilogue)
//   hidden = relu(acc + b1) -> bf16 hi/lo A tiles
//   layer2: out = hidden @ W2 + b2 (+res)  |  OUT1: out = hidden . w2vec + b2
// ---------------------------------------------------------------------------
template <int NCHUNKS, int KSTEPS1, bool PRE, bool RES, bool OUT1>
__global__ void __launch_bounds__(256, 2)
mlp64(const float* __restrict__ s0, const float* __restrict__ s1,
      const int* __restrict__ ip0, const int* __restrict__ ip1,
      const float* __restrict__ Pa, const float* __restrict__ Pb,
      int w1_chunk, int w2_chunk,
      const float* __restrict__ b1, const float* __restrict__ b2,
      const float* __restrict__ w2vec,
      const float* __restrict__ res, float* __restrict__ out, int nrows) {
    extern __shared__ char smem[];
    const uint32_t sb = smem_u32(smem);
    const int tid = threadIdx.x, lane = tid & 31, wid = tid >> 5;
    const int row0 = blockIdx.x * 64;
    const int g = lane >> 2, tig = lane & 3;
    const int m0 = (wid >> 2) * 32, n0 = (wid & 3) * 32;
    const int a_ro = (lane & 7) + ((lane >> 3) & 1) * 8;
    const int a_co = ((lane >> 4) & 1) * 8;
    const int b_ro = (lane & 7) + ((lane >> 4) & 1) * 8;
    const int b_co = ((lane >> 3) & 1) * 8;

    float* b1s = (float*)(smem + SM_B1);
    float* b2s = (float*)(smem + SM_B2);
    float* w2s = (float*)(smem + SM_W2V);
    if (tid < 128) {
        b1s[tid] = b1[tid];
        if (OUT1) w2s[tid] = w2vec[tid];
        else      b2s[tid] = b2[tid];
    }
    __syncthreads();

    const float* srcs[2] = {s0, s1};

    float acc[2][4][4];
    #pragma unroll
    for (int q = 0; q < 32; ++q) (&acc[0][0][0])[q] = 0.f;

    // ---------------- layer 1 ----------------
    #pragma unroll
    for (int c = 0; c < NCHUNKS; ++c) {
        if (c) __syncthreads();
        stage_a<KSTEPS1 * 16>(smem, wid, lane, row0, srcs[c], nullptr, nrows);
        copy_w(smem, tid, w1_chunk + c);
        __syncthreads();
        gemm3<KSTEPS1>(sb, m0, n0, a_ro, a_co, b_ro, b_co, acc);
    }
    __syncthreads();  // all layer-1 smem reads complete

    // PRE: acc += Pa[ip0[row]][col] + Pb[ip1[row]][col]
    if constexpr (PRE) {
        #pragma unroll
        for (int ma = 0; ma < 2; ++ma) {
            int rl = m0 + ma * 16 + g;
            #pragma unroll
            for (int half = 0; half < 2; ++half) {
                int grow = row0 + rl + half * 8;
                if (grow < nrows) {
                    int ia = ip0[grow], ib = ip1[grow];
                    const float* pa = Pa + (size_t)ia * DD;
                    const float* pb = Pb + (size_t)ib * DD;
                    #pragma unroll
                    for (int na = 0; na < 4; ++na) {
                        int cc = n0 + na * 8 + 2 * tig;
                        float2 va = *(const float2*)(pa + cc);
                        float2 vb = *(const float2*)(pb + cc);
                        acc[ma][na][half * 2 + 0] += va.x + vb.x;
                        acc[ma][na][half * 2 + 1] += va.y + vb.y;
                    }
                }
            }
        }
    }

    if constexpr (OUT1) {
        // hidden fp32 -> smem [row][col] stride 129, then per-row dot
        float* hT = (float*)(smem + SM_AH);
        #pragma unroll
        for (int ma = 0; ma < 2; ++ma) {
            int rl = m0 + ma * 16 + g;
            #pragma unroll
            for (int na = 0; na < 4; ++na) {
                int cc = n0 + na * 8 + 2 * tig;
                hT[rl * 129 + cc]       = fmaxf(acc[ma][na][0] + b1s[cc], 0.f);
                hT[rl * 129 + cc + 1]   = fmaxf(acc[ma][na][1] + b1s[cc + 1], 0.f);
                hT[(rl + 8) * 129 + cc]     = fmaxf(acc[ma][na][2] + b1s[cc], 0.f);
                hT[(rl + 8) * 129 + cc + 1] = fmaxf(acc[ma][na][3] + b1s[cc + 1], 0.f);
            }
        }
        __syncthreads();
        if (tid < 64) {
            int grow = row0 + tid;
            float a = __ldg(&b2[0]);
            #pragma unroll 8
            for (int k = 0; k < 128; ++k) a += hT[tid * 129 + k] * w2s[k];
            if (grow < nrows) out[grow] = a;
        }
        return;
    }

    // hidden = relu(acc + b1) -> A tiles (bf16 hi/lo)
    #pragma unroll
    for (int ma = 0; ma < 2; ++ma) {
        int rl = m0 + ma * 16 + g;
        #pragma unroll
        for (int na = 0; na < 4; ++na) {
            int cc = n0 + na * 8 + 2 * tig;
            float v0 = fmaxf(acc[ma][na][0] + b1s[cc], 0.f);
            float v1 = fmaxf(acc[ma][na][1] + b1s[cc + 1], 0.f);
            float v2 = fmaxf(acc[ma][na][2] + b1s[cc], 0.f);
            float v3 = fmaxf(acc[ma][na][3] + b1s[cc + 1], 0.f);
            uint32_t H, L;
            split2(v0, v1, H, L);
            *(uint32_t*)(smem + SM_AH + rl * ROW_B + cc * 2) = H;
            *(uint32_t*)(smem + SM_AL + rl * ROW_B + cc * 2) = L;
            split2(v2, v3, H, L);
            *(uint32_t*)(smem + SM_AH + (rl + 8) * ROW_B + cc * 2) = H;
            *(uint32_t*)(smem + SM_AL + (rl + 8) * ROW_B + cc * 2) = L;
        }
    }
    copy_w(smem, tid, w2_chunk);
    __syncthreads();

    // ---------------- layer 2 ----------------
    #pragma unroll
    for (int q = 0; q < 32; ++q) (&acc[0][0][0])[q] = 0.f;
    gemm3<8>(sb, m0, n0, a_ro, a_co, b_ro, b_co, acc);

    // epilogue: out = acc + b2 (+ res)
    #pragma unroll
    for (int ma = 0; ma < 2; ++ma) {
        int rl = m0 + ma * 16 + g;
        int g0 = row0 + rl, g1 = g0 + 8;
        #pragma unroll
        for (int na = 0; na < 4; ++na) {
            int cc = n0 + na * 8 + 2 * tig;
            float bx = b2s[cc], by = b2s[cc + 1];
            if (g0 < nrows) {
                float2 o = make_float2(acc[ma][na][0] + bx, acc[ma][na][1] + by);
                if (RES) {
                    float2 rv = *(const float2*)(res + (size_t)g0 * DD + cc);
                    o.x += rv.x; o.y += rv.y;
                }
                *(float2*)(out + (size_t)g0 * DD + cc) = o;
            }
            if (g1 < nrows) {
                float2 o = make_float2(acc[ma][na][2] + bx, acc[ma][na][3] + by);
                if (RES) {
                    float2 rv = *(const float2*)(res + (size_t)g1 * DD + cc);
                    o.x += rv.x; o.y += rv.y;
                }
                *(float2*)(out + (size_t)g1 * DD + cc) = o;
            }
        }
    }
}

// ---------------------------------------------------------------------------
extern "C" void kernel_launch(void* const* d_in, const int* in_sizes, int n_in,
                              void* d_out, int out_size) {
    const float* nodes = (const float*)d_in[0];
    const void*  eidx  = d_in[1];
    const float* ne_W1 = (const float*)d_in[2];
    const float* ne_b1 = (const float*)d_in[3];
    const float* ne_W2 = (const float*)d_in[4];
    const float* ne_b2 = (const float*)d_in[5];
    const float* ee_W1 = (const float*)d_in[6];
    const float* ee_b1 = (const float*)d_in[7];
    const float* ee_W2 = (const float*)d_in[8];
    const float* ee_b2 = (const float*)d_in[9];
    const float* nn_W1 = (const float*)d_in[10];
    const float* nn_b1 = (const float*)d_in[11];
    const float* nn_W2 = (const float*)d_in[12];
    const float* nn_b2 = (const float*)d_in[13];
    const float* en_W1 = (const float*)d_in[14];
    const float* en_b1 = (const float*)d_in[15];
    const float* en_W2 = (const float*)d_in[16];
    const float* en_b2 = (const float*)d_in[17];
    const float* pe_W1 = (const float*)d_in[18];
    const float* pe_b1 = (const float*)d_in[19];
    const float* pe_W2 = (const float*)d_in[20];
    const float* pe_b2 = (const float*)d_in[21];

    float *h, *h2, *msg, *e, *pa, *pb;
    int *st, *en_;
    cudaGetSymbolAddress((void**)&h,   g_h);
    cudaGetSymbolAddress((void**)&h2,  g_h2);
    cudaGetSymbolAddress((void**)&msg, g_msg);
    cudaGetSymbolAddress((void**)&e,   g_e);
    cudaGetSymbolAddress((void**)&pa,  g_pa);
    cudaGetSymbolAddress((void**)&pb,  g_pb);
    cudaGetSymbolAddress((void**)&st,  g_start);
    cudaGetSymbolAddress((void**)&en_, g_end);

    cudaFuncSetAttribute(node_pre,
                         cudaFuncAttributeMaxDynamicSharedMemorySize, SM_TOTAL);
    cudaFuncSetAttribute(mlp64<1, 1, false, false, false>,
                         cudaFuncAttributeMaxDynamicSharedMemorySize, SM_TOTAL);
    cudaFuncSetAttribute(mlp64<2, 8, false, true, false>,
                         cudaFuncAttributeMaxDynamicSharedMemorySize, SM_TOTAL);
    cudaFuncSetAttribute(mlp64<0, 8, true, false, false>,
                         cudaFuncAttributeMaxDynamicSharedMemorySize, SM_TOTAL);
    cudaFuncSetAttribute(mlp64<1, 8, true, true, false>,
                         cudaFuncAttributeMaxDynamicSharedMemorySize, SM_TOTAL);
    cudaFuncSetAttribute(mlp64<1, 8, true, false, true>,
                         cudaFuncAttributeMaxDynamicSharedMemorySize, SM_TOTAL);

    const int nblk_n = (N_NODES + 63) / 64;  // 1563
    const int nblk_e = (N_EDGES + 63) / 64;  // 9375

    convert_idx_kernel<<<(2 * N_EDGES + 255) / 256, 256>>>(eidx, st, en_, N_EDGES);
    pack_w_kernel<<<(15 * 16384 + 255) / 256, 256>>>(
        ne_W1, ne_W2, ee_W1, ee_W2, nn_W1, nn_W2, en_W1, en_W2, pe_W1,
        g_pwh, g_pwl);  // device symbols resolve via cudaGetSymbolAddress below
    // NOTE: pass actual addresses (device symbols not directly usable as args)
    // -> re-launch with proper pointers:
    {
        __nv_bfloat16 *pwh, *pwl;
        cudaGetSymbolAddress((void**)&pwh, g_pwh);
        cudaGetSymbolAddress((void**)&pwl, g_pwl);
        pack_w_kernel<<<(15 * 16384 + 255) / 256, 256>>>(
            ne_W1, ne_W2, ee_W1, ee_W2, nn_W1, nn_W2, en_W1, en_W2, pe_W1,
            pwh, pwl);
    }

    // 1) h = MLP_ne(nodes)
    mlp64<1, 1, false, false, false><<<nblk_n, 256, SM_TOTAL>>>(
        nodes, nullptr, nullptr, nullptr, nullptr, nullptr,
        0, 1, ne_b1, ne_b2, nullptr, nullptr, h, N_NODES);

    // 2) Pa,Pb = h@eeW1a, h@eeW1b ; e = relu(Pa[s]+Pb[e]+b1)@eeW2 + b2
    node_pre<<<nblk_n, 256, SM_TOTAL>>>(h, 2, pa, 3, pb, N_NODES);
    mlp64<0, 8, true, false, false><<<nblk_e, 256, SM_TOTAL>>>(
        nullptr, nullptr, st, en_, pa, pb,
        0, 4, ee_b1, ee_b2, nullptr, nullptr, e, N_EDGES);

    float* hA = h;
    float* hB = h2;
    const int zero_n4   = N_NODES * DD / 4;
    const int zero_blks = (zero_n4 + 255) / 256;
    const long long sc_thr = (long long)N_EDGES * 32;
    const int sc_blks = (int)((sc_thr + 255) / 256);

    for (int it = 0; it < NUM_ITERS; ++it) {
        zero_kernel<<<zero_blks, 256>>>((float4*)msg, zero_n4);
        scatter_add_kernel<<<sc_blks, 256>>>(e, en_, msg, N_EDGES);

        // h_new = MLP_nn(h || msg) + h
        mlp64<2, 8, false, true, false><<<nblk_n, 256, SM_TOTAL>>>(
            hA, msg, nullptr, nullptr, nullptr, nullptr,
            5, 7, nn_b1, nn_b2, nullptr, hA, hB, N_NODES);

        // Qa,Qb = hA@enW1a, hA@enW1b (old h)
        node_pre<<<nblk_n, 256, SM_TOTAL>>>(hA, 8, pa, 9, pb, N_NODES);

        // e = (relu(e@enW1c + Qa[s]+Qb[e]+b1) @ enW2 + b2) + e
        mlp64<1, 8, true, true, false><<<nblk_e, 256, SM_TOTAL>>>(
            e, nullptr, st, en_, pa, pb,
            10, 11, en_b1, en_b2, nullptr, e, e, N_EDGES);

        float* t = hA; hA = hB; hB = t;
    }

    // 3) Ra,Rb = h@peW1a, h@peW1b ; pred = relu(e@peW1c + Ra[s]+Rb[e]+b1).w2 + b2
    node_pre<<<nblk_n, 256, SM_TOTAL>>>(hA, 12, pa, 13, pb, N_NODES);
    mlp64<1, 8, true, false, true><<<nblk_e, 256, SM_TOTAL>>>(
        e, nullptr, st, en_, pa, pb,
        14, 0, pe_b1, pe_b2, pe_W2, nullptr, (float*)d_out, N_EDGES);
}

// round 5
// speedup vs baseline: 6.3224x; 1.1552x over previous
#include <cuda_runtime.h>
#include <cuda_bf16.h>
#include <cstdint>

// ---------------------------------------------------------------------------
// InteractionGNN on GB300 — round 5: fused node kernels (MLP + Q/R precompute),
// scatter fused into edge epilogues, cp.async weight staging, L2 prefetch.
// GEMM core: mma.sync bf16 3-term split (Ah*Wh + Ah*Wl + Al*Wh), fp32 accum.
// ---------------------------------------------------------------------------

#define N_NODES 100000
#define N_EDGES 600000
#define DD      128
#define NUM_ITERS 4

// ---------------- device scratch -------------------------------------------
__device__ float g_h  [(size_t)N_NODES * DD];
__device__ float g_h2 [(size_t)N_NODES * DD];
__device__ float g_m0 [(size_t)N_NODES * DD];
__device__ float g_m1 [(size_t)N_NODES * DD];
__device__ float g_e  [(size_t)N_EDGES * DD];
__device__ float g_pa [(size_t)N_NODES * DD];
__device__ float g_pb [(size_t)N_NODES * DD];
__device__ float g_pc [(size_t)N_NODES * DD];
__device__ float g_pd [(size_t)N_NODES * DD];
__device__ int   g_start[N_EDGES];
__device__ int   g_end  [N_EDGES];
// prepacked weights: 15 chunks x [128 n][128 k] bf16, hi and lo images
__device__ __nv_bfloat16 g_pwh[15 * 16384];
__device__ __nv_bfloat16 g_pwl[15 * 16384];

// ---------------- smem layout ------------------------------------------------
static constexpr int ROW_B  = 272;
static constexpr int SM_B1  = 64;     // 128 f32
static constexpr int SM_W2V = 576;    // 128 f32
static constexpr int SM_B2  = 1088;   // 128 f32
static constexpr int SM_IA  = 1600;   // 64 ints
static constexpr int SM_IB  = 1856;   // 64 ints
static constexpr int SM_AH  = 2176;
static constexpr int ABUF   = 64 * ROW_B;          // 17408
static constexpr int SM_AL  = SM_AH + ABUF;        // 19584
static constexpr int SM_BH  = SM_AL + ABUF;        // 36992
static constexpr int BBUF   = 128 * ROW_B;         // 34816
static constexpr int SM_BL  = SM_BH + BBUF;        // 71808
static constexpr int SM_TOTAL = SM_BL + BBUF;      // 106624

// ---------------- helpers -----------------------------------------------------
__device__ __forceinline__ uint32_t smem_u32(const void* p) {
    uint32_t a;
    asm("{ .reg .u64 t; cvta.to.shared.u64 t, %1; cvt.u32.u64 %0, t; }"
        : "=r"(a) : "l"(p));
    return a;
}

#define LDSM_X4(R0, R1, R2, R3, ADDR) \
    asm volatile("ldmatrix.sync.aligned.m8n8.x4.shared.b16 {%0,%1,%2,%3}, [%4];" \
                 : "=r"(R0), "=r"(R1), "=r"(R2), "=r"(R3) : "r"(ADDR))

__device__ __forceinline__ void mma16816(float* c, const uint32_t* a,
                                         const uint32_t* b) {
    asm volatile(
        "mma.sync.aligned.m16n8k16.row.col.f32.bf16.bf16.f32 "
        "{%0,%1,%2,%3}, {%4,%5,%6,%7}, {%8,%9}, {%0,%1,%2,%3};"
        : "+f"(c[0]), "+f"(c[1]), "+f"(c[2]), "+f"(c[3])
        : "r"(a[0]), "r"(a[1]), "r"(a[2]), "r"(a[3]), "r"(b[0]), "r"(b[1]));
}

__device__ __forceinline__ uint32_t pack_bf2(float a, float b) {
    __nv_bfloat162 t = __floats2bfloat162_rn(a, b);
    return *reinterpret_cast<uint32_t*>(&t);
}

__device__ __forceinline__ void split2(float x, float y, uint32_t& H, uint32_t& L) {
    __nv_bfloat16 hx = __float2bfloat16(x);
    __nv_bfloat16 hy = __float2bfloat16(y);
    float lx = x - __bfloat162float(hx);
    float ly = y - __bfloat162float(hy);
    H = pack_bf2(__bfloat162float(hx), __bfloat162float(hy));
    L = pack_bf2(lx, ly);
}

#define CP_WAIT_ALL() asm volatile("cp.async.wait_group 0;" ::: "memory")

// async copy of a prepacked weight chunk into B hi/lo smem tiles
__device__ __forceinline__ void copyw_async(uint32_t sb, int tid, int chunk) {
    const char* srcH = (const char*)(g_pwh + (size_t)chunk * 16384);
    const char* srcL = (const char*)(g_pwl + (size_t)chunk * 16384);
    #pragma unroll
    for (int i = tid; i < 2048; i += 256) {
        int rr = i >> 4, q = i & 15;
        uint32_t d = sb + SM_BH + rr * ROW_B + q * 16;
        asm volatile("cp.async.cg.shared.global [%0], [%1], 16;"
                     :: "r"(d), "l"(srcH + i * 16));
        asm volatile("cp.async.cg.shared.global [%0], [%1], 16;"
                     :: "r"(d + (uint32_t)(SM_BL - SM_BH)), "l"(srcL + i * 16));
    }
    asm volatile("cp.async.commit_group;" ::: "memory");
}

// 3-term split GEMM, warp tile 32(M) x 32(N)
template <int KSTEPS>
__device__ __forceinline__ void gemm3(uint32_t sb, int m0, int n0,
                                      int a_ro, int a_co, int b_ro, int b_co,
                                      float acc[2][4][4]) {
    #pragma unroll
    for (int ks = 0; ks < KSTEPS; ++ks) {
        const int k0 = ks * 16;
        uint32_t afh[2][4], afl[2][4];
        #pragma unroll
        for (int ma = 0; ma < 2; ++ma) {
            uint32_t ro = (uint32_t)(m0 + ma * 16 + a_ro) * ROW_B +
                          (uint32_t)(k0 + a_co) * 2;
            LDSM_X4(afh[ma][0], afh[ma][1], afh[ma][2], afh[ma][3], sb + SM_AH + ro);
            LDSM_X4(afl[ma][0], afl[ma][1], afl[ma][2], afl[ma][3], sb + SM_AL + ro);
        }
        uint32_t bh[4][2], bl[4][2];
        #pragma unroll
        for (int nb = 0; nb < 2; ++nb) {
            uint32_t ro = (uint32_t)(n0 + nb * 16 + b_ro) * ROW_B +
                          (uint32_t)(k0 + b_co) * 2;
            uint32_t r0, r1, r2, r3;
            LDSM_X4(r0, r1, r2, r3, sb + SM_BH + ro);
            bh[nb * 2][0] = r0; bh[nb * 2][1] = r1;
            bh[nb * 2 + 1][0] = r2; bh[nb * 2 + 1][1] = r3;
            LDSM_X4(r0, r1, r2, r3, sb + SM_BL + ro);
            bl[nb * 2][0] = r0; bl[nb * 2][1] = r1;
            bl[nb * 2 + 1][0] = r2; bl[nb * 2 + 1][1] = r3;
        }
        #pragma unroll
        for (int ma = 0; ma < 2; ++ma)
            #pragma unroll
            for (int na = 0; na < 4; ++na) {
                mma16816(acc[ma][na], afh[ma], bh[na]);
                mma16816(acc[ma][na], afh[ma], bl[na]);
                mma16816(acc[ma][na], afl[ma], bh[na]);
            }
    }
}

__device__ __forceinline__ void zacc(float acc[2][4][4]) {
    #pragma unroll
    for (int q = 0; q < 32; ++q) (&acc[0][0][0])[q] = 0.f;
}

// stage 64 rows x SRC_K fp32 into A hi/lo smem tiles (contiguous rows)
template <int SRC_K>
__device__ __forceinline__ void stage_a(char* smem, int wid, int lane, int row0,
                                        const float* __restrict__ src, int nrows) {
    for (int r = wid; r < 64; r += 8) {
        int grow = row0 + r;
        float4 v = make_float4(0.f, 0.f, 0.f, 0.f);
        if (grow < nrows && lane < SRC_K / 4)
            v = ((const float4*)(src + (size_t)grow * SRC_K))[lane];
        if (lane < SRC_K / 4) {
            uint32_t h0, l0, h1, l1;
            split2(v.x, v.y, h0, l0);
            split2(v.z, v.w, h1, l1);
            uint32_t off = r * ROW_B + lane * 8;
            *(uint2*)(smem + SM_AH + off) = make_uint2(h0, h1);
            *(uint2*)(smem + SM_AL + off) = make_uint2(l0, l1);
        }
    }
}

// split acc (optional bias+relu) into A hi/lo tiles
__device__ __forceinline__ void acc_to_A(char* smem, float acc[2][4][4],
                                         int m0, int n0, int g, int tig,
                                         const float* b1s, bool relu) {
    #pragma unroll
    for (int ma = 0; ma < 2; ++ma) {
        int rl = m0 + ma * 16 + g;
        #pragma unroll
        for (int na = 0; na < 4; ++na) {
            int cc = n0 + na * 8 + 2 * tig;
            float bx = b1s ? b1s[cc] : 0.f;
            float by = b1s ? b1s[cc + 1] : 0.f;
            float v0 = acc[ma][na][0] + bx, v1 = acc[ma][na][1] + by;
            float v2 = acc[ma][na][2] + bx, v3 = acc[ma][na][3] + by;
            if (relu) {
                v0 = fmaxf(v0, 0.f); v1 = fmaxf(v1, 0.f);
                v2 = fmaxf(v2, 0.f); v3 = fmaxf(v3, 0.f);
            }
            uint32_t H, L;
            split2(v0, v1, H, L);
            *(uint32_t*)(smem + SM_AH + rl * ROW_B + cc * 2) = H;
            *(uint32_t*)(smem + SM_AL + rl * ROW_B + cc * 2) = L;
            split2(v2, v3, H, L);
            *(uint32_t*)(smem + SM_AH + (rl + 8) * ROW_B + cc * 2) = H;
            *(uint32_t*)(smem + SM_AL + (rl + 8) * ROW_B + cc * 2) = L;
        }
    }
}

// raw store of acc to out[row][col]
__device__ __forceinline__ void acc_store(float* __restrict__ out,
                                          float acc[2][4][4], int row0,
                                          int m0, int n0, int g, int tig,
                                          int nrows) {
    #pragma unroll
    for (int ma = 0; ma < 2; ++ma) {
        int rl = m0 + ma * 16 + g;
        int g0 = row0 + rl, g1 = g0 + 8;
        #pragma unroll
        for (int na = 0; na < 4; ++na) {
            int cc = n0 + na * 8 + 2 * tig;
            if (g0 < nrows)
                *(float2*)(out + (size_t)g0 * DD + cc) =
                    make_float2(acc[ma][na][0], acc[ma][na][1]);
            if (g1 < nrows)
                *(float2*)(out + (size_t)g1 * DD + cc) =
                    make_float2(acc[ma][na][2], acc[ma][na][3]);
        }
    }
}

// ---------------- small utility kernels ------------------------------------
__global__ void convert_idx_kernel(const void* __restrict__ raw,
                                   int* __restrict__ st, int* __restrict__ en,
                                   int E) {
    __shared__ int s_is64;
    if (threadIdx.x == 0) {
        const unsigned int* w = (const unsigned int*)raw;
        unsigned int acc = 0;
        #pragma unroll 8
        for (int i = 0; i < 128; ++i) acc |= w[2 * i + 1];
        s_is64 = (acc == 0u);
    }
    __syncthreads();
    const int is64 = s_is64;
    int i = blockIdx.x * blockDim.x + threadIdx.x;
    if (i >= 2 * E) return;
    int v;
    if (is64) v = (int)((const long long*)raw)[i];
    else      v = ((const int*)raw)[i];
    if (i < E) st[i] = v; else en[i - E] = v;
}

__global__ void zero_kernel(float4* __restrict__ p, int n4) {
    int i = blockIdx.x * blockDim.x + threadIdx.x;
    if (i < n4) p[i] = make_float4(0.f, 0.f, 0.f, 0.f);
}

// Pack weights transposed: image[chunk][n][k] = W[(koff+k)*128 + n], bf16 hi/lo.
// 0:ne_W1(k<16) 1:ne_W2  2-3:ee_W1(a,b) 4:ee_W2  5-6:nn_W1 7:nn_W2
// 8-10:en_W1(a,b,c) 11:en_W2  12-14:pe_W1(a,b,c)
__global__ void pack_w_kernel(const float* neW1, const float* neW2,
                              const float* eeW1, const float* eeW2,
                              const float* nnW1, const float* nnW2,
                              const float* enW1, const float* enW2,
                              const float* peW1,
                              __nv_bfloat16* gh, __nv_bfloat16* gl) {
    int t = blockIdx.x * blockDim.x + threadIdx.x;
    if (t >= 15 * 16384) return;
    int chunk = t >> 14;
    int e = t & 16383;
    int k = e & 127;
    int n = e >> 7;
    const float* W; int koff = 0; int kvalid = 128;
    switch (chunk) {
        case 0:  W = neW1; kvalid = 16; break;
        case 1:  W = neW2; break;
        case 2: case 3:  W = eeW1; koff = (chunk - 2) * 128; break;
        case 4:  W = eeW2; break;
        case 5: case 6:  W = nnW1; koff = (chunk - 5) * 128; break;
        case 7:  W = nnW2; break;
        case 8: case 9: case 10: W = enW1; koff = (chunk - 8) * 128; break;
        case 11: W = enW2; break;
        default: W = peW1; koff = (chunk - 12) * 128; break;
    }
    float x = (k < kvalid) ? W[(size_t)(koff + k) * 128 + n] : 0.f;
    __nv_bfloat16 h = __float2bfloat16(x);
    __nv_bfloat16 l = __float2bfloat16(x - __bfloat162float(h));
    gh[(size_t)chunk * 16384 + n * 128 + k] = h;
    gl[(size_t)chunk * 16384 + n * 128 + k] = l;
}

// ---------------------------------------------------------------------------
// Fused node kernel.  64 rows/CTA, 256 thr.
//   optional PRE2: Qa = s0@W[wqa], Qb = s0@W[wqb]   (reuses staged s0 tile)
//   MLP: acc = sum over NCH chunks (s0, s1) @ W1;  h' = relu(acc+b1)@W2 + b2 (+res)
//   optional POST2: Ra = h'@W[wra], Rb = h'@W[wrb]
// ---------------------------------------------------------------------------
template <int NCH, int KS1, bool PRE2, bool POST2, bool RES>
__global__ void __launch_bounds__(256, 2)
node_fused(const float* __restrict__ s0, const float* __restrict__ s1,
           int wqa, int wqb, float* __restrict__ Qa, float* __restrict__ Qb,
           int w1c0, int w2c,
           int wra, int wrb, float* __restrict__ Ra, float* __restrict__ Rb,
           const float* __restrict__ b1, const float* __restrict__ b2,
           const float* __restrict__ res, float* __restrict__ out, int nrows) {
    extern __shared__ char smem[];
    const uint32_t sb = smem_u32(smem);
    const int tid = threadIdx.x, lane = tid & 31, wid = tid >> 5;
    const int row0 = blockIdx.x * 64;
    const int g = lane >> 2, tig = lane & 3;
    const int m0 = (wid >> 2) * 32, n0 = (wid & 3) * 32;
    const int a_ro = (lane & 7) + ((lane >> 3) & 1) * 8;
    const int a_co = ((lane >> 4) & 1) * 8;
    const int b_ro = (lane & 7) + ((lane >> 4) & 1) * 8;
    const int b_co = ((lane >> 3) & 1) * 8;

    float* b1s = (float*)(smem + SM_B1);
    float* b2s = (float*)(smem + SM_B2);
    if (tid < 128) { b1s[tid] = b1[tid]; b2s[tid] = b2[tid]; }

    float acc[2][4][4];

    // stage first input chunk; first weight copy overlaps the split math
    copyw_async(sb, tid, PRE2 ? wqa : w1c0);
    stage_a<KS1 * 16>(smem, wid, lane, row0, s0, nrows);
    CP_WAIT_ALL();
    __syncthreads();

    if constexpr (PRE2) {
        zacc(acc);
        gemm3<KS1>(sb, m0, n0, a_ro, a_co, b_ro, b_co, acc);
        acc_store(Qa, acc, row0, m0, n0, g, tig, nrows);
        __syncthreads();
        copyw_async(sb, tid, wqb);
        CP_WAIT_ALL();
        __syncthreads();
        zacc(acc);
        gemm3<KS1>(sb, m0, n0, a_ro, a_co, b_ro, b_co, acc);
        acc_store(Qb, acc, row0, m0, n0, g, tig, nrows);
        __syncthreads();
        copyw_async(sb, tid, w1c0);
        CP_WAIT_ALL();
        __syncthreads();
    }

    zacc(acc);
    gemm3<KS1>(sb, m0, n0, a_ro, a_co, b_ro, b_co, acc);

    if constexpr (NCH == 2) {
        __syncthreads();
        copyw_async(sb, tid, w1c0 + 1);
        stage_a<128>(smem, wid, lane, row0, s1, nrows);
        CP_WAIT_ALL();
        __syncthreads();
        gemm3<8>(sb, m0, n0, a_ro, a_co, b_ro, b_co, acc);
    }
    __syncthreads();

    // hidden = relu(acc + b1) -> A tiles; W2 copy overlaps the split
    copyw_async(sb, tid, w2c);
    acc_to_A(smem, acc, m0, n0, g, tig, b1s, true);
    CP_WAIT_ALL();
    __syncthreads();

    zacc(acc);
    gemm3<8>(sb, m0, n0, a_ro, a_co, b_ro, b_co, acc);

    // fold bias (+residual) into acc, then store h'
    #pragma unroll
    for (int ma = 0; ma < 2; ++ma) {
        int rl = m0 + ma * 16 + g;
        #pragma unroll
        for (int half = 0; half < 2; ++half) {
            int grow = row0 + rl + half * 8;
            #pragma unroll
            for (int na = 0; na < 4; ++na) {
                int cc = n0 + na * 8 + 2 * tig;
                float bx = b2s[cc], by = b2s[cc + 1];
                float rx = 0.f, ry = 0.f;
                if (RES && grow < nrows) {
                    float2 rv = *(const float2*)(res + (size_t)grow * DD + cc);
                    rx = rv.x; ry = rv.y;
                }
                acc[ma][na][half * 2 + 0] += bx + rx;
                acc[ma][na][half * 2 + 1] += by + ry;
            }
        }
    }
    acc_store(out, acc, row0, m0, n0, g, tig, nrows);

    if constexpr (POST2) {
        __syncthreads();                    // B/A reads done
        copyw_async(sb, tid, wra);
        acc_to_A(smem, acc, m0, n0, g, tig, nullptr, false);  // split h'
        CP_WAIT_ALL();
        __syncthreads();
        zacc(acc);
        gemm3<8>(sb, m0, n0, a_ro, a_co, b_ro, b_co, acc);
        acc_store(Ra, acc, row0, m0, n0, g, tig, nrows);
        __syncthreads();
        copyw_async(sb, tid, wrb);
        CP_WAIT_ALL();
        __syncthreads();
        zacc(acc);
        gemm3<8>(sb, m0, n0, a_ro, a_co, b_ro, b_co, acc);
        acc_store(Rb, acc, row0, m0, n0, g, tig, nrows);
    }
}

// ---------------------------------------------------------------------------
// Edge kernel.  64 edges/CTA, 256 thr.
//   layer1: acc = (NCH? e@W[w1c] : 0) + Pa[start] + Pb[end]
//   hidden = relu(acc+b1);  out = hidden@W2 + b2 (+res e)  | OUT1: dot w2vec
//   SCATTER: red.global.add of out rows into msgout[end]
// ---------------------------------------------------------------------------
template <int NCH, bool SCATTER, bool RES, bool OUT1>
__global__ void __launch_bounds__(256, 2)
edge_mlp(const float* __restrict__ s0,
         const int* __restrict__ ip0, const int* __restrict__ ip1,
         const float* __restrict__ Pa, const float* __restrict__ Pb,
         int w1c, int w2c,
         const float* __restrict__ b1, const float* __restrict__ b2,
         const float* __restrict__ w2vec,
         const float* __restrict__ res, float* __restrict__ out,
         float* __restrict__ msgout, int nrows) {
    extern __shared__ char smem[];
    const uint32_t sb = smem_u32(smem);
    const int tid = threadIdx.x, lane = tid & 31, wid = tid >> 5;
    const int row0 = blockIdx.x * 64;
    const int g = lane >> 2, tig = lane & 3;
    const int m0 = (wid >> 2) * 32, n0 = (wid & 3) * 32;
    const int a_ro = (lane & 7) + ((lane >> 3) & 1) * 8;
    const int a_co = ((lane >> 4) & 1) * 8;
    const int b_ro = (lane & 7) + ((lane >> 4) & 1) * 8;
    const int b_co = ((lane >> 3) & 1) * 8;

    float* b1s = (float*)(smem + SM_B1);
    float* b2s = (float*)(smem + SM_B2);
    float* w2s = (float*)(smem + SM_W2V);
    int*   s_ia = (int*)(smem + SM_IA);
    int*   s_ib = (int*)(smem + SM_IB);

    if (tid < 128) {
        b1s[tid] = b1[tid];
        if (OUT1) w2s[tid] = w2vec[tid];
        else      b2s[tid] = b2[tid];
    }
    // stash gather indices + L2-prefetch the Pa/Pb rows
    if (tid < 64) {
        int grow = row0 + tid;
        int ia = 0, ib = 0;
        if (grow < nrows) { ia = ip0[grow]; ib = ip1[grow]; }
        s_ia[tid] = ia; s_ib[tid] = ib;
        const char* pa = (const char*)(Pa + (size_t)ia * DD);
        const char* pb = (const char*)(Pb + (size_t)ib * DD);
        #pragma unroll
        for (int l = 0; l < 4; ++l) {
            asm volatile("prefetch.global.L2 [%0];" :: "l"(pa + l * 128));
            asm volatile("prefetch.global.L2 [%0];" :: "l"(pb + l * 128));
        }
    }

    float acc[2][4][4];
    zacc(acc);

    if constexpr (NCH == 1) {
        copyw_async(sb, tid, w1c);
        stage_a<128>(smem, wid, lane, row0, s0, nrows);
        CP_WAIT_ALL();
        __syncthreads();
        gemm3<8>(sb, m0, n0, a_ro, a_co, b_ro, b_co, acc);
    } else {
        __syncthreads();   // s_ia/s_ib + biases visible
    }

    // PRE: acc += Pa[start] + Pb[end]
    #pragma unroll
    for (int ma = 0; ma < 2; ++ma) {
        int rl = m0 + ma * 16 + g;
        #pragma unroll
        for (int half = 0; half < 2; ++half) {
            int rloc = rl + half * 8;
            int grow = row0 + rloc;
            if (grow < nrows) {
                const float* pa = Pa + (size_t)s_ia[rloc] * DD;
                const float* pb = Pb + (size_t)s_ib[rloc] * DD;
                #pragma unroll
                for (int na = 0; na < 4; ++na) {
                    int cc = n0 + na * 8 + 2 * tig;
                    float2 va = *(const float2*)(pa + cc);
                    float2 vb = *(const float2*)(pb + cc);
                    acc[ma][na][half * 2 + 0] += va.x + vb.x;
                    acc[ma][na][half * 2 + 1] += va.y + vb.y;
                }
            }
        }
    }

    if constexpr (OUT1) {
        float* hT = (float*)(smem + SM_AH);
        if (NCH == 1) __syncthreads();   // A/B reads done before overwrite
        #pragma unroll
        for (int ma = 0; ma < 2; ++ma) {
            int rl = m0 + ma * 16 + g;
            #pragma unroll
            for (int na = 0; na < 4; ++na) {
                int cc = n0 + na * 8 + 2 * tig;
                hT[rl * 129 + cc]           = fmaxf(acc[ma][na][0] + b1s[cc], 0.f);
                hT[rl * 129 + cc + 1]       = fmaxf(acc[ma][na][1] + b1s[cc + 1], 0.f);
                hT[(rl + 8) * 129 + cc]     = fmaxf(acc[ma][na][2] + b1s[cc], 0.f);
                hT[(rl + 8) * 129 + cc + 1] = fmaxf(acc[ma][na][3] + b1s[cc + 1], 0.f);
            }
        }
        __syncthreads();
        if (tid < 64) {
            int grow = row0 + tid;
            float a = __ldg(&b2[0]);
            #pragma unroll 8
            for (int k = 0; k < 128; ++k) a += hT[tid * 129 + k] * w2s[k];
            if (grow < nrows) out[grow] = a;
        }
        return;
    }

    // hidden = relu(acc + b1) -> A tiles; W2 copy overlaps the split
    __syncthreads();
    copyw_async(sb, tid, w2c);
    acc_to_A(smem, acc, m0, n0, g, tig, b1s, true);
    CP_WAIT_ALL();
    __syncthreads();

    zacc(acc);
    gemm3<8>(sb, m0, n0, a_ro, a_co, b_ro, b_co, acc);

    // epilogue: out = acc + b2 (+ res);  SCATTER: red-add into msgout[end]
    #pragma unroll
    for (int ma = 0; ma < 2; ++ma) {
        int rl = m0 + ma * 16 + g;
        #pragma unroll
        for (int half = 0; half < 2; ++half) {
            int rloc = rl + half * 8;
            int grow = row0 + rloc;
            if (grow < nrows) {
                float* mrow = SCATTER ? (msgout + (size_t)s_ib[rloc] * DD) : nullptr;
                #pragma unroll
                for (int na = 0; na < 4; ++na) {
                    int cc = n0 + na * 8 + 2 * tig;
                    float ox = acc[ma][na][half * 2 + 0] + b2s[cc];
                    float oy = acc[ma][na][half * 2 + 1] + b2s[cc + 1];
                    if (RES) {
                        float2 rv = *(const float2*)(res + (size_t)grow * DD + cc);
                        ox += rv.x; oy += rv.y;
                    }
                    *(float2*)(out + (size_t)grow * DD + cc) = make_float2(ox, oy);
                    if (SCATTER) {
                        atomicAdd(mrow + cc, ox);
                        atomicAdd(mrow + cc + 1, oy);
                    }
                }
            }
        }
    }
}

// ---------------------------------------------------------------------------
extern "C" void kernel_launch(void* const* d_in, const int* in_sizes, int n_in,
                              void* d_out, int out_size) {
    const float* nodes = (const float*)d_in[0];
    const void*  eidx  = d_in[1];
    const float* ne_W1 = (const float*)d_in[2];
    const float* ne_b1 = (const float*)d_in[3];
    const float* ne_W2 = (const float*)d_in[4];
    const float* ne_b2 = (const float*)d_in[5];
    const float* ee_W1 = (const float*)d_in[6];
    const float* ee_b1 = (const float*)d_in[7];
    const float* ee_W2 = (const float*)d_in[8];
    const float* ee_b2 = (const float*)d_in[9];
    const float* nn_W1 = (const float*)d_in[10];
    const float* nn_b1 = (const float*)d_in[11];
    const float* nn_W2 = (const float*)d_in[12];
    const float* nn_b2 = (const float*)d_in[13];
    const float* en_W1 = (const float*)d_in[14];
    const float* en_b1 = (const float*)d_in[15];
    const float* en_W2 = (const float*)d_in[16];
    const float* en_b2 = (const float*)d_in[17];
    const float* pe_W1 = (const float*)d_in[18];
    const float* pe_b1 = (const float*)d_in[19];
    const float* pe_W2 = (const float*)d_in[20];
    const float* pe_b2 = (const float*)d_in[21];

    float *h, *h2, *m0, *m1, *e, *pa, *pb, *pc, *pd;
    int *st, *en_;
    __nv_bfloat16 *pwh, *pwl;
    cudaGetSymbolAddress((void**)&h,   g_h);
    cudaGetSymbolAddress((void**)&h2,  g_h2);
    cudaGetSymbolAddress((void**)&m0,  g_m0);
    cudaGetSymbolAddress((void**)&m1,  g_m1);
    cudaGetSymbolAddress((void**)&e,   g_e);
    cudaGetSymbolAddress((void**)&pa,  g_pa);
    cudaGetSymbolAddress((void**)&pb,  g_pb);
    cudaGetSymbolAddress((void**)&pc,  g_pc);
    cudaGetSymbolAddress((void**)&pd,  g_pd);
    cudaGetSymbolAddress((void**)&st,  g_start);
    cudaGetSymbolAddress((void**)&en_, g_end);
    cudaGetSymbolAddress((void**)&pwh, g_pwh);
    cudaGetSymbolAddress((void**)&pwl, g_pwl);

    cudaFuncSetAttribute(node_fused<1, 1, false, true, false>,
                         cudaFuncAttributeMaxDynamicSharedMemorySize, SM_TOTAL);
    cudaFuncSetAttribute(node_fused<2, 8, true, false, true>,
                         cudaFuncAttributeMaxDynamicSharedMemorySize, SM_TOTAL);
    cudaFuncSetAttribute(node_fused<2, 8, true, true, true>,
                         cudaFuncAttributeMaxDynamicSharedMemorySize, SM_TOTAL);
    cudaFuncSetAttribute(edge_mlp<0, true, false, false>,
                         cudaFuncAttributeMaxDynamicSharedMemorySize, SM_TOTAL);
    cudaFuncSetAttribute(edge_mlp<1, true, true, false>,
                         cudaFuncAttributeMaxDynamicSharedMemorySize, SM_TOTAL);
    cudaFuncSetAttribute(edge_mlp<1, false, true, false>,
                         cudaFuncAttributeMaxDynamicSharedMemorySize, SM_TOTAL);
    cudaFuncSetAttribute(edge_mlp<1, false, false, true>,
                         cudaFuncAttributeMaxDynamicSharedMemorySize, SM_TOTAL);

    const int nblk_n = (N_NODES + 63) / 64;  // 1563
    const int nblk_e = (N_EDGES + 63) / 64;  // 9375
    const int zero_n4 = N_NODES * DD / 4;
    const int zero_blks = (zero_n4 + 255) / 256;

    convert_idx_kernel<<<(2 * N_EDGES + 255) / 256, 256>>>(eidx, st, en_, N_EDGES);
    pack_w_kernel<<<(15 * 16384 + 255) / 256, 256>>>(
        ne_W1, ne_W2, ee_W1, ee_W2, nn_W1, nn_W2, en_W1, en_W2, pe_W1, pwh, pwl);

    // h = MLP_ne(nodes);  Pa = h@eeW1a, Pb = h@eeW1b
    node_fused<1, 1, false, true, false><<<nblk_n, 256, SM_TOTAL>>>(
        nodes, nullptr, 0, 0, nullptr, nullptr, 0, 1,
        2, 3, pa, pb, ne_b1, ne_b2, nullptr, h, N_NODES);

    // e = relu(Pa[s]+Pb[e]+b1)@eeW2 + b2;  scatter e -> m0
    zero_kernel<<<zero_blks, 256>>>((float4*)m0, zero_n4);
    edge_mlp<0, true, false, false><<<nblk_e, 256, SM_TOTAL>>>(
        nullptr, st, en_, pa, pb, 0, 4,
        ee_b1, ee_b2, nullptr, nullptr, e, m0, N_EDGES);

    float* hA = h;
    float* hB = h2;
    float* msgs[2] = {m0, m1};

    for (int it = 0; it < NUM_ITERS; ++it) {
        float* mcur = msgs[it & 1];
        float* mnxt = msgs[(it + 1) & 1];
        const bool last = (it == NUM_ITERS - 1);

        // h' = MLP_nn(hA || mcur) + hA;  Qa,Qb = hA@enW1a/b
        // (last iter also: Ra,Rb = h'@peW1a/b)
        if (!last) {
            node_fused<2, 8, true, false, true><<<nblk_n, 256, SM_TOTAL>>>(
                hA, mcur, 8, 9, pa, pb, 5, 7,
                0, 0, nullptr, nullptr, nn_b1, nn_b2, hA, hB, N_NODES);
        } else {
            node_fused<2, 8, true, true, true><<<nblk_n, 256, SM_TOTAL>>>(
                hA, mcur, 8, 9, pa, pb, 5, 7,
                12, 13, pc, pd, nn_b1, nn_b2, hA, hB, N_NODES);
        }

        // e = (relu(e@enW1c + Qa[s]+Qb[e]+b1)@enW2 + b2) + e; scatter -> mnxt
        if (!last) {
            zero_kernel<<<zero_blks, 256>>>((float4*)mnxt, zero_n4);
            edge_mlp<1, true, true, false><<<nblk_e, 256, SM_TOTAL>>>(
                e, st, en_, pa, pb, 10, 11,
                en_b1, en_b2, nullptr, e, e, mnxt, N_EDGES);
        } else {
            edge_mlp<1, false, true, false><<<nblk_e, 256, SM_TOTAL>>>(
                e, st, en_, pa, pb, 10, 11,
                en_b1, en_b2, nullptr, e, e, nullptr, N_EDGES);
        }

        float* t = hA; hA = hB; hB = t;
    }

    // pred = relu(e@peW1c + Ra[s]+Rb[e]+b1) . peW2 + b2
    edge_mlp<1, false, false, true><<<nblk_e, 256, SM_TOTAL>>>(
        e, st, en_, pc, pd, 14, 0,
        pe_b1, pe_b2, pe_W2, nullptr, (float*)d_out, nullptr, N_EDGES);
}

// round 7
// speedup vs baseline: 6.8313x; 1.0805x over previous
#include <cuda_runtime.h>
#include <cuda_bf16.h>
#include <cstdint>

// ---------------------------------------------------------------------------
// InteractionGNN on GB300 — round 7: round-6 design (3 CTAs/SM via half-N
// weight tiles) with the copyw_half indexing bug fixed (rr=i>>4, q=i&15).
// 64 rows/CTA, 256 thr, warp tile 16x32, B smem holds 64 N-rows at a time.
// GEMM core: mma.sync bf16 3-term split (Ah*Wh + Ah*Wl + Al*Wh), fp32 accum.
// ---------------------------------------------------------------------------

#define N_NODES 100000
#define N_EDGES 600000
#define DD      128
#define NUM_ITERS 4

// ---------------- device scratch -------------------------------------------
__device__ float g_h  [(size_t)N_NODES * DD];
__device__ float g_h2 [(size_t)N_NODES * DD];
__device__ float g_m0 [(size_t)N_NODES * DD];
__device__ float g_m1 [(size_t)N_NODES * DD];
__device__ float g_e  [(size_t)N_EDGES * DD];
__device__ float g_pa [(size_t)N_NODES * DD];
__device__ float g_pb [(size_t)N_NODES * DD];
__device__ float g_pc [(size_t)N_NODES * DD];
__device__ float g_pd [(size_t)N_NODES * DD];
__device__ int   g_start[N_EDGES];
__device__ int   g_end  [N_EDGES];
// prepacked weights: 15 chunks x [128 n][128 k] bf16, hi and lo images
__device__ __nv_bfloat16 g_pwh[15 * 16384];
__device__ __nv_bfloat16 g_pwl[15 * 16384];

// ---------------- smem layout ------------------------------------------------
static constexpr int ROW_B  = 272;
static constexpr int SM_B1  = 64;     // 128 f32
static constexpr int SM_W2V = 576;    // 128 f32
static constexpr int SM_B2  = 1088;   // 128 f32
static constexpr int SM_IA  = 1600;   // 64 ints
static constexpr int SM_IB  = 1856;   // 64 ints
static constexpr int SM_AH  = 2176;
static constexpr int TBUF   = 64 * ROW_B;          // 17408
static constexpr int SM_AL  = SM_AH + TBUF;        // 19584
static constexpr int SM_BH  = SM_AL + TBUF;        // 36992  (64 N-rows half)
static constexpr int SM_BL  = SM_BH + TBUF;        // 54400
static constexpr int SM_TOTAL = SM_BL + TBUF;      // 71808

// ---------------- helpers -----------------------------------------------------
__device__ __forceinline__ uint32_t smem_u32(const void* p) {
    uint32_t a;
    asm("{ .reg .u64 t; cvta.to.shared.u64 t, %1; cvt.u32.u64 %0, t; }"
        : "=r"(a) : "l"(p));
    return a;
}

#define LDSM_X4(R0, R1, R2, R3, ADDR) \
    asm volatile("ldmatrix.sync.aligned.m8n8.x4.shared.b16 {%0,%1,%2,%3}, [%4];" \
                 : "=r"(R0), "=r"(R1), "=r"(R2), "=r"(R3) : "r"(ADDR))

__device__ __forceinline__ void mma16816(float* c, const uint32_t* a,
                                         const uint32_t* b) {
    asm volatile(
        "mma.sync.aligned.m16n8k16.row.col.f32.bf16.bf16.f32 "
        "{%0,%1,%2,%3}, {%4,%5,%6,%7}, {%8,%9}, {%0,%1,%2,%3};"
        : "+f"(c[0]), "+f"(c[1]), "+f"(c[2]), "+f"(c[3])
        : "r"(a[0]), "r"(a[1]), "r"(a[2]), "r"(a[3]), "r"(b[0]), "r"(b[1]));
}

__device__ __forceinline__ uint32_t pack_bf2(float a, float b) {
    __nv_bfloat162 t = __floats2bfloat162_rn(a, b);
    return *reinterpret_cast<uint32_t*>(&t);
}

__device__ __forceinline__ void split2(float x, float y, uint32_t& H, uint32_t& L) {
    __nv_bfloat16 hx = __float2bfloat16(x);
    __nv_bfloat16 hy = __float2bfloat16(y);
    float lx = x - __bfloat162float(hx);
    float ly = y - __bfloat162float(hy);
    H = pack_bf2(__bfloat162float(hx), __bfloat162float(hy));
    L = pack_bf2(lx, ly);
}

#define CP_WAIT_ALL() asm volatile("cp.async.wait_group 0;" ::: "memory")

// async copy of one 64-N-row half of a weight chunk into B hi/lo tiles.
// half tile = 64 rows x 256 B/row = 1024 int4; 16 int4 per 256B source row.
__device__ __forceinline__ void copyw_half(uint32_t sb, int tid, int chunk,
                                           int half) {
    const char* srcH = (const char*)(g_pwh + (size_t)chunk * 16384 + half * 8192);
    const char* srcL = (const char*)(g_pwl + (size_t)chunk * 16384 + half * 8192);
    #pragma unroll
    for (int i = tid; i < 1024; i += 256) {
        int rr = i >> 4, q = i & 15;                       // FIXED (was >>3, &7)
        uint32_t d = sb + SM_BH + rr * ROW_B + q * 16;
        asm volatile("cp.async.cg.shared.global [%0], [%1], 16;"
                     :: "r"(d), "l"(srcH + i * 16));
        asm volatile("cp.async.cg.shared.global [%0], [%1], 16;"
                     :: "r"(d + (uint32_t)TBUF), "l"(srcL + i * 16));
    }
    asm volatile("cp.async.commit_group;" ::: "memory");
}

// 3-term split GEMM over one B half; warp tile 16(M) x 32(N-local)
template <int KSTEPS>
__device__ __forceinline__ void gemm3h(uint32_t sb, int m0, int nloc,
                                       int a_ro, int a_co, int b_ro, int b_co,
                                       float accp[4][4]) {
    #pragma unroll
    for (int ks = 0; ks < KSTEPS; ++ks) {
        const int k0 = ks * 16;
        uint32_t ah[4], al[4];
        {
            uint32_t ro = (uint32_t)(m0 + a_ro) * ROW_B + (uint32_t)(k0 + a_co) * 2;
            LDSM_X4(ah[0], ah[1], ah[2], ah[3], sb + SM_AH + ro);
            LDSM_X4(al[0], al[1], al[2], al[3], sb + SM_AL + ro);
        }
        uint32_t bh[4][2], bl[4][2];
        #pragma unroll
        for (int nb = 0; nb < 2; ++nb) {
            uint32_t ro = (uint32_t)(nloc + nb * 16 + b_ro) * ROW_B +
                          (uint32_t)(k0 + b_co) * 2;
            uint32_t r0, r1, r2, r3;
            LDSM_X4(r0, r1, r2, r3, sb + SM_BH + ro);
            bh[nb * 2][0] = r0; bh[nb * 2][1] = r1;
            bh[nb * 2 + 1][0] = r2; bh[nb * 2 + 1][1] = r3;
            LDSM_X4(r0, r1, r2, r3, sb + SM_BL + ro);
            bl[nb * 2][0] = r0; bl[nb * 2][1] = r1;
            bl[nb * 2 + 1][0] = r2; bl[nb * 2 + 1][1] = r3;
        }
        #pragma unroll
        for (int na = 0; na < 4; ++na) {
            mma16816(accp[na], ah, bh[na]);
            mma16816(accp[na], ah, bl[na]);
            mma16816(accp[na], al, bh[na]);
        }
    }
}

// one full layer GEMM = two N-half passes (acc[p] accumulates half p)
template <int KS>
__device__ __forceinline__ void layer_gemm(uint32_t sb, int tid, int chunk,
                                           int m0, int nloc,
                                           int a_ro, int a_co, int b_ro, int b_co,
                                           float acc[2][4][4]) {
    #pragma unroll
    for (int p = 0; p < 2; ++p) {
        __syncthreads();                 // prior B reads / smem writes ordered
        copyw_half(sb, tid, chunk, p);
        CP_WAIT_ALL();
        __syncthreads();
        gemm3h<KS>(sb, m0, nloc, a_ro, a_co, b_ro, b_co, acc[p]);
    }
}

__device__ __forceinline__ void zacc2(float acc[2][4][4]) {
    #pragma unroll
    for (int q = 0; q < 32; ++q) (&acc[0][0][0])[q] = 0.f;
}

// stage 64 rows x SRC_K fp32 into A hi/lo smem tiles (contiguous rows)
template <int SRC_K>
__device__ __forceinline__ void stage_a(char* smem, int wid, int lane, int row0,
                                        const float* __restrict__ src, int nrows) {
    for (int r = wid; r < 64; r += 8) {
        int grow = row0 + r;
        float4 v = make_float4(0.f, 0.f, 0.f, 0.f);
        if (grow < nrows && lane < SRC_K / 4)
            v = ((const float4*)(src + (size_t)grow * SRC_K))[lane];
        if (lane < SRC_K / 4) {
            uint32_t h0, l0, h1, l1;
            split2(v.x, v.y, h0, l0);
            split2(v.z, v.w, h1, l1);
            uint32_t off = r * ROW_B + lane * 8;
            *(uint2*)(smem + SM_AH + off) = make_uint2(h0, h1);
            *(uint2*)(smem + SM_AL + off) = make_uint2(l0, l1);
        }
    }
}

// split acc (optional bias+relu) into A hi/lo tiles (cols = both N halves)
__device__ __forceinline__ void acc_to_A(char* smem, float acc[2][4][4],
                                         int m0, int nwn, int g, int tig,
                                         const float* b1s, bool relu) {
    const int rl = m0 + g;
    #pragma unroll
    for (int p = 0; p < 2; ++p)
        #pragma unroll
        for (int na = 0; na < 4; ++na) {
            int cc = p * 64 + nwn + na * 8 + 2 * tig;
            float bx = b1s ? b1s[cc] : 0.f;
            float by = b1s ? b1s[cc + 1] : 0.f;
            float v0 = acc[p][na][0] + bx, v1 = acc[p][na][1] + by;
            float v2 = acc[p][na][2] + bx, v3 = acc[p][na][3] + by;
            if (relu) {
                v0 = fmaxf(v0, 0.f); v1 = fmaxf(v1, 0.f);
                v2 = fmaxf(v2, 0.f); v3 = fmaxf(v3, 0.f);
            }
            uint32_t H, L;
            split2(v0, v1, H, L);
            *(uint32_t*)(smem + SM_AH + rl * ROW_B + cc * 2) = H;
            *(uint32_t*)(smem + SM_AL + rl * ROW_B + cc * 2) = L;
            split2(v2, v3, H, L);
            *(uint32_t*)(smem + SM_AH + (rl + 8) * ROW_B + cc * 2) = H;
            *(uint32_t*)(smem + SM_AL + (rl + 8) * ROW_B + cc * 2) = L;
        }
}

// raw store of acc to out[row][col]
__device__ __forceinline__ void acc_store(float* __restrict__ out,
                                          float acc[2][4][4], int row0,
                                          int m0, int nwn, int g, int tig,
                                          int nrows) {
    const int rl = m0 + g;
    const int g0 = row0 + rl, g1 = g0 + 8;
    #pragma unroll
    for (int p = 0; p < 2; ++p)
        #pragma unroll
        for (int na = 0; na < 4; ++na) {
            int cc = p * 64 + nwn + na * 8 + 2 * tig;
            if (g0 < nrows)
                *(float2*)(out + (size_t)g0 * DD + cc) =
                    make_float2(acc[p][na][0], acc[p][na][1]);
            if (g1 < nrows)
                *(float2*)(out + (size_t)g1 * DD + cc) =
                    make_float2(acc[p][na][2], acc[p][na][3]);
        }
}

// ---------------- small utility kernels ------------------------------------
__global__ void convert_idx_kernel(const void* __restrict__ raw,
                                   int* __restrict__ st, int* __restrict__ en,
                                   int E) {
    __shared__ int s_is64;
    if (threadIdx.x == 0) {
        const unsigned int* w = (const unsigned int*)raw;
        unsigned int acc = 0;
        #pragma unroll 8
        for (int i = 0; i < 128; ++i) acc |= w[2 * i + 1];
        s_is64 = (acc == 0u);
    }
    __syncthreads();
    const int is64 = s_is64;
    int i = blockIdx.x * blockDim.x + threadIdx.x;
    if (i >= 2 * E) return;
    int v;
    if (is64) v = (int)((const long long*)raw)[i];
    else      v = ((const int*)raw)[i];
    if (i < E) st[i] = v; else en[i - E] = v;
}

__global__ void zero_kernel(float4* __restrict__ p, int n4) {
    int i = blockIdx.x * blockDim.x + threadIdx.x;
    if (i < n4) p[i] = make_float4(0.f, 0.f, 0.f, 0.f);
}

// Pack weights transposed: image[chunk][n][k] = W[(koff+k)*128 + n], bf16 hi/lo.
// 0:ne_W1(k<16) 1:ne_W2  2-3:ee_W1(a,b) 4:ee_W2  5-6:nn_W1 7:nn_W2
// 8-10:en_W1(a,b,c) 11:en_W2  12-14:pe_W1(a,b,c)
__global__ void pack_w_kernel(const float* neW1, const float* neW2,
                              const float* eeW1, const float* eeW2,
                              const float* nnW1, const float* nnW2,
                              const float* enW1, const float* enW2,
                              const float* peW1,
                              __nv_bfloat16* gh, __nv_bfloat16* gl) {
    int t = blockIdx.x * blockDim.x + threadIdx.x;
    if (t >= 15 * 16384) return;
    int chunk = t >> 14;
    int e = t & 16383;
    int k = e & 127;
    int n = e >> 7;
    const float* W; int koff = 0; int kvalid = 128;
    switch (chunk) {
        case 0:  W = neW1; kvalid = 16; break;
        case 1:  W = neW2; break;
        case 2: case 3:  W = eeW1; koff = (chunk - 2) * 128; break;
        case 4:  W = eeW2; break;
        case 5: case 6:  W = nnW1; koff = (chunk - 5) * 128; break;
        case 7:  W = nnW2; break;
        case 8: case 9: case 10: W = enW1; koff = (chunk - 8) * 128; break;
        case 11: W = enW2; break;
        default: W = peW1; koff = (chunk - 12) * 128; break;
    }
    float x = (k < kvalid) ? W[(size_t)(koff + k) * 128 + n] : 0.f;
    __nv_bfloat16 h = __float2bfloat16(x);
    __nv_bfloat16 l = __float2bfloat16(x - __bfloat162float(h));
    gh[(size_t)chunk * 16384 + n * 128 + k] = h;
    gl[(size_t)chunk * 16384 + n * 128 + k] = l;
}

// ---------------------------------------------------------------------------
// Fused node kernel.  64 rows/CTA, 256 thr, warp tile 16x32.
// ---------------------------------------------------------------------------
template <int NCH, int KS1, bool PRE2, bool POST2, bool RES>
__global__ void __launch_bounds__(256, 3)
node_fused(const float* __restrict__ s0, const float* __restrict__ s1,
           int wqa, int wqb, float* __restrict__ Qa, float* __restrict__ Qb,
           int w1c0, int w2c,
           int wra, int wrb, float* __restrict__ Ra, float* __restrict__ Rb,
           const float* __restrict__ b1, const float* __restrict__ b2,
           const float* __restrict__ res, float* __restrict__ out, int nrows) {
    extern __shared__ char smem[];
    const uint32_t sb = smem_u32(smem);
    const int tid = threadIdx.x, lane = tid & 31, wid = tid >> 5;
    const int row0 = blockIdx.x * 64;
    const int g = lane >> 2, tig = lane & 3;
    const int m0 = (wid >> 1) * 16;
    const int nwn = (wid & 1) * 32;
    const int a_ro = (lane & 7) + ((lane >> 3) & 1) * 8;
    const int a_co = ((lane >> 4) & 1) * 8;
    const int b_ro = (lane & 7) + ((lane >> 4) & 1) * 8;
    const int b_co = ((lane >> 3) & 1) * 8;

    float* b1s = (float*)(smem + SM_B1);
    float* b2s = (float*)(smem + SM_B2);
    if (tid < 128) { b1s[tid] = b1[tid]; b2s[tid] = b2[tid]; }

    stage_a<KS1 * 16>(smem, wid, lane, row0, s0, nrows);

    float acc[2][4][4];

    if constexpr (PRE2) {
        zacc2(acc);
        layer_gemm<KS1>(sb, tid, wqa, m0, nwn, a_ro, a_co, b_ro, b_co, acc);
        acc_store(Qa, acc, row0, m0, nwn, g, tig, nrows);
        zacc2(acc);
        layer_gemm<KS1>(sb, tid, wqb, m0, nwn, a_ro, a_co, b_ro, b_co, acc);
        acc_store(Qb, acc, row0, m0, nwn, g, tig, nrows);
    }

    zacc2(acc);
    layer_gemm<KS1>(sb, tid, w1c0, m0, nwn, a_ro, a_co, b_ro, b_co, acc);

    if constexpr (NCH == 2) {
        __syncthreads();   // A reads done before restage
        stage_a<128>(smem, wid, lane, row0, s1, nrows);
        layer_gemm<8>(sb, tid, w1c0 + 1, m0, nwn, a_ro, a_co, b_ro, b_co, acc);
    }
    __syncthreads();       // all A/B reads done

    // hidden = relu(acc + b1) -> A tiles
    acc_to_A(smem, acc, m0, nwn, g, tig, b1s, true);

    // layer 2
    zacc2(acc);
    layer_gemm<8>(sb, tid, w2c, m0, nwn, a_ro, a_co, b_ro, b_co, acc);

    // fold b2 (+res) and store h'
    {
        const int rl = m0 + g;
        #pragma unroll
        for (int half = 0; half < 2; ++half) {
            int grow = row0 + rl + half * 8;
            #pragma unroll
            for (int p = 0; p < 2; ++p)
                #pragma unroll
                for (int na = 0; na < 4; ++na) {
                    int cc = p * 64 + nwn + na * 8 + 2 * tig;
                    float bx = b2s[cc], by = b2s[cc + 1];
                    float rx = 0.f, ry = 0.f;
                    if (RES && grow < nrows) {
                        float2 rv = *(const float2*)(res + (size_t)grow * DD + cc);
                        rx = rv.x; ry = rv.y;
                    }
                    acc[p][na][half * 2 + 0] += bx + rx;
                    acc[p][na][half * 2 + 1] += by + ry;
                }
        }
    }
    acc_store(out, acc, row0, m0, nwn, g, tig, nrows);

    if constexpr (POST2) {
        __syncthreads();                          // hidden-A reads done
        acc_to_A(smem, acc, m0, nwn, g, tig, nullptr, false);  // split h'
        zacc2(acc);
        layer_gemm<8>(sb, tid, wra, m0, nwn, a_ro, a_co, b_ro, b_co, acc);
        acc_store(Ra, acc, row0, m0, nwn, g, tig, nrows);
        zacc2(acc);
        layer_gemm<8>(sb, tid, wrb, m0, nwn, a_ro, a_co, b_ro, b_co, acc);
        acc_store(Rb, acc, row0, m0, nwn, g, tig, nrows);
    }
}

// ---------------------------------------------------------------------------
// Edge kernel.  64 edges/CTA, 256 thr, warp tile 16x32.
// ---------------------------------------------------------------------------
template <int NCH, bool SCATTER, bool RES, bool OUT1>
__global__ void __launch_bounds__(256, 3)
edge_mlp(const float* __restrict__ s0,
         const int* __restrict__ ip0, const int* __restrict__ ip1,
         const float* __restrict__ Pa, const float* __restrict__ Pb,
         int w1c, int w2c,
         const float* __restrict__ b1, const float* __restrict__ b2,
         const float* __restrict__ w2vec,
         const float* __restrict__ res, float* __restrict__ out,
         float* __restrict__ msgout, int nrows) {
    extern __shared__ char smem[];
    const uint32_t sb = smem_u32(smem);
    const int tid = threadIdx.x, lane = tid & 31, wid = tid >> 5;
    const int row0 = blockIdx.x * 64;
    const int g = lane >> 2, tig = lane & 3;
    const int m0 = (wid >> 1) * 16;
    const int nwn = (wid & 1) * 32;
    const int a_ro = (lane & 7) + ((lane >> 3) & 1) * 8;
    const int a_co = ((lane >> 4) & 1) * 8;
    const int b_ro = (lane & 7) + ((lane >> 4) & 1) * 8;
    const int b_co = ((lane >> 3) & 1) * 8;

    float* b1s = (float*)(smem + SM_B1);
    float* b2s = (float*)(smem + SM_B2);
    float* w2s = (float*)(smem + SM_W2V);
    int*   s_ia = (int*)(smem + SM_IA);
    int*   s_ib = (int*)(smem + SM_IB);

    if (tid < 128) {
        b1s[tid] = b1[tid];
        if (OUT1) w2s[tid] = w2vec[tid];
        else      b2s[tid] = b2[tid];
    }
    if (tid < 64) {
        int grow = row0 + tid;
        int ia = 0, ib = 0;
        if (grow < nrows) { ia = ip0[grow]; ib = ip1[grow]; }
        s_ia[tid] = ia; s_ib[tid] = ib;
        const char* pa = (const char*)(Pa + (size_t)ia * DD);
        const char* pb = (const char*)(Pb + (size_t)ib * DD);
        #pragma unroll
        for (int l = 0; l < 4; ++l) {
            asm volatile("prefetch.global.L2 [%0];" :: "l"(pa + l * 128));
            asm volatile("prefetch.global.L2 [%0];" :: "l"(pb + l * 128));
        }
    }

    float acc[2][4][4];
    zacc2(acc);

    if constexpr (NCH == 1) {
        stage_a<128>(smem, wid, lane, row0, s0, nrows);
        layer_gemm<8>(sb, tid, w1c, m0, nwn, a_ro, a_co, b_ro, b_co, acc);
    } else {
        __syncthreads();   // s_ia/s_ib + biases visible
    }

    // PRE: acc += Pa[start] + Pb[end]
    {
        const int rl = m0 + g;
        #pragma unroll
        for (int half = 0; half < 2; ++half) {
            int rloc = rl + half * 8;
            int grow = row0 + rloc;
            if (grow < nrows) {
                const float* pa = Pa + (size_t)s_ia[rloc] * DD;
                const float* pb = Pb + (size_t)s_ib[rloc] * DD;
                #pragma unroll
                for (int p = 0; p < 2; ++p)
                    #pragma unroll
                    for (int na = 0; na < 4; ++na) {
                        int cc = p * 64 + nwn + na * 8 + 2 * tig;
                        float2 va = *(const float2*)(pa + cc);
                        float2 vb = *(const float2*)(pb + cc);
                        acc[p][na][half * 2 + 0] += va.x + vb.x;
                        acc[p][na][half * 2 + 1] += va.y + vb.y;
                    }
            }
        }
    }

    if constexpr (OUT1) {
        // hidden fp32 -> hT[64][129] over A tiles, then per-row dot
        float* hT = (float*)(smem + SM_AH);
        __syncthreads();      // A/B reads done before overwrite
        const int rl = m0 + g;
        #pragma unroll
        for (int p = 0; p < 2; ++p)
            #pragma unroll
            for (int na = 0; na < 4; ++na) {
                int cc = p * 64 + nwn + na * 8 + 2 * tig;
                hT[rl * 129 + cc]           = fmaxf(acc[p][na][0] + b1s[cc], 0.f);
                hT[rl * 129 + cc + 1]       = fmaxf(acc[p][na][1] + b1s[cc + 1], 0.f);
                hT[(rl + 8) * 129 + cc]     = fmaxf(acc[p][na][2] + b1s[cc], 0.f);
                hT[(rl + 8) * 129 + cc + 1] = fmaxf(acc[p][na][3] + b1s[cc + 1], 0.f);
            }
        __syncthreads();
        if (tid < 64) {
            int grow = row0 + tid;
            float a = __ldg(&b2[0]);
            #pragma unroll 8
            for (int k = 0; k < 128; ++k) a += hT[tid * 129 + k] * w2s[k];
            if (grow < nrows) out[grow] = a;
        }
        return;
    }

    // hidden = relu(acc + b1) -> A tiles
    __syncthreads();          // A/B reads done
    acc_to_A(smem, acc, m0, nwn, g, tig, b1s, true);

    // layer 2
    zacc2(acc);
    layer_gemm<8>(sb, tid, w2c, m0, nwn, a_ro, a_co, b_ro, b_co, acc);

    // epilogue: out = acc + b2 (+ res);  SCATTER: atomics into msgout[end]
    {
        const int rl = m0 + g;
        #pragma unroll
        for (int half = 0; half < 2; ++half) {
            int rloc = rl + half * 8;
            int grow = row0 + rloc;
            if (grow < nrows) {
                float* mrow = SCATTER ? (msgout + (size_t)s_ib[rloc] * DD) : nullptr;
                #pragma unroll
                for (int p = 0; p < 2; ++p)
                    #pragma unroll
                    for (int na = 0; na < 4; ++na) {
                        int cc = p * 64 + nwn + na * 8 + 2 * tig;
                        float ox = acc[p][na][half * 2 + 0] + b2s[cc];
                        float oy = acc[p][na][half * 2 + 1] + b2s[cc + 1];
                        if (RES) {
                            float2 rv = *(const float2*)(res + (size_t)grow * DD + cc);
                            ox += rv.x; oy += rv.y;
                        }
                        *(float2*)(out + (size_t)grow * DD + cc) = make_float2(ox, oy);
                        if (SCATTER) {
                            atomicAdd(mrow + cc, ox);
                            atomicAdd(mrow + cc + 1, oy);
                        }
                    }
            }
        }
    }
}

// ---------------------------------------------------------------------------
extern "C" void kernel_launch(void* const* d_in, const int* in_sizes, int n_in,
                              void* d_out, int out_size) {
    const float* nodes = (const float*)d_in[0];
    const void*  eidx  = d_in[1];
    const float* ne_W1 = (const float*)d_in[2];
    const float* ne_b1 = (const float*)d_in[3];
    const float* ne_W2 = (const float*)d_in[4];
    const float* ne_b2 = (const float*)d_in[5];
    const float* ee_W1 = (const float*)d_in[6];
    const float* ee_b1 = (const float*)d_in[7];
    const float* ee_W2 = (const float*)d_in[8];
    const float* ee_b2 = (const float*)d_in[9];
    const float* nn_W1 = (const float*)d_in[10];
    const float* nn_b1 = (const float*)d_in[11];
    const float* nn_W2 = (const float*)d_in[12];
    const float* nn_b2 = (const float*)d_in[13];
    const float* en_W1 = (const float*)d_in[14];
    const float* en_b1 = (const float*)d_in[15];
    const float* en_W2 = (const float*)d_in[16];
    const float* en_b2 = (const float*)d_in[17];
    const float* pe_W1 = (const float*)d_in[18];
    const float* pe_b1 = (const float*)d_in[19];
    const float* pe_W2 = (const float*)d_in[20];
    const float* pe_b2 = (const float*)d_in[21];

    float *h, *h2, *m0, *m1, *e, *pa, *pb, *pc, *pd;
    int *st, *en_;
    __nv_bfloat16 *pwh, *pwl;
    cudaGetSymbolAddress((void**)&h,   g_h);
    cudaGetSymbolAddress((void**)&h2,  g_h2);
    cudaGetSymbolAddress((void**)&m0,  g_m0);
    cudaGetSymbolAddress((void**)&m1,  g_m1);
    cudaGetSymbolAddress((void**)&e,   g_e);
    cudaGetSymbolAddress((void**)&pa,  g_pa);
    cudaGetSymbolAddress((void**)&pb,  g_pb);
    cudaGetSymbolAddress((void**)&pc,  g_pc);
    cudaGetSymbolAddress((void**)&pd,  g_pd);
    cudaGetSymbolAddress((void**)&st,  g_start);
    cudaGetSymbolAddress((void**)&en_, g_end);
    cudaGetSymbolAddress((void**)&pwh, g_pwh);
    cudaGetSymbolAddress((void**)&pwl, g_pwl);

    cudaFuncSetAttribute(node_fused<1, 1, false, true, false>,
                         cudaFuncAttributeMaxDynamicSharedMemorySize, SM_TOTAL);
    cudaFuncSetAttribute(node_fused<2, 8, true, false, true>,
                         cudaFuncAttributeMaxDynamicSharedMemorySize, SM_TOTAL);
    cudaFuncSetAttribute(node_fused<2, 8, true, true, true>,
                         cudaFuncAttributeMaxDynamicSharedMemorySize, SM_TOTAL);
    cudaFuncSetAttribute(edge_mlp<0, true, false, false>,
                         cudaFuncAttributeMaxDynamicSharedMemorySize, SM_TOTAL);
    cudaFuncSetAttribute(edge_mlp<1, true, true, false>,
                         cudaFuncAttributeMaxDynamicSharedMemorySize, SM_TOTAL);
    cudaFuncSetAttribute(edge_mlp<1, false, true, false>,
                         cudaFuncAttributeMaxDynamicSharedMemorySize, SM_TOTAL);
    cudaFuncSetAttribute(edge_mlp<1, false, false, true>,
                         cudaFuncAttributeMaxDynamicSharedMemorySize, SM_TOTAL);

    const int nblk_n = (N_NODES + 63) / 64;  // 1563
    const int nblk_e = (N_EDGES + 63) / 64;  // 9375
    const int zero_n4 = N_NODES * DD / 4;
    const int zero_blks = (zero_n4 + 255) / 256;

    convert_idx_kernel<<<(2 * N_EDGES + 255) / 256, 256>>>(eidx, st, en_, N_EDGES);
    pack_w_kernel<<<(15 * 16384 + 255) / 256, 256>>>(
        ne_W1, ne_W2, ee_W1, ee_W2, nn_W1, nn_W2, en_W1, en_W2, pe_W1, pwh, pwl);

    // h = MLP_ne(nodes);  Pa = h@eeW1a, Pb = h@eeW1b
    node_fused<1, 1, false, true, false><<<nblk_n, 256, SM_TOTAL>>>(
        nodes, nullptr, 0, 0, nullptr, nullptr, 0, 1,
        2, 3, pa, pb, ne_b1, ne_b2, nullptr, h, N_NODES);

    // e = relu(Pa[s]+Pb[e]+b1)@eeW2 + b2;  scatter e -> m0
    zero_kernel<<<zero_blks, 256>>>((float4*)m0, zero_n4);
    edge_mlp<0, true, false, false><<<nblk_e, 256, SM_TOTAL>>>(
        nullptr, st, en_, pa, pb, 0, 4,
        ee_b1, ee_b2, nullptr, nullptr, e, m0, N_EDGES);

    float* hA = h;
    float* hB = h2;
    float* msgs[2] = {m0, m1};

    for (int it = 0; it < NUM_ITERS; ++it) {
        float* mcur = msgs[it & 1];
        float* mnxt = msgs[(it + 1) & 1];
        const bool last = (it == NUM_ITERS - 1);

        if (!last) {
            node_fused<2, 8, true, false, true><<<nblk_n, 256, SM_TOTAL>>>(
                hA, mcur, 8, 9, pa, pb, 5, 7,
                0, 0, nullptr, nullptr, nn_b1, nn_b2, hA, hB, N_NODES);
        } else {
            node_fused<2, 8, true, true, true><<<nblk_n, 256, SM_TOTAL>>>(
                hA, mcur, 8, 9, pa, pb, 5, 7,
                12, 13, pc, pd, nn_b1, nn_b2, hA, hB, N_NODES);
        }

        if (!last) {
            zero_kernel<<<zero_blks, 256>>>((float4*)mnxt, zero_n4);
            edge_mlp<1, true, true, false><<<nblk_e, 256, SM_TOTAL>>>(
                e, st, en_, pa, pb, 10, 11,
                en_b1, en_b2, nullptr, e, e, mnxt, N_EDGES);
        } else {
            edge_mlp<1, false, true, false><<<nblk_e, 256, SM_TOTAL>>>(
                e, st, en_, pa, pb, 10, 11,
                en_b1, en_b2, nullptr, e, e, nullptr, N_EDGES);
        }

        float* t = hA; hA = hB; hB = t;
    }

    // pred = relu(e@peW1c + Ra[s]+Rb[e]+b1) . peW2 + b2
    edge_mlp<1, false, false, true><<<nblk_e, 256, SM_TOTAL>>>(
        e, st, en_, pc, pd, 14, 0,
        pe_b1, pe_b2, pe_W2, nullptr, (float*)d_out, nullptr, N_EDGES);
}

// round 8
// speedup vs baseline: 6.9206x; 1.0131x over previous
#include <cuda_runtime.h>
#include <cuda_bf16.h>
#include <cstdint>

// ---------------------------------------------------------------------------
// InteractionGNN on GB300 — round 8: R7 + scatter via cp.reduce.async.bulk
// (TMA-path bulk f32 add) instead of per-element global atomics.
// 64 rows/CTA, 256 thr, warp tile 16x32, half-N weight tiles, 3 CTAs/SM.
// GEMM core: mma.sync bf16 3-term split (Ah*Wh + Ah*Wl + Al*Wh), fp32 accum.
// ---------------------------------------------------------------------------

#define N_NODES 100000
#define N_EDGES 600000
#define DD      128
#define NUM_ITERS 4

// ---------------- device scratch -------------------------------------------
__device__ float g_h  [(size_t)N_NODES * DD];
__device__ float g_h2 [(size_t)N_NODES * DD];
__device__ float g_m0 [(size_t)N_NODES * DD];
__device__ float g_m1 [(size_t)N_NODES * DD];
__device__ float g_e  [(size_t)N_EDGES * DD];
__device__ float g_pa [(size_t)N_NODES * DD];
__device__ float g_pb [(size_t)N_NODES * DD];
__device__ float g_pc [(size_t)N_NODES * DD];
__device__ float g_pd [(size_t)N_NODES * DD];
__device__ int   g_start[N_EDGES];
__device__ int   g_end  [N_EDGES];
// prepacked weights: 15 chunks x [128 n][128 k] bf16, hi and lo images
__device__ __nv_bfloat16 g_pwh[15 * 16384];
__device__ __nv_bfloat16 g_pwl[15 * 16384];

// ---------------- smem layout ------------------------------------------------
static constexpr int ROW_B  = 272;
static constexpr int SM_B1  = 64;     // 128 f32
static constexpr int SM_W2V = 576;    // 128 f32
static constexpr int SM_B2  = 1088;   // 128 f32
static constexpr int SM_IA  = 1600;   // 64 ints
static constexpr int SM_IB  = 1856;   // 64 ints
static constexpr int SM_AH  = 2176;
static constexpr int TBUF   = 64 * ROW_B;          // 17408
static constexpr int SM_AL  = SM_AH + TBUF;        // 19584
static constexpr int SM_BH  = SM_AL + TBUF;        // 36992  (64 N-rows half)
static constexpr int SM_BL  = SM_BH + TBUF;        // 54400
static constexpr int SM_TOTAL = SM_BL + TBUF;      // 71808
// scatter staging: 64 rows x 512 B = 32768, overlaid on A tiles (34816 B)
static constexpr int SM_STG = SM_AH;

// ---------------- helpers -----------------------------------------------------
__device__ __forceinline__ uint32_t smem_u32(const void* p) {
    uint32_t a;
    asm("{ .reg .u64 t; cvta.to.shared.u64 t, %1; cvt.u32.u64 %0, t; }"
        : "=r"(a) : "l"(p));
    return a;
}

#define LDSM_X4(R0, R1, R2, R3, ADDR) \
    asm volatile("ldmatrix.sync.aligned.m8n8.x4.shared.b16 {%0,%1,%2,%3}, [%4];" \
                 : "=r"(R0), "=r"(R1), "=r"(R2), "=r"(R3) : "r"(ADDR))

__device__ __forceinline__ void mma16816(float* c, const uint32_t* a,
                                         const uint32_t* b) {
    asm volatile(
        "mma.sync.aligned.m16n8k16.row.col.f32.bf16.bf16.f32 "
        "{%0,%1,%2,%3}, {%4,%5,%6,%7}, {%8,%9}, {%0,%1,%2,%3};"
        : "+f"(c[0]), "+f"(c[1]), "+f"(c[2]), "+f"(c[3])
        : "r"(a[0]), "r"(a[1]), "r"(a[2]), "r"(a[3]), "r"(b[0]), "r"(b[1]));
}

__device__ __forceinline__ uint32_t pack_bf2(float a, float b) {
    __nv_bfloat162 t = __floats2bfloat162_rn(a, b);
    return *reinterpret_cast<uint32_t*>(&t);
}

__device__ __forceinline__ void split2(float x, float y, uint32_t& H, uint32_t& L) {
    __nv_bfloat16 hx = __float2bfloat16(x);
    __nv_bfloat16 hy = __float2bfloat16(y);
    float lx = x - __bfloat162float(hx);
    float ly = y - __bfloat162float(hy);
    H = pack_bf2(__bfloat162float(hx), __bfloat162float(hy));
    L = pack_bf2(lx, ly);
}

#define CP_WAIT_ALL() asm volatile("cp.async.wait_group 0;" ::: "memory")

// async copy of one 64-N-row half of a weight chunk into B hi/lo tiles.
__device__ __forceinline__ void copyw_half(uint32_t sb, int tid, int chunk,
                                           int half) {
    const char* srcH = (const char*)(g_pwh + (size_t)chunk * 16384 + half * 8192);
    const char* srcL = (const char*)(g_pwl + (size_t)chunk * 16384 + half * 8192);
    #pragma unroll
    for (int i = tid; i < 1024; i += 256) {
        int rr = i >> 4, q = i & 15;
        uint32_t d = sb + SM_BH + rr * ROW_B + q * 16;
        asm volatile("cp.async.cg.shared.global [%0], [%1], 16;"
                     :: "r"(d), "l"(srcH + i * 16));
        asm volatile("cp.async.cg.shared.global [%0], [%1], 16;"
                     :: "r"(d + (uint32_t)TBUF), "l"(srcL + i * 16));
    }
    asm volatile("cp.async.commit_group;" ::: "memory");
}

// 3-term split GEMM over one B half; warp tile 16(M) x 32(N-local)
template <int KSTEPS>
__device__ __forceinline__ void gemm3h(uint32_t sb, int m0, int nloc,
                                       int a_ro, int a_co, int b_ro, int b_co,
                                       float accp[4][4]) {
    #pragma unroll
    for (int ks = 0; ks < KSTEPS; ++ks) {
        const int k0 = ks * 16;
        uint32_t ah[4], al[4];
        {
            uint32_t ro = (uint32_t)(m0 + a_ro) * ROW_B + (uint32_t)(k0 + a_co) * 2;
            LDSM_X4(ah[0], ah[1], ah[2], ah[3], sb + SM_AH + ro);
            LDSM_X4(al[0], al[1], al[2], al[3], sb + SM_AL + ro);
        }
        uint32_t bh[4][2], bl[4][2];
        #pragma unroll
        for (int nb = 0; nb < 2; ++nb) {
            uint32_t ro = (uint32_t)(nloc + nb * 16 + b_ro) * ROW_B +
                          (uint32_t)(k0 + b_co) * 2;
            uint32_t r0, r1, r2, r3;
            LDSM_X4(r0, r1, r2, r3, sb + SM_BH + ro);
            bh[nb * 2][0] = r0; bh[nb * 2][1] = r1;
            bh[nb * 2 + 1][0] = r2; bh[nb * 2 + 1][1] = r3;
            LDSM_X4(r0, r1, r2, r3, sb + SM_BL + ro);
            bl[nb * 2][0] = r0; bl[nb * 2][1] = r1;
            bl[nb * 2 + 1][0] = r2; bl[nb * 2 + 1][1] = r3;
        }
        #pragma unroll
        for (int na = 0; na < 4; ++na) {
            mma16816(accp[na], ah, bh[na]);
            mma16816(accp[na], ah, bl[na]);
            mma16816(accp[na], al, bh[na]);
        }
    }
}

// one full layer GEMM = two N-half passes (acc[p] accumulates half p)
template <int KS>
__device__ __forceinline__ void layer_gemm(uint32_t sb, int tid, int chunk,
                                           int m0, int nloc,
                                           int a_ro, int a_co, int b_ro, int b_co,
                                           float acc[2][4][4]) {
    #pragma unroll
    for (int p = 0; p < 2; ++p) {
        __syncthreads();                 // prior B reads / smem writes ordered
        copyw_half(sb, tid, chunk, p);
        CP_WAIT_ALL();
        __syncthreads();
        gemm3h<KS>(sb, m0, nloc, a_ro, a_co, b_ro, b_co, acc[p]);
    }
}

__device__ __forceinline__ void zacc2(float acc[2][4][4]) {
    #pragma unroll
    for (int q = 0; q < 32; ++q) (&acc[0][0][0])[q] = 0.f;
}

// stage 64 rows x SRC_K fp32 into A hi/lo smem tiles (contiguous rows)
template <int SRC_K>
__device__ __forceinline__ void stage_a(char* smem, int wid, int lane, int row0,
                                        const float* __restrict__ src, int nrows) {
    for (int r = wid; r < 64; r += 8) {
        int grow = row0 + r;
        float4 v = make_float4(0.f, 0.f, 0.f, 0.f);
        if (grow < nrows && lane < SRC_K / 4)
            v = ((const float4*)(src + (size_t)grow * SRC_K))[lane];
        if (lane < SRC_K / 4) {
            uint32_t h0, l0, h1, l1;
            split2(v.x, v.y, h0, l0);
            split2(v.z, v.w, h1, l1);
            uint32_t off = r * ROW_B + lane * 8;
            *(uint2*)(smem + SM_AH + off) = make_uint2(h0, h1);
            *(uint2*)(smem + SM_AL + off) = make_uint2(l0, l1);
        }
    }
}

// split acc (optional bias+relu) into A hi/lo tiles (cols = both N halves)
__device__ __forceinline__ void acc_to_A(char* smem, float acc[2][4][4],
                                         int m0, int nwn, int g, int tig,
                                         const float* b1s, bool relu) {
    const int rl = m0 + g;
    #pragma unroll
    for (int p = 0; p < 2; ++p)
        #pragma unroll
        for (int na = 0; na < 4; ++na) {
            int cc = p * 64 + nwn + na * 8 + 2 * tig;
            float bx = b1s ? b1s[cc] : 0.f;
            float by = b1s ? b1s[cc + 1] : 0.f;
            float v0 = acc[p][na][0] + bx, v1 = acc[p][na][1] + by;
            float v2 = acc[p][na][2] + bx, v3 = acc[p][na][3] + by;
            if (relu) {
                v0 = fmaxf(v0, 0.f); v1 = fmaxf(v1, 0.f);
                v2 = fmaxf(v2, 0.f); v3 = fmaxf(v3, 0.f);
            }
            uint32_t H, L;
            split2(v0, v1, H, L);
            *(uint32_t*)(smem + SM_AH + rl * ROW_B + cc * 2) = H;
            *(uint32_t*)(smem + SM_AL + rl * ROW_B + cc * 2) = L;
            split2(v2, v3, H, L);
            *(uint32_t*)(smem + SM_AH + (rl + 8) * ROW_B + cc * 2) = H;
            *(uint32_t*)(smem + SM_AL + (rl + 8) * ROW_B + cc * 2) = L;
        }
}

// raw store of acc to out[row][col]
__device__ __forceinline__ void acc_store(float* __restrict__ out,
                                          float acc[2][4][4], int row0,
                                          int m0, int nwn, int g, int tig,
                                          int nrows) {
    const int rl = m0 + g;
    const int g0 = row0 + rl, g1 = g0 + 8;
    #pragma unroll
    for (int p = 0; p < 2; ++p)
        #pragma unroll
        for (int na = 0; na < 4; ++na) {
            int cc = p * 64 + nwn + na * 8 + 2 * tig;
            if (g0 < nrows)
                *(float2*)(out + (size_t)g0 * DD + cc) =
                    make_float2(acc[p][na][0], acc[p][na][1]);
            if (g1 < nrows)
                *(float2*)(out + (size_t)g1 * DD + cc) =
                    make_float2(acc[p][na][2], acc[p][na][3]);
        }
}

// ---------------- small utility kernels ------------------------------------
__global__ void convert_idx_kernel(const void* __restrict__ raw,
                                   int* __restrict__ st, int* __restrict__ en,
                                   int E) {
    __shared__ int s_is64;
    if (threadIdx.x == 0) {
        const unsigned int* w = (const unsigned int*)raw;
        unsigned int acc = 0;
        #pragma unroll 8
        for (int i = 0; i < 128; ++i) acc |= w[2 * i + 1];
        s_is64 = (acc == 0u);
    }
    __syncthreads();
    const int is64 = s_is64;
    int i = blockIdx.x * blockDim.x + threadIdx.x;
    if (i >= 2 * E) return;
    int v;
    if (is64) v = (int)((const long long*)raw)[i];
    else      v = ((const int*)raw)[i];
    if (i < E) st[i] = v; else en[i - E] = v;
}

__global__ void zero_kernel(float4* __restrict__ p, int n4) {
    int i = blockIdx.x * blockDim.x + threadIdx.x;
    if (i < n4) p[i] = make_float4(0.f, 0.f, 0.f, 0.f);
}

// Pack weights transposed: image[chunk][n][k] = W[(koff+k)*128 + n], bf16 hi/lo.
// 0:ne_W1(k<16) 1:ne_W2  2-3:ee_W1(a,b) 4:ee_W2  5-6:nn_W1 7:nn_W2
// 8-10:en_W1(a,b,c) 11:en_W2  12-14:pe_W1(a,b,c)
__global__ void pack_w_kernel(const float* neW1, const float* neW2,
                              const float* eeW1, const float* eeW2,
                              const float* nnW1, const float* nnW2,
                              const float* enW1, const float* enW2,
                              const float* peW1,
                              __nv_bfloat16* gh, __nv_bfloat16* gl) {
    int t = blockIdx.x * blockDim.x + threadIdx.x;
    if (t >= 15 * 16384) return;
    int chunk = t >> 14;
    int e = t & 16383;
    int k = e & 127;
    int n = e >> 7;
    const float* W; int koff = 0; int kvalid = 128;
    switch (chunk) {
        case 0:  W = neW1; kvalid = 16; break;
        case 1:  W = neW2; break;
        case 2: case 3:  W = eeW1; koff = (chunk - 2) * 128; break;
        case 4:  W = eeW2; break;
        case 5: case 6:  W = nnW1; koff = (chunk - 5) * 128; break;
        case 7:  W = nnW2; break;
        case 8: case 9: case 10: W = enW1; koff = (chunk - 8) * 128; break;
        case 11: W = enW2; break;
        default: W = peW1; koff = (chunk - 12) * 128; break;
    }
    float x = (k < kvalid) ? W[(size_t)(koff + k) * 128 + n] : 0.f;
    __nv_bfloat16 h = __float2bfloat16(x);
    __nv_bfloat16 l = __float2bfloat16(x - __bfloat162float(h));
    gh[(size_t)chunk * 16384 + n * 128 + k] = h;
    gl[(size_t)chunk * 16384 + n * 128 + k] = l;
}

// ---------------------------------------------------------------------------
// Fused node kernel.  64 rows/CTA, 256 thr, warp tile 16x32.
// ---------------------------------------------------------------------------
template <int NCH, int KS1, bool PRE2, bool POST2, bool RES>
__global__ void __launch_bounds__(256, 3)
node_fused(const float* __restrict__ s0, const float* __restrict__ s1,
           int wqa, int wqb, float* __restrict__ Qa, float* __restrict__ Qb,
           int w1c0, int w2c,
           int wra, int wrb, float* __restrict__ Ra, float* __restrict__ Rb,
           const float* __restrict__ b1, const float* __restrict__ b2,
           const float* __restrict__ res, float* __restrict__ out, int nrows) {
    extern __shared__ char smem[];
    const uint32_t sb = smem_u32(smem);
    const int tid = threadIdx.x, lane = tid & 31, wid = tid >> 5;
    const int row0 = blockIdx.x * 64;
    const int g = lane >> 2, tig = lane & 3;
    const int m0 = (wid >> 1) * 16;
    const int nwn = (wid & 1) * 32;
    const int a_ro = (lane & 7) + ((lane >> 3) & 1) * 8;
    const int a_co = ((lane >> 4) & 1) * 8;
    const int b_ro = (lane & 7) + ((lane >> 4) & 1) * 8;
    const int b_co = ((lane >> 3) & 1) * 8;

    float* b1s = (float*)(smem + SM_B1);
    float* b2s = (float*)(smem + SM_B2);
    if (tid < 128) { b1s[tid] = b1[tid]; b2s[tid] = b2[tid]; }

    stage_a<KS1 * 16>(smem, wid, lane, row0, s0, nrows);

    float acc[2][4][4];

    if constexpr (PRE2) {
        zacc2(acc);
        layer_gemm<KS1>(sb, tid, wqa, m0, nwn, a_ro, a_co, b_ro, b_co, acc);
        acc_store(Qa, acc, row0, m0, nwn, g, tig, nrows);
        zacc2(acc);
        layer_gemm<KS1>(sb, tid, wqb, m0, nwn, a_ro, a_co, b_ro, b_co, acc);
        acc_store(Qb, acc, row0, m0, nwn, g, tig, nrows);
    }

    zacc2(acc);
    layer_gemm<KS1>(sb, tid, w1c0, m0, nwn, a_ro, a_co, b_ro, b_co, acc);

    if constexpr (NCH == 2) {
        __syncthreads();   // A reads done before restage
        stage_a<128>(smem, wid, lane, row0, s1, nrows);
        layer_gemm<8>(sb, tid, w1c0 + 1, m0, nwn, a_ro, a_co, b_ro, b_co, acc);
    }
    __syncthreads();       // all A/B reads done

    // hidden = relu(acc + b1) -> A tiles
    acc_to_A(smem, acc, m0, nwn, g, tig, b1s, true);

    // layer 2
    zacc2(acc);
    layer_gemm<8>(sb, tid, w2c, m0, nwn, a_ro, a_co, b_ro, b_co, acc);

    // fold b2 (+res) and store h'
    {
        const int rl = m0 + g;
        #pragma unroll
        for (int half = 0; half < 2; ++half) {
            int grow = row0 + rl + half * 8;
            #pragma unroll
            for (int p = 0; p < 2; ++p)
                #pragma unroll
                for (int na = 0; na < 4; ++na) {
                    int cc = p * 64 + nwn + na * 8 + 2 * tig;
                    float bx = b2s[cc], by = b2s[cc + 1];
                    float rx = 0.f, ry = 0.f;
                    if (RES && grow < nrows) {
                        float2 rv = *(const float2*)(res + (size_t)grow * DD + cc);
                        rx = rv.x; ry = rv.y;
                    }
                    acc[p][na][half * 2 + 0] += bx + rx;
                    acc[p][na][half * 2 + 1] += by + ry;
                }
        }
    }
    acc_store(out, acc, row0, m0, nwn, g, tig, nrows);

    if constexpr (POST2) {
        __syncthreads();                          // hidden-A reads done
        acc_to_A(smem, acc, m0, nwn, g, tig, nullptr, false);  // split h'
        zacc2(acc);
        layer_gemm<8>(sb, tid, wra, m0, nwn, a_ro, a_co, b_ro, b_co, acc);
        acc_store(Ra, acc, row0, m0, nwn, g, tig, nrows);
        zacc2(acc);
        layer_gemm<8>(sb, tid, wrb, m0, nwn, a_ro, a_co, b_ro, b_co, acc);
        acc_store(Rb, acc, row0, m0, nwn, g, tig, nrows);
    }
}

// ---------------------------------------------------------------------------
// Edge kernel.  64 edges/CTA, 256 thr, warp tile 16x32.
// SCATTER: stage out rows in smem, then cp.reduce.async.bulk add into msgout.
// ---------------------------------------------------------------------------
template <int NCH, bool SCATTER, bool RES, bool OUT1>
__global__ void __launch_bounds__(256, 3)
edge_mlp(const float* __restrict__ s0,
         const int* __restrict__ ip0, const int* __restrict__ ip1,
         const float* __restrict__ Pa, const float* __restrict__ Pb,
         int w1c, int w2c,
         const float* __restrict__ b1, const float* __restrict__ b2,
         const float* __restrict__ w2vec,
         const float* __restrict__ res, float* __restrict__ out,
         float* __restrict__ msgout, int nrows) {
    extern __shared__ char smem[];
    const uint32_t sb = smem_u32(smem);
    const int tid = threadIdx.x, lane = tid & 31, wid = tid >> 5;
    const int row0 = blockIdx.x * 64;
    const int g = lane >> 2, tig = lane & 3;
    const int m0 = (wid >> 1) * 16;
    const int nwn = (wid & 1) * 32;
    const int a_ro = (lane & 7) + ((lane >> 3) & 1) * 8;
    const int a_co = ((lane >> 4) & 1) * 8;
    const int b_ro = (lane & 7) + ((lane >> 4) & 1) * 8;
    const int b_co = ((lane >> 3) & 1) * 8;

    float* b1s = (float*)(smem + SM_B1);
    float* b2s = (float*)(smem + SM_B2);
    float* w2s = (float*)(smem + SM_W2V);
    int*   s_ia = (int*)(smem + SM_IA);
    int*   s_ib = (int*)(smem + SM_IB);

    if (tid < 128) {
        b1s[tid] = b1[tid];
        if (OUT1) w2s[tid] = w2vec[tid];
        else      b2s[tid] = b2[tid];
    }
    if (tid < 64) {
        int grow = row0 + tid;
        int ia = 0, ib = 0;
        if (grow < nrows) { ia = ip0[grow]; ib = ip1[grow]; }
        s_ia[tid] = ia; s_ib[tid] = ib;
        const char* pa = (const char*)(Pa + (size_t)ia * DD);
        const char* pb = (const char*)(Pb + (size_t)ib * DD);
        #pragma unroll
        for (int l = 0; l < 4; ++l) {
            asm volatile("prefetch.global.L2 [%0];" :: "l"(pa + l * 128));
            asm volatile("prefetch.global.L2 [%0];" :: "l"(pb + l * 128));
        }
    }

    float acc[2][4][4];
    zacc2(acc);

    if constexpr (NCH == 1) {
        stage_a<128>(smem, wid, lane, row0, s0, nrows);
        layer_gemm<8>(sb, tid, w1c, m0, nwn, a_ro, a_co, b_ro, b_co, acc);
    } else {
        __syncthreads();   // s_ia/s_ib + biases visible
    }

    // PRE: acc += Pa[start] + Pb[end]
    {
        const int rl = m0 + g;
        #pragma unroll
        for (int half = 0; half < 2; ++half) {
            int rloc = rl + half * 8;
            int grow = row0 + rloc;
            if (grow < nrows) {
                const float* pa = Pa + (size_t)s_ia[rloc] * DD;
                const float* pb = Pb + (size_t)s_ib[rloc] * DD;
                #pragma unroll
                for (int p = 0; p < 2; ++p)
                    #pragma unroll
                    for (int na = 0; na < 4; ++na) {
                        int cc = p * 64 + nwn + na * 8 + 2 * tig;
                        float2 va = *(const float2*)(pa + cc);
                        float2 vb = *(const float2*)(pb + cc);
                        acc[p][na][half * 2 + 0] += va.x + vb.x;
                        acc[p][na][half * 2 + 1] += va.y + vb.y;
                    }
            }
        }
    }

    if constexpr (OUT1) {
        // hidden fp32 -> hT[64][129] over A tiles, then per-row dot
        float* hT = (float*)(smem + SM_AH);
        __syncthreads();      // A/B reads done before overwrite
        const int rl = m0 + g;
        #pragma unroll
        for (int p = 0; p < 2; ++p)
            #pragma unroll
            for (int na = 0; na < 4; ++na) {
                int cc = p * 64 + nwn + na * 8 + 2 * tig;
                hT[rl * 129 + cc]           = fmaxf(acc[p][na][0] + b1s[cc], 0.f);
                hT[rl * 129 + cc + 1]       = fmaxf(acc[p][na][1] + b1s[cc + 1], 0.f);
                hT[(rl + 8) * 129 + cc]     = fmaxf(acc[p][na][2] + b1s[cc], 0.f);
                hT[(rl + 8) * 129 + cc + 1] = fmaxf(acc[p][na][3] + b1s[cc + 1], 0.f);
            }
        __syncthreads();
        if (tid < 64) {
            int grow = row0 + tid;
            float a = __ldg(&b2[0]);
            #pragma unroll 8
            for (int k = 0; k < 128; ++k) a += hT[tid * 129 + k] * w2s[k];
            if (grow < nrows) out[grow] = a;
        }
        return;
    }

    // hidden = relu(acc + b1) -> A tiles
    __syncthreads();          // A/B reads done
    acc_to_A(smem, acc, m0, nwn, g, tig, b1s, true);

    // layer 2
    zacc2(acc);
    layer_gemm<8>(sb, tid, w2c, m0, nwn, a_ro, a_co, b_ro, b_co, acc);

    // epilogue: out = acc + b2 (+ res)
    if constexpr (!SCATTER) {
        const int rl = m0 + g;
        #pragma unroll
        for (int half = 0; half < 2; ++half) {
            int rloc = rl + half * 8;
            int grow = row0 + rloc;
            if (grow < nrows) {
                #pragma unroll
                for (int p = 0; p < 2; ++p)
                    #pragma unroll
                    for (int na = 0; na < 4; ++na) {
                        int cc = p * 64 + nwn + na * 8 + 2 * tig;
                        float ox = acc[p][na][half * 2 + 0] + b2s[cc];
                        float oy = acc[p][na][half * 2 + 1] + b2s[cc + 1];
                        if (RES) {
                            float2 rv = *(const float2*)(res + (size_t)grow * DD + cc);
                            ox += rv.x; oy += rv.y;
                        }
                        *(float2*)(out + (size_t)grow * DD + cc) = make_float2(ox, oy);
                    }
            }
        }
    } else {
        // stage final rows in smem (A-tile region is free after layer2 gemm),
        // store to out, then bulk-reduce rows into msgout[end].
        __syncthreads();      // all warps done reading A/B tiles
        float* stg = (float*)(smem + SM_STG);   // [64][128] fp32, 512 B rows
        const int rl = m0 + g;
        #pragma unroll
        for (int half = 0; half < 2; ++half) {
            int rloc = rl + half * 8;
            int grow = row0 + rloc;
            if (grow < nrows) {
                #pragma unroll
                for (int p = 0; p < 2; ++p)
                    #pragma unroll
                    for (int na = 0; na < 4; ++na) {
                        int cc = p * 64 + nwn + na * 8 + 2 * tig;
                        float ox = acc[p][na][half * 2 + 0] + b2s[cc];
                        float oy = acc[p][na][half * 2 + 1] + b2s[cc + 1];
                        if (RES) {
                            float2 rv = *(const float2*)(res + (size_t)grow * DD + cc);
                            ox += rv.x; oy += rv.y;
                        }
                        float2 o = make_float2(ox, oy);
                        *(float2*)(out + (size_t)grow * DD + cc) = o;
                        *(float2*)(stg + rloc * DD + cc) = o;
                    }
            }
        }
        __syncthreads();
        asm volatile("fence.proxy.async.shared::cta;" ::: "memory");
        if (tid < 64 && row0 + tid < nrows) {
            uint32_t src = sb + SM_STG + tid * 512;
            float* dst = msgout + (size_t)s_ib[tid] * DD;
            asm volatile(
                "cp.reduce.async.bulk.global.shared::cta.bulk_group.add.f32 "
                "[%0], [%1], 512;"
                :: "l"(dst), "r"(src) : "memory");
        }
        asm volatile("cp.async.bulk.commit_group;" ::: "memory");
        asm volatile("cp.async.bulk.wait_group 0;" ::: "memory");
    }
}

// ---------------------------------------------------------------------------
extern "C" void kernel_launch(void* const* d_in, const int* in_sizes, int n_in,
                              void* d_out, int out_size) {
    const float* nodes = (const float*)d_in[0];
    const void*  eidx  = d_in[1];
    const float* ne_W1 = (const float*)d_in[2];
    const float* ne_b1 = (const float*)d_in[3];
    const float* ne_W2 = (const float*)d_in[4];
    const float* ne_b2 = (const float*)d_in[5];
    const float* ee_W1 = (const float*)d_in[6];
    const float* ee_b1 = (const float*)d_in[7];
    const float* ee_W2 = (const float*)d_in[8];
    const float* ee_b2 = (const float*)d_in[9];
    const float* nn_W1 = (const float*)d_in[10];
    const float* nn_b1 = (const float*)d_in[11];
    const float* nn_W2 = (const float*)d_in[12];
    const float* nn_b2 = (const float*)d_in[13];
    const float* en_W1 = (const float*)d_in[14];
    const float* en_b1 = (const float*)d_in[15];
    const float* en_W2 = (const float*)d_in[16];
    const float* en_b2 = (const float*)d_in[17];
    const float* pe_W1 = (const float*)d_in[18];
    const float* pe_b1 = (const float*)d_in[19];
    const float* pe_W2 = (const float*)d_in[20];
    const float* pe_b2 = (const float*)d_in[21];

    float *h, *h2, *m0, *m1, *e, *pa, *pb, *pc, *pd;
    int *st, *en_;
    __nv_bfloat16 *pwh, *pwl;
    cudaGetSymbolAddress((void**)&h,   g_h);
    cudaGetSymbolAddress((void**)&h2,  g_h2);
    cudaGetSymbolAddress((void**)&m0,  g_m0);
    cudaGetSymbolAddress((void**)&m1,  g_m1);
    cudaGetSymbolAddress((void**)&e,   g_e);
    cudaGetSymbolAddress((void**)&pa,  g_pa);
    cudaGetSymbolAddress((void**)&pb,  g_pb);
    cudaGetSymbolAddress((void**)&pc,  g_pc);
    cudaGetSymbolAddress((void**)&pd,  g_pd);
    cudaGetSymbolAddress((void**)&st,  g_start);
    cudaGetSymbolAddress((void**)&en_, g_end);
    cudaGetSymbolAddress((void**)&pwh, g_pwh);
    cudaGetSymbolAddress((void**)&pwl, g_pwl);

    cudaFuncSetAttribute(node_fused<1, 1, false, true, false>,
                         cudaFuncAttributeMaxDynamicSharedMemorySize, SM_TOTAL);
    cudaFuncSetAttribute(node_fused<2, 8, true, false, true>,
                         cudaFuncAttributeMaxDynamicSharedMemorySize, SM_TOTAL);
    cudaFuncSetAttribute(node_fused<2, 8, true, true, true>,
                         cudaFuncAttributeMaxDynamicSharedMemorySize, SM_TOTAL);
    cudaFuncSetAttribute(edge_mlp<0, true, false, false>,
                         cudaFuncAttributeMaxDynamicSharedMemorySize, SM_TOTAL);
    cudaFuncSetAttribute(edge_mlp<1, true, true, false>,
                         cudaFuncAttributeMaxDynamicSharedMemorySize, SM_TOTAL);
    cudaFuncSetAttribute(edge_mlp<1, false, true, false>,
                         cudaFuncAttributeMaxDynamicSharedMemorySize, SM_TOTAL);
    cudaFuncSetAttribute(edge_mlp<1, false, false, true>,
                         cudaFuncAttributeMaxDynamicSharedMemorySize, SM_TOTAL);

    const int nblk_n = (N_NODES + 63) / 64;  // 1563
    const int nblk_e = (N_EDGES + 63) / 64;  // 9375
    const int zero_n4 = N_NODES * DD / 4;
    const int zero_blks = (zero_n4 + 255) / 256;

    convert_idx_kernel<<<(2 * N_EDGES + 255) / 256, 256>>>(eidx, st, en_, N_EDGES);
    pack_w_kernel<<<(15 * 16384 + 255) / 256, 256>>>(
        ne_W1, ne_W2, ee_W1, ee_W2, nn_W1, nn_W2, en_W1, en_W2, pe_W1, pwh, pwl);

    // h = MLP_ne(nodes);  Pa = h@eeW1a, Pb = h@eeW1b
    node_fused<1, 1, false, true, false><<<nblk_n, 256, SM_TOTAL>>>(
        nodes, nullptr, 0, 0, nullptr, nullptr, 0, 1,
        2, 3, pa, pb, ne_b1, ne_b2, nullptr, h, N_NODES);

    // e = relu(Pa[s]+Pb[e]+b1)@eeW2 + b2;  scatter e -> m0
    zero_kernel<<<zero_blks, 256>>>((float4*)m0, zero_n4);
    edge_mlp<0, true, false, false><<<nblk_e, 256, SM_TOTAL>>>(
        nullptr, st, en_, pa, pb, 0, 4,
        ee_b1, ee_b2, nullptr, nullptr, e, m0, N_EDGES);

    float* hA = h;
    float* hB = h2;
    float* msgs[2] = {m0, m1};

    for (int it = 0; it < NUM_ITERS; ++it) {
        float* mcur = msgs[it & 1];
        float* mnxt = msgs[(it + 1) & 1];
        const bool last = (it == NUM_ITERS - 1);

        if (!last) {
            node_fused<2, 8, true, false, true><<<nblk_n, 256, SM_TOTAL>>>(
                hA, mcur, 8, 9, pa, pb, 5, 7,
                0, 0, nullptr, nullptr, nn_b1, nn_b2, hA, hB, N_NODES);
        } else {
            node_fused<2, 8, true, true, true><<<nblk_n, 256, SM_TOTAL>>>(
                hA, mcur, 8, 9, pa, pb, 5, 7,
                12, 13, pc, pd, nn_b1, nn_b2, hA, hB, N_NODES);
        }

        if (!last) {
            zero_kernel<<<zero_blks, 256>>>((float4*)mnxt, zero_n4);
            edge_mlp<1, true, true, false><<<nblk_e, 256, SM_TOTAL>>>(
                e, st, en_, pa, pb, 10, 11,
                en_b1, en_b2, nullptr, e, e, mnxt, N_EDGES);
        } else {
            edge_mlp<1, false, true, false><<<nblk_e, 256, SM_TOTAL>>>(
                e, st, en_, pa, pb, 10, 11,
                en_b1, en_b2, nullptr, e, e, nullptr, N_EDGES);
        }

        float* t = hA; hA = hB; hB = t;
    }

    // pred = relu(e@peW1c + Ra[s]+Rb[e]+b1) . peW2 + b2
    edge_mlp<1, false, false, true><<<nblk_e, 256, SM_TOTAL>>>(
        e, st, en_, pc, pd, 14, 0,
        pe_b1, pe_b2, pe_W2, nullptr, (float*)d_out, nullptr, N_EDGES);
}

// round 9
// speedup vs baseline: 7.1442x; 1.0323x over previous
#include <cuda_runtime.h>
#include <cuda_bf16.h>
#include <cstdint>

// ---------------------------------------------------------------------------
// InteractionGNN on GB300 — round 9: R8 + copy/compute overlap at phase
// boundaries (issue weight-half copy early, wait late) + msg zeroing fused
// into node kernels (zero_kernel launches removed).
// 64 rows/CTA, 256 thr, warp tile 16x32, half-N weight tiles, 3 CTAs/SM.
// GEMM core: mma.sync bf16 3-term split (Ah*Wh + Ah*Wl + Al*Wh), fp32 accum.
// ---------------------------------------------------------------------------

#define N_NODES 100000
#define N_EDGES 600000
#define DD      128
#define NUM_ITERS 4

// ---------------- device scratch -------------------------------------------
__device__ float g_h  [(size_t)N_NODES * DD];
__device__ float g_h2 [(size_t)N_NODES * DD];
__device__ float g_m0 [(size_t)N_NODES * DD];
__device__ float g_m1 [(size_t)N_NODES * DD];
__device__ float g_e  [(size_t)N_EDGES * DD];
__device__ float g_pa [(size_t)N_NODES * DD];
__device__ float g_pb [(size_t)N_NODES * DD];
__device__ float g_pc [(size_t)N_NODES * DD];
__device__ float g_pd [(size_t)N_NODES * DD];
__device__ int   g_start[N_EDGES];
__device__ int   g_end  [N_EDGES];
// prepacked weights: 15 chunks x [128 n][128 k] bf16, hi and lo images
__device__ __nv_bfloat16 g_pwh[15 * 16384];
__device__ __nv_bfloat16 g_pwl[15 * 16384];

// ---------------- smem layout ------------------------------------------------
static constexpr int ROW_B  = 272;
static constexpr int SM_B1  = 64;     // 128 f32
static constexpr int SM_W2V = 576;    // 128 f32
static constexpr int SM_B2  = 1088;   // 128 f32
static constexpr int SM_IA  = 1600;   // 64 ints
static constexpr int SM_IB  = 1856;   // 64 ints
static constexpr int SM_AH  = 2176;
static constexpr int TBUF   = 64 * ROW_B;          // 17408
static constexpr int SM_AL  = SM_AH + TBUF;        // 19584
static constexpr int SM_BH  = SM_AL + TBUF;        // 36992  (64 N-rows half)
static constexpr int SM_BL  = SM_BH + TBUF;        // 54400
static constexpr int SM_TOTAL = SM_BL + TBUF;      // 71808
// scatter staging: 64 rows x 512 B = 32768, overlaid on A tiles
static constexpr int SM_STG = SM_AH;

// ---------------- helpers -----------------------------------------------------
__device__ __forceinline__ uint32_t smem_u32(const void* p) {
    uint32_t a;
    asm("{ .reg .u64 t; cvta.to.shared.u64 t, %1; cvt.u32.u64 %0, t; }"
        : "=r"(a) : "l"(p));
    return a;
}

#define LDSM_X4(R0, R1, R2, R3, ADDR) \
    asm volatile("ldmatrix.sync.aligned.m8n8.x4.shared.b16 {%0,%1,%2,%3}, [%4];" \
                 : "=r"(R0), "=r"(R1), "=r"(R2), "=r"(R3) : "r"(ADDR))

__device__ __forceinline__ void mma16816(float* c, const uint32_t* a,
                                         const uint32_t* b) {
    asm volatile(
        "mma.sync.aligned.m16n8k16.row.col.f32.bf16.bf16.f32 "
        "{%0,%1,%2,%3}, {%4,%5,%6,%7}, {%8,%9}, {%0,%1,%2,%3};"
        : "+f"(c[0]), "+f"(c[1]), "+f"(c[2]), "+f"(c[3])
        : "r"(a[0]), "r"(a[1]), "r"(a[2]), "r"(a[3]), "r"(b[0]), "r"(b[1]));
}

__device__ __forceinline__ uint32_t pack_bf2(float a, float b) {
    __nv_bfloat162 t = __floats2bfloat162_rn(a, b);
    return *reinterpret_cast<uint32_t*>(&t);
}

__device__ __forceinline__ void split2(float x, float y, uint32_t& H, uint32_t& L) {
    __nv_bfloat16 hx = __float2bfloat16(x);
    __nv_bfloat16 hy = __float2bfloat16(y);
    float lx = x - __bfloat162float(hx);
    float ly = y - __bfloat162float(hy);
    H = pack_bf2(__bfloat162float(hx), __bfloat162float(hy));
    L = pack_bf2(lx, ly);
}

#define CP_WAIT_ALL() asm volatile("cp.async.wait_group 0;" ::: "memory")

// async copy of one 64-N-row half of a weight chunk into B hi/lo tiles.
__device__ __forceinline__ void copyw_half(uint32_t sb, int tid, int chunk,
                                           int half) {
    const char* srcH = (const char*)(g_pwh + (size_t)chunk * 16384 + half * 8192);
    const char* srcL = (const char*)(g_pwl + (size_t)chunk * 16384 + half * 8192);
    #pragma unroll
    for (int i = tid; i < 1024; i += 256) {
        int rr = i >> 4, q = i & 15;
        uint32_t d = sb + SM_BH + rr * ROW_B + q * 16;
        asm volatile("cp.async.cg.shared.global [%0], [%1], 16;"
                     :: "r"(d), "l"(srcH + i * 16));
        asm volatile("cp.async.cg.shared.global [%0], [%1], 16;"
                     :: "r"(d + (uint32_t)TBUF), "l"(srcL + i * 16));
    }
    asm volatile("cp.async.commit_group;" ::: "memory");
}

// 3-term split GEMM over one B half; warp tile 16(M) x 32(N-local)
template <int KSTEPS>
__device__ __forceinline__ void gemm3h(uint32_t sb, int m0, int nloc,
                                       int a_ro, int a_co, int b_ro, int b_co,
                                       float accp[4][4]) {
    #pragma unroll
    for (int ks = 0; ks < KSTEPS; ++ks) {
        const int k0 = ks * 16;
        uint32_t ah[4], al[4];
        {
            uint32_t ro = (uint32_t)(m0 + a_ro) * ROW_B + (uint32_t)(k0 + a_co) * 2;
            LDSM_X4(ah[0], ah[1], ah[2], ah[3], sb + SM_AH + ro);
            LDSM_X4(al[0], al[1], al[2], al[3], sb + SM_AL + ro);
        }
        uint32_t bh[4][2], bl[4][2];
        #pragma unroll
        for (int nb = 0; nb < 2; ++nb) {
            uint32_t ro = (uint32_t)(nloc + nb * 16 + b_ro) * ROW_B +
                          (uint32_t)(k0 + b_co) * 2;
            uint32_t r0, r1, r2, r3;
            LDSM_X4(r0, r1, r2, r3, sb + SM_BH + ro);
            bh[nb * 2][0] = r0; bh[nb * 2][1] = r1;
            bh[nb * 2 + 1][0] = r2; bh[nb * 2 + 1][1] = r3;
            LDSM_X4(r0, r1, r2, r3, sb + SM_BL + ro);
            bl[nb * 2][0] = r0; bl[nb * 2][1] = r1;
            bl[nb * 2 + 1][0] = r2; bl[nb * 2 + 1][1] = r3;
        }
        #pragma unroll
        for (int na = 0; na < 4; ++na) {
            mma16816(accp[na], ah, bh[na]);
            mma16816(accp[na], ah, bl[na]);
            mma16816(accp[na], al, bh[na]);
        }
    }
}

// Full layer GEMM assuming copyw_half(chunk, 0) was ALREADY issued by caller
// (after a __syncthreads() that retired all prior B reads).
template <int KS>
__device__ __forceinline__ void layer_gemm_issued(uint32_t sb, int tid, int chunk,
                                                  int m0, int nloc,
                                                  int a_ro, int a_co,
                                                  int b_ro, int b_co,
                                                  float acc[2][4][4]) {
    CP_WAIT_ALL();
    __syncthreads();
    gemm3h<KS>(sb, m0, nloc, a_ro, a_co, b_ro, b_co, acc[0]);
    __syncthreads();                 // half-0 B reads done
    copyw_half(sb, tid, chunk, 1);
    CP_WAIT_ALL();
    __syncthreads();
    gemm3h<KS>(sb, m0, nloc, a_ro, a_co, b_ro, b_co, acc[1]);
}

__device__ __forceinline__ void zacc2(float acc[2][4][4]) {
    #pragma unroll
    for (int q = 0; q < 32; ++q) (&acc[0][0][0])[q] = 0.f;
}

// stage 64 rows x SRC_K fp32 into A hi/lo smem tiles (contiguous rows)
template <int SRC_K>
__device__ __forceinline__ void stage_a(char* smem, int wid, int lane, int row0,
                                        const float* __restrict__ src, int nrows) {
    for (int r = wid; r < 64; r += 8) {
        int grow = row0 + r;
        float4 v = make_float4(0.f, 0.f, 0.f, 0.f);
        if (grow < nrows && lane < SRC_K / 4)
            v = ((const float4*)(src + (size_t)grow * SRC_K))[lane];
        if (lane < SRC_K / 4) {
            uint32_t h0, l0, h1, l1;
            split2(v.x, v.y, h0, l0);
            split2(v.z, v.w, h1, l1);
            uint32_t off = r * ROW_B + lane * 8;
            *(uint2*)(smem + SM_AH + off) = make_uint2(h0, h1);
            *(uint2*)(smem + SM_AL + off) = make_uint2(l0, l1);
        }
    }
}

// split acc (optional bias+relu) into A hi/lo tiles (cols = both N halves)
__device__ __forceinline__ void acc_to_A(char* smem, float acc[2][4][4],
                                         int m0, int nwn, int g, int tig,
                                         const float* b1s, bool relu) {
    const int rl = m0 + g;
    #pragma unroll
    for (int p = 0; p < 2; ++p)
        #pragma unroll
        for (int na = 0; na < 4; ++na) {
            int cc = p * 64 + nwn + na * 8 + 2 * tig;
            float bx = b1s ? b1s[cc] : 0.f;
            float by = b1s ? b1s[cc + 1] : 0.f;
            float v0 = acc[p][na][0] + bx, v1 = acc[p][na][1] + by;
            float v2 = acc[p][na][2] + bx, v3 = acc[p][na][3] + by;
            if (relu) {
                v0 = fmaxf(v0, 0.f); v1 = fmaxf(v1, 0.f);
                v2 = fmaxf(v2, 0.f); v3 = fmaxf(v3, 0.f);
            }
            uint32_t H, L;
            split2(v0, v1, H, L);
            *(uint32_t*)(smem + SM_AH + rl * ROW_B + cc * 2) = H;
            *(uint32_t*)(smem + SM_AL + rl * ROW_B + cc * 2) = L;
            split2(v2, v3, H, L);
            *(uint32_t*)(smem + SM_AH + (rl + 8) * ROW_B + cc * 2) = H;
            *(uint32_t*)(smem + SM_AL + (rl + 8) * ROW_B + cc * 2) = L;
        }
}

// raw store of acc to out[row][col]
__device__ __forceinline__ void acc_store(float* __restrict__ out,
                                          float acc[2][4][4], int row0,
                                          int m0, int nwn, int g, int tig,
                                          int nrows) {
    const int rl = m0 + g;
    const int g0 = row0 + rl, g1 = g0 + 8;
    #pragma unroll
    for (int p = 0; p < 2; ++p)
        #pragma unroll
        for (int na = 0; na < 4; ++na) {
            int cc = p * 64 + nwn + na * 8 + 2 * tig;
            if (g0 < nrows)
                *(float2*)(out + (size_t)g0 * DD + cc) =
                    make_float2(acc[p][na][0], acc[p][na][1]);
            if (g1 < nrows)
                *(float2*)(out + (size_t)g1 * DD + cc) =
                    make_float2(acc[p][na][2], acc[p][na][3]);
        }
}

// ---------------- small utility kernels ------------------------------------
__global__ void convert_idx_kernel(const void* __restrict__ raw,
                                   int* __restrict__ st, int* __restrict__ en,
                                   int E) {
    __shared__ int s_is64;
    if (threadIdx.x == 0) {
        const unsigned int* w = (const unsigned int*)raw;
        unsigned int acc = 0;
        #pragma unroll 8
        for (int i = 0; i < 128; ++i) acc |= w[2 * i + 1];
        s_is64 = (acc == 0u);
    }
    __syncthreads();
    const int is64 = s_is64;
    int i = blockIdx.x * blockDim.x + threadIdx.x;
    if (i >= 2 * E) return;
    int v;
    if (is64) v = (int)((const long long*)raw)[i];
    else      v = ((const int*)raw)[i];
    if (i < E) st[i] = v; else en[i - E] = v;
}

// Pack weights transposed: image[chunk][n][k] = W[(koff+k)*128 + n], bf16 hi/lo.
// 0:ne_W1(k<16) 1:ne_W2  2-3:ee_W1(a,b) 4:ee_W2  5-6:nn_W1 7:nn_W2
// 8-10:en_W1(a,b,c) 11:en_W2  12-14:pe_W1(a,b,c)
__global__ void pack_w_kernel(const float* neW1, const float* neW2,
                              const float* eeW1, const float* eeW2,
                              const float* nnW1, const float* nnW2,
                              const float* enW1, const float* enW2,
                              const float* peW1,
                              __nv_bfloat16* gh, __nv_bfloat16* gl) {
    int t = blockIdx.x * blockDim.x + threadIdx.x;
    if (t >= 15 * 16384) return;
    int chunk = t >> 14;
    int e = t & 16383;
    int k = e & 127;
    int n = e >> 7;
    const float* W; int koff = 0; int kvalid = 128;
    switch (chunk) {
        case 0:  W = neW1; kvalid = 16; break;
        case 1:  W = neW2; break;
        case 2: case 3:  W = eeW1; koff = (chunk - 2) * 128; break;
        case 4:  W = eeW2; break;
        case 5: case 6:  W = nnW1; koff = (chunk - 5) * 128; break;
        case 7:  W = nnW2; break;
        case 8: case 9: case 10: W = enW1; koff = (chunk - 8) * 128; break;
        case 11: W = enW2; break;
        default: W = peW1; koff = (chunk - 12) * 128; break;
    }
    float x = (k < kvalid) ? W[(size_t)(koff + k) * 128 + n] : 0.f;
    __nv_bfloat16 h = __float2bfloat16(x);
    __nv_bfloat16 l = __float2bfloat16(x - __bfloat162float(h));
    gh[(size_t)chunk * 16384 + n * 128 + k] = h;
    gl[(size_t)chunk * 16384 + n * 128 + k] = l;
}

// ---------------------------------------------------------------------------
// Fused node kernel.  64 rows/CTA, 256 thr, warp tile 16x32.
// zrow != nullptr: zero zrow rows [row0, row0+64) (next msg buffer).
// ---------------------------------------------------------------------------
template <int NCH, int KS1, bool PRE2, bool POST2, bool RES>
__global__ void __launch_bounds__(256, 3)
node_fused(const float* __restrict__ s0, const float* __restrict__ s1,
           int wqa, int wqb, float* __restrict__ Qa, float* __restrict__ Qb,
           int w1c0, int w2c,
           int wra, int wrb, float* __restrict__ Ra, float* __restrict__ Rb,
           const float* __restrict__ b1, const float* __restrict__ b2,
           const float* __restrict__ res, float* __restrict__ out,
           float* __restrict__ zrow, int nrows) {
    extern __shared__ char smem[];
    const uint32_t sb = smem_u32(smem);
    const int tid = threadIdx.x, lane = tid & 31, wid = tid >> 5;
    const int row0 = blockIdx.x * 64;
    const int g = lane >> 2, tig = lane & 3;
    const int m0 = (wid >> 1) * 16;
    const int nwn = (wid & 1) * 32;
    const int a_ro = (lane & 7) + ((lane >> 3) & 1) * 8;
    const int a_co = ((lane >> 4) & 1) * 8;
    const int b_ro = (lane & 7) + ((lane >> 4) & 1) * 8;
    const int b_co = ((lane >> 3) & 1) * 8;

    float* b1s = (float*)(smem + SM_B1);
    float* b2s = (float*)(smem + SM_B2);
    if (tid < 128) { b1s[tid] = b1[tid]; b2s[tid] = b2[tid]; }

    // issue first weight-half copy ASAP (fresh B buffers)
    copyw_half(sb, tid, PRE2 ? wqa : w1c0, 0);

    // fused zeroing of next msg buffer rows (independent global stores)
    if (zrow != nullptr) {
        float4* zp = (float4*)(zrow + (size_t)row0 * DD);
        int nz = (nrows - row0 < 64 ? nrows - row0 : 64) * 32;
        for (int i = tid; i < nz; i += 256)
            zp[i] = make_float4(0.f, 0.f, 0.f, 0.f);
    }

    stage_a<KS1 * 16>(smem, wid, lane, row0, s0, nrows);

    float acc[2][4][4];

    if constexpr (PRE2) {
        zacc2(acc);
        layer_gemm_issued<KS1>(sb, tid, wqa, m0, nwn, a_ro, a_co, b_ro, b_co, acc);
        __syncthreads();
        copyw_half(sb, tid, wqb, 0);
        acc_store(Qa, acc, row0, m0, nwn, g, tig, nrows);   // overlaps copy
        zacc2(acc);
        layer_gemm_issued<KS1>(sb, tid, wqb, m0, nwn, a_ro, a_co, b_ro, b_co, acc);
        __syncthreads();
        copyw_half(sb, tid, w1c0, 0);
        acc_store(Qb, acc, row0, m0, nwn, g, tig, nrows);   // overlaps copy
    }

    zacc2(acc);
    layer_gemm_issued<KS1>(sb, tid, w1c0, m0, nwn, a_ro, a_co, b_ro, b_co, acc);

    if constexpr (NCH == 2) {
        __syncthreads();                 // A/B reads done
        copyw_half(sb, tid, w1c0 + 1, 0);
        stage_a<128>(smem, wid, lane, row0, s1, nrows);     // overlaps copy
        layer_gemm_issued<8>(sb, tid, w1c0 + 1, m0, nwn, a_ro, a_co, b_ro, b_co, acc);
    }

    __syncthreads();                     // all A/B reads done
    copyw_half(sb, tid, w2c, 0);
    acc_to_A(smem, acc, m0, nwn, g, tig, b1s, true);        // overlaps copy

    // layer 2
    float hid[2][4][4];
    #pragma unroll
    for (int q = 0; q < 32; ++q) (&hid[0][0][0])[q] = (&acc[0][0][0])[q];
    zacc2(acc);
    layer_gemm_issued<8>(sb, tid, w2c, m0, nwn, a_ro, a_co, b_ro, b_co, acc);

    // fold b2 (+res) and store h'
    {
        const int rl = m0 + g;
        #pragma unroll
        for (int half = 0; half < 2; ++half) {
            int grow = row0 + rl + half * 8;
            #pragma unroll
            for (int p = 0; p < 2; ++p)
                #pragma unroll
                for (int na = 0; na < 4; ++na) {
                    int cc = p * 64 + nwn + na * 8 + 2 * tig;
                    float bx = b2s[cc], by = b2s[cc + 1];
                    float rx = 0.f, ry = 0.f;
                    if (RES && grow < nrows) {
                        float2 rv = *(const float2*)(res + (size_t)grow * DD + cc);
                        rx = rv.x; ry = rv.y;
                    }
                    acc[p][na][half * 2 + 0] += bx + rx;
                    acc[p][na][half * 2 + 1] += by + ry;
                }
        }
    }

    if constexpr (POST2) {
        __syncthreads();                 // hidden-A + B reads done
        copyw_half(sb, tid, wra, 0);
        acc_store(out, acc, row0, m0, nwn, g, tig, nrows);  // overlaps copy
        acc_to_A(smem, acc, m0, nwn, g, tig, nullptr, false);  // split h'
        zacc2(acc);
        layer_gemm_issued<8>(sb, tid, wra, m0, nwn, a_ro, a_co, b_ro, b_co, acc);
        __syncthreads();
        copyw_half(sb, tid, wrb, 0);
        acc_store(Ra, acc, row0, m0, nwn, g, tig, nrows);   // overlaps copy
        zacc2(acc);
        layer_gemm_issued<8>(sb, tid, wrb, m0, nwn, a_ro, a_co, b_ro, b_co, acc);
        acc_store(Rb, acc, row0, m0, nwn, g, tig, nrows);
    } else {
        acc_store(out, acc, row0, m0, nwn, g, tig, nrows);
        (void)hid;
    }
}

// ---------------------------------------------------------------------------
// Edge kernel.  64 edges/CTA, 256 thr, warp tile 16x32.
// SCATTER: stage out rows in smem, then cp.reduce.async.bulk add into msgout.
// ---------------------------------------------------------------------------
template <int NCH, bool SCATTER, bool RES, bool OUT1>
__global__ void __launch_bounds__(256, 3)
edge_mlp(const float* __restrict__ s0,
         const int* __restrict__ ip0, const int* __restrict__ ip1,
         const float* __restrict__ Pa, const float* __restrict__ Pb,
         int w1c, int w2c,
         const float* __restrict__ b1, const float* __restrict__ b2,
         const float* __restrict__ w2vec,
         const float* __restrict__ res, float* __restrict__ out,
         float* __restrict__ msgout, int nrows) {
    extern __shared__ char smem[];
    const uint32_t sb = smem_u32(smem);
    const int tid = threadIdx.x, lane = tid & 31, wid = tid >> 5;
    const int row0 = blockIdx.x * 64;
    const int g = lane >> 2, tig = lane & 3;
    const int m0 = (wid >> 1) * 16;
    const int nwn = (wid & 1) * 32;
    const int a_ro = (lane & 7) + ((lane >> 3) & 1) * 8;
    const int a_co = ((lane >> 4) & 1) * 8;
    const int b_ro = (lane & 7) + ((lane >> 4) & 1) * 8;
    const int b_co = ((lane >> 3) & 1) * 8;

    float* b1s = (float*)(smem + SM_B1);
    float* b2s = (float*)(smem + SM_B2);
    float* w2s = (float*)(smem + SM_W2V);
    int*   s_ia = (int*)(smem + SM_IA);
    int*   s_ib = (int*)(smem + SM_IB);

    // issue first weight copy ASAP (fresh B buffers)
    copyw_half(sb, tid, NCH == 1 ? w1c : w2c, 0);

    if (tid < 128) {
        b1s[tid] = b1[tid];
        if (OUT1) w2s[tid] = w2vec[tid];
        else      b2s[tid] = b2[tid];
    }
    if (tid < 64) {
        int grow = row0 + tid;
        int ia = 0, ib = 0;
        if (grow < nrows) { ia = ip0[grow]; ib = ip1[grow]; }
        s_ia[tid] = ia; s_ib[tid] = ib;
        const char* pa = (const char*)(Pa + (size_t)ia * DD);
        const char* pb = (const char*)(Pb + (size_t)ib * DD);
        #pragma unroll
        for (int l = 0; l < 4; ++l) {
            asm volatile("prefetch.global.L2 [%0];" :: "l"(pa + l * 128));
            asm volatile("prefetch.global.L2 [%0];" :: "l"(pb + l * 128));
        }
    }

    float acc[2][4][4];
    zacc2(acc);

    if constexpr (NCH == 1) {
        stage_a<128>(smem, wid, lane, row0, s0, nrows);     // overlaps copy
        layer_gemm_issued<8>(sb, tid, w1c, m0, nwn, a_ro, a_co, b_ro, b_co, acc);
    } else {
        __syncthreads();   // s_ia/s_ib + biases visible
    }

    // PRE: acc += Pa[start] + Pb[end]
    {
        const int rl = m0 + g;
        #pragma unroll
        for (int half = 0; half < 2; ++half) {
            int rloc = rl + half * 8;
            int grow = row0 + rloc;
            if (grow < nrows) {
                const float* pa = Pa + (size_t)s_ia[rloc] * DD;
                const float* pb = Pb + (size_t)s_ib[rloc] * DD;
                #pragma unroll
                for (int p = 0; p < 2; ++p)
                    #pragma unroll
                    for (int na = 0; na < 4; ++na) {
                        int cc = p * 64 + nwn + na * 8 + 2 * tig;
                        float2 va = *(const float2*)(pa + cc);
                        float2 vb = *(const float2*)(pb + cc);
                        acc[p][na][half * 2 + 0] += va.x + vb.x;
                        acc[p][na][half * 2 + 1] += va.y + vb.y;
                    }
            }
        }
    }

    if constexpr (OUT1) {
        // hidden fp32 -> hT[64][129] over A tiles, then per-row dot
        float* hT = (float*)(smem + SM_AH);
        __syncthreads();      // A/B reads done before overwrite
        const int rl = m0 + g;
        #pragma unroll
        for (int p = 0; p < 2; ++p)
            #pragma unroll
            for (int na = 0; na < 4; ++na) {
                int cc = p * 64 + nwn + na * 8 + 2 * tig;
                hT[rl * 129 + cc]           = fmaxf(acc[p][na][0] + b1s[cc], 0.f);
                hT[rl * 129 + cc + 1]       = fmaxf(acc[p][na][1] + b1s[cc + 1], 0.f);
                hT[(rl + 8) * 129 + cc]     = fmaxf(acc[p][na][2] + b1s[cc], 0.f);
                hT[(rl + 8) * 129 + cc + 1] = fmaxf(acc[p][na][3] + b1s[cc + 1], 0.f);
            }
        __syncthreads();
        if (tid < 64) {
            int grow = row0 + tid;
            float a = __ldg(&b2[0]);
            #pragma unroll 8
            for (int k = 0; k < 128; ++k) a += hT[tid * 129 + k] * w2s[k];
            if (grow < nrows) out[grow] = a;
        }
        return;
    }

    // layer 2: issue W2 copy, then hidden split overlaps it
    if constexpr (NCH == 1) {
        __syncthreads();          // A/B reads done
        copyw_half(sb, tid, w2c, 0);
    }
    acc_to_A(smem, acc, m0, nwn, g, tig, b1s, true);
    zacc2(acc);
    layer_gemm_issued<8>(sb, tid, w2c, m0, nwn, a_ro, a_co, b_ro, b_co, acc);

    // epilogue: out = acc + b2 (+ res)
    if constexpr (!SCATTER) {
        const int rl = m0 + g;
        #pragma unroll
        for (int half = 0; half < 2; ++half) {
            int rloc = rl + half * 8;
            int grow = row0 + rloc;
            if (grow < nrows) {
                #pragma unroll
                for (int p = 0; p < 2; ++p)
                    #pragma unroll
                    for (int na = 0; na < 4; ++na) {
                        int cc = p * 64 + nwn + na * 8 + 2 * tig;
                        float ox = acc[p][na][half * 2 + 0] + b2s[cc];
                        float oy = acc[p][na][half * 2 + 1] + b2s[cc + 1];
                        if (RES) {
                            float2 rv = *(const float2*)(res + (size_t)grow * DD + cc);
                            ox += rv.x; oy += rv.y;
                        }
                        *(float2*)(out + (size_t)grow * DD + cc) = make_float2(ox, oy);
                    }
            }
        }
    } else {
        __syncthreads();      // all warps done reading A/B tiles
        float* stg = (float*)(smem + SM_STG);   // [64][128] fp32
        const int rl = m0 + g;
        #pragma unroll
        for (int half = 0; half < 2; ++half) {
            int rloc = rl + half * 8;
            int grow = row0 + rloc;
            if (grow < nrows) {
                #pragma unroll
                for (int p = 0; p < 2; ++p)
                    #pragma unroll
                    for (int na = 0; na < 4; ++na) {
                        int cc = p * 64 + nwn + na * 8 + 2 * tig;
                        float ox = acc[p][na][half * 2 + 0] + b2s[cc];
                        float oy = acc[p][na][half * 2 + 1] + b2s[cc + 1];
                        if (RES) {
                            float2 rv = *(const float2*)(res + (size_t)grow * DD + cc);
                            ox += rv.x; oy += rv.y;
                        }
                        float2 o = make_float2(ox, oy);
                        *(float2*)(out + (size_t)grow * DD + cc) = o;
                        *(float2*)(stg + rloc * DD + cc) = o;
                    }
            }
        }
        __syncthreads();
        asm volatile("fence.proxy.async.shared::cta;" ::: "memory");
        if (tid < 64 && row0 + tid < nrows) {
            uint32_t src = sb + SM_STG + tid * 512;
            float* dst = msgout + (size_t)s_ib[tid] * DD;
            asm volatile(
                "cp.reduce.async.bulk.global.shared::cta.bulk_group.add.f32 "
                "[%0], [%1], 512;"
                :: "l"(dst), "r"(src) : "memory");
        }
        asm volatile("cp.async.bulk.commit_group;" ::: "memory");
        asm volatile("cp.async.bulk.wait_group 0;" ::: "memory");
    }
}

// ---------------------------------------------------------------------------
extern "C" void kernel_launch(void* const* d_in, const int* in_sizes, int n_in,
                              void* d_out, int out_size) {
    const float* nodes = (const float*)d_in[0];
    const void*  eidx  = d_in[1];
    const float* ne_W1 = (const float*)d_in[2];
    const float* ne_b1 = (const float*)d_in[3];
    const float* ne_W2 = (const float*)d_in[4];
    const float* ne_b2 = (const float*)d_in[5];
    const float* ee_W1 = (const float*)d_in[6];
    const float* ee_b1 = (const float*)d_in[7];
    const float* ee_W2 = (const float*)d_in[8];
    const float* ee_b2 = (const float*)d_in[9];
    const float* nn_W1 = (const float*)d_in[10];
    const float* nn_b1 = (const float*)d_in[11];
    const float* nn_W2 = (const float*)d_in[12];
    const float* nn_b2 = (const float*)d_in[13];
    const float* en_W1 = (const float*)d_in[14];
    const float* en_b1 = (const float*)d_in[15];
    const float* en_W2 = (const float*)d_in[16];
    const float* en_b2 = (const float*)d_in[17];
    const float* pe_W1 = (const float*)d_in[18];
    const float* pe_b1 = (const float*)d_in[19];
    const float* pe_W2 = (const float*)d_in[20];
    const float* pe_b2 = (const float*)d_in[21];

    float *h, *h2, *m0, *m1, *e, *pa, *pb, *pc, *pd;
    int *st, *en_;
    __nv_bfloat16 *pwh, *pwl;
    cudaGetSymbolAddress((void**)&h,   g_h);
    cudaGetSymbolAddress((void**)&h2,  g_h2);
    cudaGetSymbolAddress((void**)&m0,  g_m0);
    cudaGetSymbolAddress((void**)&m1,  g_m1);
    cudaGetSymbolAddress((void**)&e,   g_e);
    cudaGetSymbolAddress((void**)&pa,  g_pa);
    cudaGetSymbolAddress((void**)&pb,  g_pb);
    cudaGetSymbolAddress((void**)&pc,  g_pc);
    cudaGetSymbolAddress((void**)&pd,  g_pd);
    cudaGetSymbolAddress((void**)&st,  g_start);
    cudaGetSymbolAddress((void**)&en_, g_end);
    cudaGetSymbolAddress((void**)&pwh, g_pwh);
    cudaGetSymbolAddress((void**)&pwl, g_pwl);

    cudaFuncSetAttribute(node_fused<1, 1, false, true, false>,
                         cudaFuncAttributeMaxDynamicSharedMemorySize, SM_TOTAL);
    cudaFuncSetAttribute(node_fused<2, 8, true, false, true>,
                         cudaFuncAttributeMaxDynamicSharedMemorySize, SM_TOTAL);
    cudaFuncSetAttribute(node_fused<2, 8, true, true, true>,
                         cudaFuncAttributeMaxDynamicSharedMemorySize, SM_TOTAL);
    cudaFuncSetAttribute(edge_mlp<0, true, false, false>,
                         cudaFuncAttributeMaxDynamicSharedMemorySize, SM_TOTAL);
    cudaFuncSetAttribute(edge_mlp<1, true, true, false>,
                         cudaFuncAttributeMaxDynamicSharedMemorySize, SM_TOTAL);
    cudaFuncSetAttribute(edge_mlp<1, false, true, false>,
                         cudaFuncAttributeMaxDynamicSharedMemorySize, SM_TOTAL);
    cudaFuncSetAttribute(edge_mlp<1, false, false, true>,
                         cudaFuncAttributeMaxDynamicSharedMemorySize, SM_TOTAL);

    const int nblk_n = (N_NODES + 63) / 64;  // 1563
    const int nblk_e = (N_EDGES + 63) / 64;  // 9375

    convert_idx_kernel<<<(2 * N_EDGES + 255) / 256, 256>>>(eidx, st, en_, N_EDGES);
    pack_w_kernel<<<(15 * 16384 + 255) / 256, 256>>>(
        ne_W1, ne_W2, ee_W1, ee_W2, nn_W1, nn_W2, en_W1, en_W2, pe_W1, pwh, pwl);

    // h = MLP_ne(nodes);  Pa = h@eeW1a, Pb = h@eeW1b;  zero m0
    node_fused<1, 1, false, true, false><<<nblk_n, 256, SM_TOTAL>>>(
        nodes, nullptr, 0, 0, nullptr, nullptr, 0, 1,
        2, 3, pa, pb, ne_b1, ne_b2, nullptr, h, m0, N_NODES);

    // e = relu(Pa[s]+Pb[e]+b1)@eeW2 + b2;  scatter e -> m0
    edge_mlp<0, true, false, false><<<nblk_e, 256, SM_TOTAL>>>(
        nullptr, st, en_, pa, pb, 0, 4,
        ee_b1, ee_b2, nullptr, nullptr, e, m0, N_EDGES);

    float* hA = h;
    float* hB = h2;
    float* msgs[2] = {m0, m1};

    for (int it = 0; it < NUM_ITERS; ++it) {
        float* mcur = msgs[it & 1];
        float* mnxt = msgs[(it + 1) & 1];
        const bool last = (it == NUM_ITERS - 1);
        float* zr = last ? nullptr : mnxt;

        if (!last) {
            node_fused<2, 8, true, false, true><<<nblk_n, 256, SM_TOTAL>>>(
                hA, mcur, 8, 9, pa, pb, 5, 7,
                0, 0, nullptr, nullptr, nn_b1, nn_b2, hA, hB, zr, N_NODES);
        } else {
            node_fused<2, 8, true, true, true><<<nblk_n, 256, SM_TOTAL>>>(
                hA, mcur, 8, 9, pa, pb, 5, 7,
                12, 13, pc, pd, nn_b1, nn_b2, hA, hB, zr, N_NODES);
        }

        if (!last) {
            edge_mlp<1, true, true, false><<<nblk_e, 256, SM_TOTAL>>>(
                e, st, en_, pa, pb, 10, 11,
                en_b1, en_b2, nullptr, e, e, mnxt, N_EDGES);
        } else {
            edge_mlp<1, false, true, false><<<nblk_e, 256, SM_TOTAL>>>(
                e, st, en_, pa, pb, 10, 11,
                en_b1, en_b2, nullptr, e, e, nullptr, N_EDGES);
        }

        float* t = hA; hA = hB; hB = t;
    }

    // pred = relu(e@peW1c + Ra[s]+Rb[e]+b1) . peW2 + b2
    edge_mlp<1, false, false, true><<<nblk_e, 256, SM_TOTAL>>>(
        e, st, en_, pc, pd, 14, 0,
        pe_b1, pe_b2, pe_W2, nullptr, (float*)d_out, nullptr, N_EDGES);
}

// round 10
// speedup vs baseline: 7.3287x; 1.0258x over previous
#include <cuda_runtime.h>
#include <cuda_bf16.h>
#include <cstdint>

// ---------------------------------------------------------------------------
// InteractionGNN on GB300 — round 10: R9 + final en+pe fusion (e_final never
// touches DRAM) + dead-register fix in node kernel.
// 64 rows/CTA, 256 thr, warp tile 16x32, half-N weight tiles, 3 CTAs/SM.
// GEMM core: mma.sync bf16 3-term split (Ah*Wh + Ah*Wl + Al*Wh), fp32 accum.
// ---------------------------------------------------------------------------

#define N_NODES 100000
#define N_EDGES 600000
#define DD      128
#define NUM_ITERS 4

// ---------------- device scratch -------------------------------------------
__device__ float g_h  [(size_t)N_NODES * DD];
__device__ float g_h2 [(size_t)N_NODES * DD];
__device__ float g_m0 [(size_t)N_NODES * DD];
__device__ float g_m1 [(size_t)N_NODES * DD];
__device__ float g_e  [(size_t)N_EDGES * DD];
__device__ float g_pa [(size_t)N_NODES * DD];
__device__ float g_pb [(size_t)N_NODES * DD];
__device__ float g_pc [(size_t)N_NODES * DD];
__device__ float g_pd [(size_t)N_NODES * DD];
__device__ int   g_start[N_EDGES];
__device__ int   g_end  [N_EDGES];
// prepacked weights: 15 chunks x [128 n][128 k] bf16, hi and lo images
__device__ __nv_bfloat16 g_pwh[15 * 16384];
__device__ __nv_bfloat16 g_pwl[15 * 16384];

// ---------------- smem layout ------------------------------------------------
static constexpr int ROW_B  = 272;
static constexpr int SM_B1  = 64;     // 128 f32
static constexpr int SM_W2V = 576;    // 128 f32
static constexpr int SM_B2  = 1088;   // 128 f32
static constexpr int SM_B1P = 1600;   // 128 f32 (pe_b1 in fused kernel)
static constexpr int SM_IA  = 2112;   // 64 ints
static constexpr int SM_IB  = 2368;   // 64 ints
static constexpr int SM_AH  = 2688;
static constexpr int TBUF   = 64 * ROW_B;          // 17408
static constexpr int SM_AL  = SM_AH + TBUF;        // 20096
static constexpr int SM_BH  = SM_AL + TBUF;        // 37504
static constexpr int SM_BL  = SM_BH + TBUF;        // 54912
static constexpr int SM_TOTAL = SM_BL + TBUF;      // 72320
// scatter staging: 64 rows x 512 B = 32768, overlaid on A tiles
static constexpr int SM_STG = SM_AH;

// ---------------- helpers -----------------------------------------------------
__device__ __forceinline__ uint32_t smem_u32(const void* p) {
    uint32_t a;
    asm("{ .reg .u64 t; cvta.to.shared.u64 t, %1; cvt.u32.u64 %0, t; }"
        : "=r"(a) : "l"(p));
    return a;
}

#define LDSM_X4(R0, R1, R2, R3, ADDR) \
    asm volatile("ldmatrix.sync.aligned.m8n8.x4.shared.b16 {%0,%1,%2,%3}, [%4];" \
                 : "=r"(R0), "=r"(R1), "=r"(R2), "=r"(R3) : "r"(ADDR))

__device__ __forceinline__ void mma16816(float* c, const uint32_t* a,
                                         const uint32_t* b) {
    asm volatile(
        "mma.sync.aligned.m16n8k16.row.col.f32.bf16.bf16.f32 "
        "{%0,%1,%2,%3}, {%4,%5,%6,%7}, {%8,%9}, {%0,%1,%2,%3};"
        : "+f"(c[0]), "+f"(c[1]), "+f"(c[2]), "+f"(c[3])
        : "r"(a[0]), "r"(a[1]), "r"(a[2]), "r"(a[3]), "r"(b[0]), "r"(b[1]));
}

__device__ __forceinline__ uint32_t pack_bf2(float a, float b) {
    __nv_bfloat162 t = __floats2bfloat162_rn(a, b);
    return *reinterpret_cast<uint32_t*>(&t);
}

__device__ __forceinline__ void split2(float x, float y, uint32_t& H, uint32_t& L) {
    __nv_bfloat16 hx = __float2bfloat16(x);
    __nv_bfloat16 hy = __float2bfloat16(y);
    float lx = x - __bfloat162float(hx);
    float ly = y - __bfloat162float(hy);
    H = pack_bf2(__bfloat162float(hx), __bfloat162float(hy));
    L = pack_bf2(lx, ly);
}

#define CP_WAIT_ALL() asm volatile("cp.async.wait_group 0;" ::: "memory")

// async copy of one 64-N-row half of a weight chunk into B hi/lo tiles.
__device__ __forceinline__ void copyw_half(uint32_t sb, int tid, int chunk,
                                           int half) {
    const char* srcH = (const char*)(g_pwh + (size_t)chunk * 16384 + half * 8192);
    const char* srcL = (const char*)(g_pwl + (size_t)chunk * 16384 + half * 8192);
    #pragma unroll
    for (int i = tid; i < 1024; i += 256) {
        int rr = i >> 4, q = i & 15;
        uint32_t d = sb + SM_BH + rr * ROW_B + q * 16;
        asm volatile("cp.async.cg.shared.global [%0], [%1], 16;"
                     :: "r"(d), "l"(srcH + i * 16));
        asm volatile("cp.async.cg.shared.global [%0], [%1], 16;"
                     :: "r"(d + (uint32_t)TBUF), "l"(srcL + i * 16));
    }
    asm volatile("cp.async.commit_group;" ::: "memory");
}

// 3-term split GEMM over one B half; warp tile 16(M) x 32(N-local)
template <int KSTEPS>
__device__ __forceinline__ void gemm3h(uint32_t sb, int m0, int nloc,
                                       int a_ro, int a_co, int b_ro, int b_co,
                                       float accp[4][4]) {
    #pragma unroll
    for (int ks = 0; ks < KSTEPS; ++ks) {
        const int k0 = ks * 16;
        uint32_t ah[4], al[4];
        {
            uint32_t ro = (uint32_t)(m0 + a_ro) * ROW_B + (uint32_t)(k0 + a_co) * 2;
            LDSM_X4(ah[0], ah[1], ah[2], ah[3], sb + SM_AH + ro);
            LDSM_X4(al[0], al[1], al[2], al[3], sb + SM_AL + ro);
        }
        uint32_t bh[4][2], bl[4][2];
        #pragma unroll
        for (int nb = 0; nb < 2; ++nb) {
            uint32_t ro = (uint32_t)(nloc + nb * 16 + b_ro) * ROW_B +
                          (uint32_t)(k0 + b_co) * 2;
            uint32_t r0, r1, r2, r3;
            LDSM_X4(r0, r1, r2, r3, sb + SM_BH + ro);
            bh[nb * 2][0] = r0; bh[nb * 2][1] = r1;
            bh[nb * 2 + 1][0] = r2; bh[nb * 2 + 1][1] = r3;
            LDSM_X4(r0, r1, r2, r3, sb + SM_BL + ro);
            bl[nb * 2][0] = r0; bl[nb * 2][1] = r1;
            bl[nb * 2 + 1][0] = r2; bl[nb * 2 + 1][1] = r3;
        }
        #pragma unroll
        for (int na = 0; na < 4; ++na) {
            mma16816(accp[na], ah, bh[na]);
            mma16816(accp[na], ah, bl[na]);
            mma16816(accp[na], al, bh[na]);
        }
    }
}

// Full layer GEMM assuming copyw_half(chunk, 0) was ALREADY issued by caller
// (after a __syncthreads() that retired all prior B reads).
template <int KS>
__device__ __forceinline__ void layer_gemm_issued(uint32_t sb, int tid, int chunk,
                                                  int m0, int nloc,
                                                  int a_ro, int a_co,
                                                  int b_ro, int b_co,
                                                  float acc[2][4][4]) {
    CP_WAIT_ALL();
    __syncthreads();
    gemm3h<KS>(sb, m0, nloc, a_ro, a_co, b_ro, b_co, acc[0]);
    __syncthreads();                 // half-0 B reads done
    copyw_half(sb, tid, chunk, 1);
    CP_WAIT_ALL();
    __syncthreads();
    gemm3h<KS>(sb, m0, nloc, a_ro, a_co, b_ro, b_co, acc[1]);
}

__device__ __forceinline__ void zacc2(float acc[2][4][4]) {
    #pragma unroll
    for (int q = 0; q < 32; ++q) (&acc[0][0][0])[q] = 0.f;
}

// stage 64 rows x SRC_K fp32 into A hi/lo smem tiles (contiguous rows)
template <int SRC_K>
__device__ __forceinline__ void stage_a(char* smem, int wid, int lane, int row0,
                                        const float* __restrict__ src, int nrows) {
    for (int r = wid; r < 64; r += 8) {
        int grow = row0 + r;
        float4 v = make_float4(0.f, 0.f, 0.f, 0.f);
        if (grow < nrows && lane < SRC_K / 4)
            v = ((const float4*)(src + (size_t)grow * SRC_K))[lane];
        if (lane < SRC_K / 4) {
            uint32_t h0, l0, h1, l1;
            split2(v.x, v.y, h0, l0);
            split2(v.z, v.w, h1, l1);
            uint32_t off = r * ROW_B + lane * 8;
            *(uint2*)(smem + SM_AH + off) = make_uint2(h0, h1);
            *(uint2*)(smem + SM_AL + off) = make_uint2(l0, l1);
        }
    }
}

// split acc (optional bias+relu) into A hi/lo tiles (cols = both N halves)
__device__ __forceinline__ void acc_to_A(char* smem, float acc[2][4][4],
                                         int m0, int nwn, int g, int tig,
                                         const float* b1s, bool relu) {
    const int rl = m0 + g;
    #pragma unroll
    for (int p = 0; p < 2; ++p)
        #pragma unroll
        for (int na = 0; na < 4; ++na) {
            int cc = p * 64 + nwn + na * 8 + 2 * tig;
            float bx = b1s ? b1s[cc] : 0.f;
            float by = b1s ? b1s[cc + 1] : 0.f;
            float v0 = acc[p][na][0] + bx, v1 = acc[p][na][1] + by;
            float v2 = acc[p][na][2] + bx, v3 = acc[p][na][3] + by;
            if (relu) {
                v0 = fmaxf(v0, 0.f); v1 = fmaxf(v1, 0.f);
                v2 = fmaxf(v2, 0.f); v3 = fmaxf(v3, 0.f);
            }
            uint32_t H, L;
            split2(v0, v1, H, L);
            *(uint32_t*)(smem + SM_AH + rl * ROW_B + cc * 2) = H;
            *(uint32_t*)(smem + SM_AL + rl * ROW_B + cc * 2) = L;
            split2(v2, v3, H, L);
            *(uint32_t*)(smem + SM_AH + (rl + 8) * ROW_B + cc * 2) = H;
            *(uint32_t*)(smem + SM_AL + (rl + 8) * ROW_B + cc * 2) = L;
        }
}

// raw store of acc to out[row][col]
__device__ __forceinline__ void acc_store(float* __restrict__ out,
                                          float acc[2][4][4], int row0,
                                          int m0, int nwn, int g, int tig,
                                          int nrows) {
    const int rl = m0 + g;
    const int g0 = row0 + rl, g1 = g0 + 8;
    #pragma unroll
    for (int p = 0; p < 2; ++p)
        #pragma unroll
        for (int na = 0; na < 4; ++na) {
            int cc = p * 64 + nwn + na * 8 + 2 * tig;
            if (g0 < nrows)
                *(float2*)(out + (size_t)g0 * DD + cc) =
                    make_float2(acc[p][na][0], acc[p][na][1]);
            if (g1 < nrows)
                *(float2*)(out + (size_t)g1 * DD + cc) =
                    make_float2(acc[p][na][2], acc[p][na][3]);
        }
}

// gather-add: acc += U[ia] + V[ib]  (per-row indices from smem)
__device__ __forceinline__ void pre_add(float acc[2][4][4],
                                        const float* __restrict__ U,
                                        const float* __restrict__ V,
                                        const int* s_ia, const int* s_ib,
                                        int row0, int m0, int nwn, int g,
                                        int tig, int nrows) {
    const int rl = m0 + g;
    #pragma unroll
    for (int half = 0; half < 2; ++half) {
        int rloc = rl + half * 8;
        int grow = row0 + rloc;
        if (grow < nrows) {
            const float* pu = U + (size_t)s_ia[rloc] * DD;
            const float* pv = V + (size_t)s_ib[rloc] * DD;
            #pragma unroll
            for (int p = 0; p < 2; ++p)
                #pragma unroll
                for (int na = 0; na < 4; ++na) {
                    int cc = p * 64 + nwn + na * 8 + 2 * tig;
                    float2 va = *(const float2*)(pu + cc);
                    float2 vb = *(const float2*)(pv + cc);
                    acc[p][na][half * 2 + 0] += va.x + vb.x;
                    acc[p][na][half * 2 + 1] += va.y + vb.y;
                }
        }
    }
}

// ---------------- small utility kernels ------------------------------------
__global__ void convert_idx_kernel(const void* __restrict__ raw,
                                   int* __restrict__ st, int* __restrict__ en,
                                   int E) {
    __shared__ int s_is64;
    if (threadIdx.x == 0) {
        const unsigned int* w = (const unsigned int*)raw;
        unsigned int acc = 0;
        #pragma unroll 8
        for (int i = 0; i < 128; ++i) acc |= w[2 * i + 1];
        s_is64 = (acc == 0u);
    }
    __syncthreads();
    const int is64 = s_is64;
    int i = blockIdx.x * blockDim.x + threadIdx.x;
    if (i >= 2 * E) return;
    int v;
    if (is64) v = (int)((const long long*)raw)[i];
    else      v = ((const int*)raw)[i];
    if (i < E) st[i] = v; else en[i - E] = v;
}

// Pack weights transposed: image[chunk][n][k] = W[(koff+k)*128 + n], bf16 hi/lo.
// 0:ne_W1(k<16) 1:ne_W2  2-3:ee_W1(a,b) 4:ee_W2  5-6:nn_W1 7:nn_W2
// 8-10:en_W1(a,b,c) 11:en_W2  12-14:pe_W1(a,b,c)
__global__ void pack_w_kernel(const float* neW1, const float* neW2,
                              const float* eeW1, const float* eeW2,
                              const float* nnW1, const float* nnW2,
                              const float* enW1, const float* enW2,
                              const float* peW1,
                              __nv_bfloat16* gh, __nv_bfloat16* gl) {
    int t = blockIdx.x * blockDim.x + threadIdx.x;
    if (t >= 15 * 16384) return;
    int chunk = t >> 14;
    int e = t & 16383;
    int k = e & 127;
    int n = e >> 7;
    const float* W; int koff = 0; int kvalid = 128;
    switch (chunk) {
        case 0:  W = neW1; kvalid = 16; break;
        case 1:  W = neW2; break;
        case 2: case 3:  W = eeW1; koff = (chunk - 2) * 128; break;
        case 4:  W = eeW2; break;
        case 5: case 6:  W = nnW1; koff = (chunk - 5) * 128; break;
        case 7:  W = nnW2; break;
        case 8: case 9: case 10: W = enW1; koff = (chunk - 8) * 128; break;
        case 11: W = enW2; break;
        default: W = peW1; koff = (chunk - 12) * 128; break;
    }
    float x = (k < kvalid) ? W[(size_t)(koff + k) * 128 + n] : 0.f;
    __nv_bfloat16 h = __float2bfloat16(x);
    __nv_bfloat16 l = __float2bfloat16(x - __bfloat162float(h));
    gh[(size_t)chunk * 16384 + n * 128 + k] = h;
    gl[(size_t)chunk * 16384 + n * 128 + k] = l;
}

// ---------------------------------------------------------------------------
// Fused node kernel.  64 rows/CTA, 256 thr, warp tile 16x32.
// ---------------------------------------------------------------------------
template <int NCH, int KS1, bool PRE2, bool POST2, bool RES>
__global__ void __launch_bounds__(256, 3)
node_fused(const float* __restrict__ s0, const float* __restrict__ s1,
           int wqa, int wqb, float* __restrict__ Qa, float* __restrict__ Qb,
           int w1c0, int w2c,
           int wra, int wrb, float* __restrict__ Ra, float* __restrict__ Rb,
           const float* __restrict__ b1, const float* __restrict__ b2,
           const float* __restrict__ res, float* __restrict__ out,
           float* __restrict__ zrow, int nrows) {
    extern __shared__ char smem[];
    const uint32_t sb = smem_u32(smem);
    const int tid = threadIdx.x, lane = tid & 31, wid = tid >> 5;
    const int row0 = blockIdx.x * 64;
    const int g = lane >> 2, tig = lane & 3;
    const int m0 = (wid >> 1) * 16;
    const int nwn = (wid & 1) * 32;
    const int a_ro = (lane & 7) + ((lane >> 3) & 1) * 8;
    const int a_co = ((lane >> 4) & 1) * 8;
    const int b_ro = (lane & 7) + ((lane >> 4) & 1) * 8;
    const int b_co = ((lane >> 3) & 1) * 8;

    float* b1s = (float*)(smem + SM_B1);
    float* b2s = (float*)(smem + SM_B2);
    if (tid < 128) { b1s[tid] = b1[tid]; b2s[tid] = b2[tid]; }

    // issue first weight-half copy ASAP (fresh B buffers)
    copyw_half(sb, tid, PRE2 ? wqa : w1c0, 0);

    // fused zeroing of next msg buffer rows (independent global stores)
    if (zrow != nullptr) {
        float4* zp = (float4*)(zrow + (size_t)row0 * DD);
        int nz = (nrows - row0 < 64 ? nrows - row0 : 64) * 32;
        for (int i = tid; i < nz; i += 256)
            zp[i] = make_float4(0.f, 0.f, 0.f, 0.f);
    }

    stage_a<KS1 * 16>(smem, wid, lane, row0, s0, nrows);

    float acc[2][4][4];

    if constexpr (PRE2) {
        zacc2(acc);
        layer_gemm_issued<KS1>(sb, tid, wqa, m0, nwn, a_ro, a_co, b_ro, b_co, acc);
        __syncthreads();
        copyw_half(sb, tid, wqb, 0);
        acc_store(Qa, acc, row0, m0, nwn, g, tig, nrows);   // overlaps copy
        zacc2(acc);
        layer_gemm_issued<KS1>(sb, tid, wqb, m0, nwn, a_ro, a_co, b_ro, b_co, acc);
        __syncthreads();
        copyw_half(sb, tid, w1c0, 0);
        acc_store(Qb, acc, row0, m0, nwn, g, tig, nrows);   // overlaps copy
    }

    zacc2(acc);
    layer_gemm_issued<KS1>(sb, tid, w1c0, m0, nwn, a_ro, a_co, b_ro, b_co, acc);

    if constexpr (NCH == 2) {
        __syncthreads();                 // A/B reads done
        copyw_half(sb, tid, w1c0 + 1, 0);
        stage_a<128>(smem, wid, lane, row0, s1, nrows);     // overlaps copy
        layer_gemm_issued<8>(sb, tid, w1c0 + 1, m0, nwn, a_ro, a_co, b_ro, b_co, acc);
    }

    __syncthreads();                     // all A/B reads done
    copyw_half(sb, tid, w2c, 0);
    acc_to_A(smem, acc, m0, nwn, g, tig, b1s, true);        // overlaps copy

    // layer 2
    zacc2(acc);
    layer_gemm_issued<8>(sb, tid, w2c, m0, nwn, a_ro, a_co, b_ro, b_co, acc);

    // fold b2 (+res)
    {
        const int rl = m0 + g;
        #pragma unroll
        for (int half = 0; half < 2; ++half) {
            int grow = row0 + rl + half * 8;
            #pragma unroll
            for (int p = 0; p < 2; ++p)
                #pragma unroll
                for (int na = 0; na < 4; ++na) {
                    int cc = p * 64 + nwn + na * 8 + 2 * tig;
                    float bx = b2s[cc], by = b2s[cc + 1];
                    float rx = 0.f, ry = 0.f;
                    if (RES && grow < nrows) {
                        float2 rv = *(const float2*)(res + (size_t)grow * DD + cc);
                        rx = rv.x; ry = rv.y;
                    }
                    acc[p][na][half * 2 + 0] += bx + rx;
                    acc[p][na][half * 2 + 1] += by + ry;
                }
        }
    }

    if constexpr (POST2) {
        __syncthreads();                 // hidden-A + B reads done
        copyw_half(sb, tid, wra, 0);
        acc_store(out, acc, row0, m0, nwn, g, tig, nrows);  // overlaps copy
        acc_to_A(smem, acc, m0, nwn, g, tig, nullptr, false);  // split h'
        zacc2(acc);
        layer_gemm_issued<8>(sb, tid, wra, m0, nwn, a_ro, a_co, b_ro, b_co, acc);
        __syncthreads();
        copyw_half(sb, tid, wrb, 0);
        acc_store(Ra, acc, row0, m0, nwn, g, tig, nrows);   // overlaps copy
        zacc2(acc);
        layer_gemm_issued<8>(sb, tid, wrb, m0, nwn, a_ro, a_co, b_ro, b_co, acc);
        acc_store(Rb, acc, row0, m0, nwn, g, tig, nrows);
    } else {
        acc_store(out, acc, row0, m0, nwn, g, tig, nrows);
    }
}

// ---------------------------------------------------------------------------
// Edge kernel.  64 edges/CTA, 256 thr, warp tile 16x32.
// SCATTER: stage out rows in smem, then cp.reduce.async.bulk add into msgout.
// ---------------------------------------------------------------------------
template <int NCH, bool SCATTER, bool RES>
__global__ void __launch_bounds__(256, 3)
edge_mlp(const float* __restrict__ s0,
         const int* __restrict__ ip0, const int* __restrict__ ip1,
         const float* __restrict__ Pa, const float* __restrict__ Pb,
         int w1c, int w2c,
         const float* __restrict__ b1, const float* __restrict__ b2,
         const float* __restrict__ res, float* __restrict__ out,
         float* __restrict__ msgout, int nrows) {
    extern __shared__ char smem[];
    const uint32_t sb = smem_u32(smem);
    const int tid = threadIdx.x, lane = tid & 31, wid = tid >> 5;
    const int row0 = blockIdx.x * 64;
    const int g = lane >> 2, tig = lane & 3;
    const int m0 = (wid >> 1) * 16;
    const int nwn = (wid & 1) * 32;
    const int a_ro = (lane & 7) + ((lane >> 3) & 1) * 8;
    const int a_co = ((lane >> 4) & 1) * 8;
    const int b_ro = (lane & 7) + ((lane >> 4) & 1) * 8;
    const int b_co = ((lane >> 3) & 1) * 8;

    float* b1s = (float*)(smem + SM_B1);
    float* b2s = (float*)(smem + SM_B2);
    int*   s_ia = (int*)(smem + SM_IA);
    int*   s_ib = (int*)(smem + SM_IB);

    // issue first weight copy ASAP (fresh B buffers)
    copyw_half(sb, tid, NCH == 1 ? w1c : w2c, 0);

    if (tid < 128) { b1s[tid] = b1[tid]; b2s[tid] = b2[tid]; }
    if (tid < 64) {
        int grow = row0 + tid;
        int ia = 0, ib = 0;
        if (grow < nrows) { ia = ip0[grow]; ib = ip1[grow]; }
        s_ia[tid] = ia; s_ib[tid] = ib;
        const char* pa = (const char*)(Pa + (size_t)ia * DD);
        const char* pb = (const char*)(Pb + (size_t)ib * DD);
        #pragma unroll
        for (int l = 0; l < 4; ++l) {
            asm volatile("prefetch.global.L2 [%0];" :: "l"(pa + l * 128));
            asm volatile("prefetch.global.L2 [%0];" :: "l"(pb + l * 128));
        }
    }

    float acc[2][4][4];
    zacc2(acc);

    if constexpr (NCH == 1) {
        stage_a<128>(smem, wid, lane, row0, s0, nrows);     // overlaps copy
        layer_gemm_issued<8>(sb, tid, w1c, m0, nwn, a_ro, a_co, b_ro, b_co, acc);
    } else {
        __syncthreads();   // s_ia/s_ib + biases visible
    }

    // PRE: acc += Pa[start] + Pb[end]
    pre_add(acc, Pa, Pb, s_ia, s_ib, row0, m0, nwn, g, tig, nrows);

    // layer 2: issue W2 copy, then hidden split overlaps it
    if constexpr (NCH == 1) {
        __syncthreads();          // A/B reads done
        copyw_half(sb, tid, w2c, 0);
    }
    acc_to_A(smem, acc, m0, nwn, g, tig, b1s, true);
    zacc2(acc);
    layer_gemm_issued<8>(sb, tid, w2c, m0, nwn, a_ro, a_co, b_ro, b_co, acc);

    // epilogue: out = acc + b2 (+ res)
    if constexpr (!SCATTER) {
        const int rl = m0 + g;
        #pragma unroll
        for (int half = 0; half < 2; ++half) {
            int rloc = rl + half * 8;
            int grow = row0 + rloc;
            if (grow < nrows) {
                #pragma unroll
                for (int p = 0; p < 2; ++p)
                    #pragma unroll
                    for (int na = 0; na < 4; ++na) {
                        int cc = p * 64 + nwn + na * 8 + 2 * tig;
                        float ox = acc[p][na][half * 2 + 0] + b2s[cc];
                        float oy = acc[p][na][half * 2 + 1] + b2s[cc + 1];
                        if (RES) {
                            float2 rv = *(const float2*)(res + (size_t)grow * DD + cc);
                            ox += rv.x; oy += rv.y;
                        }
                        *(float2*)(out + (size_t)grow * DD + cc) = make_float2(ox, oy);
                    }
            }
        }
    } else {
        __syncthreads();      // all warps done reading A/B tiles
        float* stg = (float*)(smem + SM_STG);   // [64][128] fp32
        const int rl = m0 + g;
        #pragma unroll
        for (int half = 0; half < 2; ++half) {
            int rloc = rl + half * 8;
            int grow = row0 + rloc;
            if (grow < nrows) {
                #pragma unroll
                for (int p = 0; p < 2; ++p)
                    #pragma unroll
                    for (int na = 0; na < 4; ++na) {
                        int cc = p * 64 + nwn + na * 8 + 2 * tig;
                        float ox = acc[p][na][half * 2 + 0] + b2s[cc];
                        float oy = acc[p][na][half * 2 + 1] + b2s[cc + 1];
                        if (RES) {
                            float2 rv = *(const float2*)(res + (size_t)grow * DD + cc);
                            ox += rv.x; oy += rv.y;
                        }
                        float2 o = make_float2(ox, oy);
                        *(float2*)(out + (size_t)grow * DD + cc) = o;
                        *(float2*)(stg + rloc * DD + cc) = o;
                    }
            }
        }
        __syncthreads();
        asm volatile("fence.proxy.async.shared::cta;" ::: "memory");
        if (tid < 64 && row0 + tid < nrows) {
            uint32_t src = sb + SM_STG + tid * 512;
            float* dst = msgout + (size_t)s_ib[tid] * DD;
            asm volatile(
                "cp.reduce.async.bulk.global.shared::cta.bulk_group.add.f32 "
                "[%0], [%1], 512;"
                :: "l"(dst), "r"(src) : "memory");
        }
        asm volatile("cp.async.bulk.commit_group;" ::: "memory");
        asm volatile("cp.async.bulk.wait_group 0;" ::: "memory");
    }
}

// ---------------------------------------------------------------------------
// Fused final edge kernel: e_new = en-MLP(e, Qa, Qb) + e  (registers only),
// then pred = relu(e_new@peW1c + Ra[s]+Rb[e] + pe_b1) . pe_w2 + pe_b2.
// e_new is never written to global memory.
// ---------------------------------------------------------------------------
__global__ void __launch_bounds__(256, 3)
edge_en_pe(const float* __restrict__ e,
           const int* __restrict__ ip0, const int* __restrict__ ip1,
           const float* __restrict__ Qa, const float* __restrict__ Qb,
           const float* __restrict__ Ra, const float* __restrict__ Rb,
           const float* __restrict__ en_b1, const float* __restrict__ en_b2,
           const float* __restrict__ pe_b1v, const float* __restrict__ pe_b2v,
           const float* __restrict__ pe_w2v,
           float* __restrict__ pred, int nrows) {
    extern __shared__ char smem[];
    const uint32_t sb = smem_u32(smem);
    const int tid = threadIdx.x, lane = tid & 31, wid = tid >> 5;
    const int row0 = blockIdx.x * 64;
    const int g = lane >> 2, tig = lane & 3;
    const int m0 = (wid >> 1) * 16;
    const int nwn = (wid & 1) * 32;
    const int a_ro = (lane & 7) + ((lane >> 3) & 1) * 8;
    const int a_co = ((lane >> 4) & 1) * 8;
    const int b_ro = (lane & 7) + ((lane >> 4) & 1) * 8;
    const int b_co = ((lane >> 3) & 1) * 8;

    float* b1s = (float*)(smem + SM_B1);    // en_b1
    float* b2s = (float*)(smem + SM_B2);    // en_b2
    float* b1p = (float*)(smem + SM_B1P);   // pe_b1
    float* w2s = (float*)(smem + SM_W2V);   // pe_w2 vector
    int*   s_ia = (int*)(smem + SM_IA);
    int*   s_ib = (int*)(smem + SM_IB);

    copyw_half(sb, tid, 10, 0);             // enW1c half 0

    if (tid < 128) {
        b1s[tid] = en_b1[tid];
        b2s[tid] = en_b2[tid];
        b1p[tid] = pe_b1v[tid];
        w2s[tid] = pe_w2v[tid];
    }
    if (tid < 64) {
        int grow = row0 + tid;
        int ia = 0, ib = 0;
        if (grow < nrows) { ia = ip0[grow]; ib = ip1[grow]; }
        s_ia[tid] = ia; s_ib[tid] = ib;
        const char* qa = (const char*)(Qa + (size_t)ia * DD);
        const char* qb = (const char*)(Qb + (size_t)ib * DD);
        const char* ra = (const char*)(Ra + (size_t)ia * DD);
        const char* rb = (const char*)(Rb + (size_t)ib * DD);
        #pragma unroll
        for (int l = 0; l < 4; ++l) {
            asm volatile("prefetch.global.L2 [%0];" :: "l"(qa + l * 128));
            asm volatile("prefetch.global.L2 [%0];" :: "l"(qb + l * 128));
            asm volatile("prefetch.global.L2 [%0];" :: "l"(ra + l * 128));
            asm volatile("prefetch.global.L2 [%0];" :: "l"(rb + l * 128));
        }
    }

    float acc[2][4][4];
    zacc2(acc);

    // ---- en layer 1: e @ enW1c + Qa[s] + Qb[e] ----
    stage_a<128>(smem, wid, lane, row0, e, nrows);
    layer_gemm_issued<8>(sb, tid, 10, m0, nwn, a_ro, a_co, b_ro, b_co, acc);
    pre_add(acc, Qa, Qb, s_ia, s_ib, row0, m0, nwn, g, tig, nrows);

    // ---- en layer 2 ----
    __syncthreads();
    copyw_half(sb, tid, 11, 0);
    acc_to_A(smem, acc, m0, nwn, g, tig, b1s, true);
    zacc2(acc);
    layer_gemm_issued<8>(sb, tid, 11, m0, nwn, a_ro, a_co, b_ro, b_co, acc);

    // fold en_b2 + residual e  ->  e_new stays in registers
    {
        const int rl = m0 + g;
        #pragma unroll
        for (int half = 0; half < 2; ++half) {
            int grow = row0 + rl + half * 8;
            if (grow < nrows) {
                #pragma unroll
                for (int p = 0; p < 2; ++p)
                    #pragma unroll
                    for (int na = 0; na < 4; ++na) {
                        int cc = p * 64 + nwn + na * 8 + 2 * tig;
                        float2 rv = *(const float2*)(e + (size_t)grow * DD + cc);
                        acc[p][na][half * 2 + 0] += b2s[cc] + rv.x;
                        acc[p][na][half * 2 + 1] += b2s[cc + 1] + rv.y;
                    }
            }
        }
    }

    // ---- pe layer 1: e_new @ peW1c + Ra[s] + Rb[e] ----
    __syncthreads();                         // A/B reads done
    copyw_half(sb, tid, 14, 0);
    acc_to_A(smem, acc, m0, nwn, g, tig, nullptr, false);   // split e_new
    zacc2(acc);
    layer_gemm_issued<8>(sb, tid, 14, m0, nwn, a_ro, a_co, b_ro, b_co, acc);
    pre_add(acc, Ra, Rb, s_ia, s_ib, row0, m0, nwn, g, tig, nrows);

    // ---- pe layer 2: per-row dot ----
    float* hT = (float*)(smem + SM_AH);      // [64][129] fp32
    __syncthreads();                          // A/B reads done before overwrite
    {
        const int rl = m0 + g;
        #pragma unroll
        for (int p = 0; p < 2; ++p)
            #pragma unroll
            for (int na = 0; na < 4; ++na) {
                int cc = p * 64 + nwn + na * 8 + 2 * tig;
                hT[rl * 129 + cc]           = fmaxf(acc[p][na][0] + b1p[cc], 0.f);
                hT[rl * 129 + cc + 1]       = fmaxf(acc[p][na][1] + b1p[cc + 1], 0.f);
                hT[(rl + 8) * 129 + cc]     = fmaxf(acc[p][na][2] + b1p[cc], 0.f);
                hT[(rl + 8) * 129 + cc + 1] = fmaxf(acc[p][na][3] + b1p[cc + 1], 0.f);
            }
    }
    __syncthreads();
    if (tid < 64) {
        int grow = row0 + tid;
        float a = __ldg(&pe_b2v[0]);
        #pragma unroll 8
        for (int k = 0; k < 128; ++k) a += hT[tid * 129 + k] * w2s[k];
        if (grow < nrows) pred[grow] = a;
    }
}

// ---------------------------------------------------------------------------
extern "C" void kernel_launch(void* const* d_in, const int* in_sizes, int n_in,
                              void* d_out, int out_size) {
    const float* nodes = (const float*)d_in[0];
    const void*  eidx  = d_in[1];
    const float* ne_W1 = (const float*)d_in[2];
    const float* ne_b1 = (const float*)d_in[3];
    const float* ne_W2 = (const float*)d_in[4];
    const float* ne_b2 = (const float*)d_in[5];
    const float* ee_W1 = (const float*)d_in[6];
    const float* ee_b1 = (const float*)d_in[7];
    const float* ee_W2 = (const float*)d_in[8];
    const float* ee_b2 = (const float*)d_in[9];
    const float* nn_W1 = (const float*)d_in[10];
    const float* nn_b1 = (const float*)d_in[11];
    const float* nn_W2 = (const float*)d_in[12];
    const float* nn_b2 = (const float*)d_in[13];
    const float* en_W1 = (const float*)d_in[14];
    const float* en_b1 = (const float*)d_in[15];
    const float* en_W2 = (const float*)d_in[16];
    const float* en_b2 = (const float*)d_in[17];
    const float* pe_W1 = (const float*)d_in[18];
    const float* pe_b1 = (const float*)d_in[19];
    const float* pe_W2 = (const float*)d_in[20];
    const float* pe_b2 = (const float*)d_in[21];

    float *h, *h2, *m0, *m1, *e, *pa, *pb, *pc, *pd;
    int *st, *en_;
    __nv_bfloat16 *pwh, *pwl;
    cudaGetSymbolAddress((void**)&h,   g_h);
    cudaGetSymbolAddress((void**)&h2,  g_h2);
    cudaGetSymbolAddress((void**)&m0,  g_m0);
    cudaGetSymbolAddress((void**)&m1,  g_m1);
    cudaGetSymbolAddress((void**)&e,   g_e);
    cudaGetSymbolAddress((void**)&pa,  g_pa);
    cudaGetSymbolAddress((void**)&pb,  g_pb);
    cudaGetSymbolAddress((void**)&pc,  g_pc);
    cudaGetSymbolAddress((void**)&pd,  g_pd);
    cudaGetSymbolAddress((void**)&st,  g_start);
    cudaGetSymbolAddress((void**)&en_, g_end);
    cudaGetSymbolAddress((void**)&pwh, g_pwh);
    cudaGetSymbolAddress((void**)&pwl, g_pwl);

    cudaFuncSetAttribute(node_fused<1, 1, false, true, false>,
                         cudaFuncAttributeMaxDynamicSharedMemorySize, SM_TOTAL);
    cudaFuncSetAttribute(node_fused<2, 8, true, false, true>,
                         cudaFuncAttributeMaxDynamicSharedMemorySize, SM_TOTAL);
    cudaFuncSetAttribute(node_fused<2, 8, true, true, true>,
                         cudaFuncAttributeMaxDynamicSharedMemorySize, SM_TOTAL);
    cudaFuncSetAttribute(edge_mlp<0, true, false>,
                         cudaFuncAttributeMaxDynamicSharedMemorySize, SM_TOTAL);
    cudaFuncSetAttribute(edge_mlp<1, true, true>,
                         cudaFuncAttributeMaxDynamicSharedMemorySize, SM_TOTAL);
    cudaFuncSetAttribute(edge_en_pe,
                         cudaFuncAttributeMaxDynamicSharedMemorySize, SM_TOTAL);

    const int nblk_n = (N_NODES + 63) / 64;  // 1563
    const int nblk_e = (N_EDGES + 63) / 64;  // 9375

    convert_idx_kernel<<<(2 * N_EDGES + 255) / 256, 256>>>(eidx, st, en_, N_EDGES);
    pack_w_kernel<<<(15 * 16384 + 255) / 256, 256>>>(
        ne_W1, ne_W2, ee_W1, ee_W2, nn_W1, nn_W2, en_W1, en_W2, pe_W1, pwh, pwl);

    // h = MLP_ne(nodes);  Pa = h@eeW1a, Pb = h@eeW1b;  zero m0
    node_fused<1, 1, false, true, false><<<nblk_n, 256, SM_TOTAL>>>(
        nodes, nullptr, 0, 0, nullptr, nullptr, 0, 1,
        2, 3, pa, pb, ne_b1, ne_b2, nullptr, h, m0, N_NODES);

    // e = relu(Pa[s]+Pb[e]+b1)@eeW2 + b2;  scatter e -> m0
    edge_mlp<0, true, false><<<nblk_e, 256, SM_TOTAL>>>(
        nullptr, st, en_, pa, pb, 0, 4,
        ee_b1, ee_b2, nullptr, e, m0, N_EDGES);

    float* hA = h;
    float* hB = h2;
    float* msgs[2] = {m0, m1};

    for (int it = 0; it < NUM_ITERS; ++it) {
        float* mcur = msgs[it & 1];
        float* mnxt = msgs[(it + 1) & 1];
        const bool last = (it == NUM_ITERS - 1);
        float* zr = last ? nullptr : mnxt;

        if (!last) {
            node_fused<2, 8, true, false, true><<<nblk_n, 256, SM_TOTAL>>>(
                hA, mcur, 8, 9, pa, pb, 5, 7,
                0, 0, nullptr, nullptr, nn_b1, nn_b2, hA, hB, zr, N_NODES);

            edge_mlp<1, true, true><<<nblk_e, 256, SM_TOTAL>>>(
                e, st, en_, pa, pb, 10, 11,
                en_b1, en_b2, e, e, mnxt, N_EDGES);
        } else {
            // h' + Qa/Qb (en) + Ra/Rb (pe, from h')
            node_fused<2, 8, true, true, true><<<nblk_n, 256, SM_TOTAL>>>(
                hA, mcur, 8, 9, pa, pb, 5, 7,
                12, 13, pc, pd, nn_b1, nn_b2, hA, hB, zr, N_NODES);

            // fused en+pe: pred written directly; e_final never hits DRAM
            edge_en_pe<<<nblk_e, 256, SM_TOTAL>>>(
                e, st, en_, pa, pb, pc, pd,
                en_b1, en_b2, pe_b1, pe_b2, pe_W2,
                (float*)d_out, N_EDGES);
        }

        float* t = hA; hA = hB; hB = t;
    }
}